// round 8
// baseline (speedup 1.0000x reference)
#include <cuda_runtime.h>
#include <cuda_bf16.h>
#include <math.h>
#include <stdint.h>

#define BB 2
#define TT 2048
#define DD 1024
#define SS 32
#define CN 128
#define NCH 16
#define ALPHA 0.05f
#define AVAL 0.95f
#define RSCALE 0.03125f
#define LNEPS 1e-5f

// scratch (device globals)
__device__ __nv_bfloat16 g_hn_hi[BB*TT*DD];
__device__ __nv_bfloat16 g_hn_lo[BB*TT*DD];
__device__ __nv_bfloat16 g_W_hi [2*DD*DD];
__device__ __nv_bfloat16 g_W_lo [2*DD*DD];
__device__ float g_q  [BB*TT*DD];
__device__ float g_v  [BB*TT*DD];
__device__ __nv_bfloat16 g_q_hi[BB*TT*DD];
__device__ __nv_bfloat16 g_q_lo[BB*TT*DD];
__device__ __nv_bfloat16 g_v_hi[BB*TT*DD];
__device__ __nv_bfloat16 g_v_lo[BB*TT*DD];
__device__ float g_w  [BB*TT*SS];
__device__ float g_wsp[BB*NCH*8*CN*SS];
__device__ float g_U  [BB*NCH*SS*DD];
__device__ float g_Ms [BB*NCH*SS*DD];
__device__ __nv_bfloat16 g_Ms_hi[BB*NCH*SS*DD];
__device__ __nv_bfloat16 g_Ms_lo[BB*NCH*SS*DD];
__device__ float g_P  [BB*NCH*CN*CN];
__device__ float g_QM [BB*NCH*CN*SS];
__device__ float g_G  [BB*NCH*CN*CN];
__device__ float g_at [BB*NCH*CN*SS];

// ---------------- helpers ----------------------------------------------------
__device__ __forceinline__ uint32_t smem_u32(const void* p) {
    uint32_t a;
    asm("{ .reg .u64 t; cvta.to.shared.u64 t, %1; cvt.u32.u64 %0, t; }" : "=r"(a) : "l"(p));
    return a;
}
#define LDMX4(r0, r1, r2, r3, addr) \
    asm volatile("ldmatrix.sync.aligned.m8n8.x4.shared.b16 {%0,%1,%2,%3}, [%4];" \
        : "=r"(r0), "=r"(r1), "=r"(r2), "=r"(r3) : "r"(addr))
#define LDMX2(r0, r1, addr) \
    asm volatile("ldmatrix.sync.aligned.m8n8.x2.shared.b16 {%0,%1}, [%2];" \
        : "=r"(r0), "=r"(r1) : "r"(addr))
#define MMA16816(d, a, b) \
    asm volatile("mma.sync.aligned.m16n8k16.row.col.f32.bf16.bf16.f32 " \
        "{%0,%1,%2,%3}, {%4,%5,%6,%7}, {%8,%9}, {%0,%1,%2,%3};" \
        : "+f"((d)[0]), "+f"((d)[1]), "+f"((d)[2]), "+f"((d)[3]) \
        : "r"((a)[0]), "r"((a)[1]), "r"((a)[2]), "r"((a)[3]), "r"((b)[0]), "r"((b)[1]))
#define CP_ASYNC16(smaddr, gptr) \
    asm volatile("cp.async.cg.shared.global [%0], [%1], 16;" :: "r"(smaddr), "l"(gptr) : "memory")
#define CP_COMMIT() asm volatile("cp.async.commit_group;" ::: "memory")
#define CP_WAIT0()  asm volatile("cp.async.wait_group 0;" ::: "memory")

// ---------------- 1) LayerNorm -> bf16 hi/lo --------------------------------
__global__ void __launch_bounds__(256) ln_kernel(const float* __restrict__ h,
                                                 const float* __restrict__ gamma,
                                                 const float* __restrict__ beta) {
    __shared__ float sx[DD];
    __shared__ float sred[256];
    const int row = blockIdx.x;
    const float* hr = h + (size_t)row * DD;
    const int tid = threadIdx.x;
    float lsum = 0.f;
    for (int i = tid; i < DD; i += 256) { float x = hr[i]; sx[i] = x; lsum += x; }
    sred[tid] = lsum; __syncthreads();
    #pragma unroll
    for (int s = 128; s > 0; s >>= 1) { if (tid < s) sred[tid] += sred[tid + s]; __syncthreads(); }
    const float mu = sred[0] * (1.0f / DD);
    __syncthreads();
    float lvar = 0.f;
    for (int i = tid; i < DD; i += 256) { float d = sx[i] - mu; lvar += d * d; }
    sred[tid] = lvar; __syncthreads();
    #pragma unroll
    for (int s = 128; s > 0; s >>= 1) { if (tid < s) sred[tid] += sred[tid + s]; __syncthreads(); }
    const float rstd = rsqrtf(sred[0] * (1.0f / DD) + LNEPS);
    __nv_bfloat16* ohi = g_hn_hi + (size_t)row * DD;
    __nv_bfloat16* olo = g_hn_lo + (size_t)row * DD;
    for (int i = tid; i < DD; i += 256) {
        float y = (sx[i] - mu) * rstd * gamma[i] + beta[i];
        __nv_bfloat16 hi = __float2bfloat16(y);
        ohi[i] = hi;
        olo[i] = __float2bfloat16(y - __bfloat162float(hi));
    }
}

// ---------------- 1b) W -> bf16 hi/lo ---------------------------------------
__global__ void __launch_bounds__(256) convw_kernel(const float* __restrict__ Wq,
                                                    const float* __restrict__ Wv) {
    const size_t base = ((size_t)blockIdx.x * 256 + threadIdx.x) * 4;
    const float* W = (base < (size_t)DD*DD) ? Wq : Wv;
    const size_t off = (base < (size_t)DD*DD) ? base : base - (size_t)DD*DD;
    float4 x = *(const float4*)(&W[off]);
    __nv_bfloat16 h0 = __float2bfloat16(x.x), h1 = __float2bfloat16(x.y);
    __nv_bfloat16 h2 = __float2bfloat16(x.z), h3 = __float2bfloat16(x.w);
    *(__nv_bfloat162*)(&g_W_hi[base + 0]) = __nv_bfloat162(h0, h1);
    *(__nv_bfloat162*)(&g_W_hi[base + 2]) = __nv_bfloat162(h2, h3);
    *(__nv_bfloat162*)(&g_W_lo[base + 0]) = __nv_bfloat162(
        __float2bfloat16(x.x - __bfloat162float(h0)), __float2bfloat16(x.y - __bfloat162float(h1)));
    *(__nv_bfloat162*)(&g_W_lo[base + 2]) = __nv_bfloat162(
        __float2bfloat16(x.z - __bfloat162float(h2)), __float2bfloat16(x.w - __bfloat162float(h3)));
}

// ---------------- 2) q/v projection: mma.sync bf16, cp.async 2-stage --------
#define TSTRIDE 72
#define TILE_B (128*TSTRIDE*2)
#define GEMM_SMEM (8*TILE_B)
__global__ void __launch_bounds__(256) gemm_tc_kernel(const float* __restrict__ bq,
                                                      const float* __restrict__ bv) {
    extern __shared__ char smc[];
    const uint32_t smb = smem_u32(smc);
    const int tid = threadIdx.x;
    const int wid = tid >> 5, lane = tid & 31;
    const int n0 = blockIdx.x * 128;
    const int m0 = blockIdx.y * 128;
    const int z  = blockIdx.z;
    const __nv_bfloat16* Whi = g_W_hi + (size_t)z * DD * DD;
    const __nv_bfloat16* Wlo = g_W_lo + (size_t)z * DD * DD;
    const int m_base = (wid >> 2) * 64;
    const int n_base = (wid & 3) * 32;

    float acc[4][4][4];
    #pragma unroll
    for (int mi = 0; mi < 4; mi++)
        #pragma unroll
        for (int nj = 0; nj < 4; nj++)
            #pragma unroll
            for (int r = 0; r < 4; r++) acc[mi][nj][r] = 0.f;

    const int a_rr = lane & 15;
    const int a_kk = (lane >> 4) * 8;
    const int b_g  = lane >> 3;
    const int b_rr = lane & 7;
    const int b_nofs = (b_g >> 1) * 8;
    const int b_kofs = (b_g & 1) * 8;

    const int lr = tid >> 3, lc8 = (tid & 7) * 8;   // per-thread load coords (32 rows/iter)
    const uint32_t lso = (uint32_t)(lr * TSTRIDE + lc8) * 2;

    // prologue: stage 0 <- chunk 0
    #pragma unroll
    for (int l = 0; l < 4; l++) {
        const int r = lr + l * 32;
        const size_t ga = (size_t)(m0 + r) * DD + lc8;
        const size_t gb = (size_t)(n0 + r) * DD + lc8;
        const uint32_t so = lso + (uint32_t)(l * 32 * TSTRIDE) * 2;
        CP_ASYNC16(smb + 0*TILE_B + so, &g_hn_hi[ga]);
        CP_ASYNC16(smb + 1*TILE_B + so, &g_hn_lo[ga]);
        CP_ASYNC16(smb + 2*TILE_B + so, &Whi[gb]);
        CP_ASYNC16(smb + 3*TILE_B + so, &Wlo[gb]);
    }
    CP_COMMIT(); CP_WAIT0(); __syncthreads();

    for (int ch = 0; ch < 16; ch++) {
        const int s = ch & 1;
        const uint32_t sb = smb + (uint32_t)s * 4 * TILE_B;
        if (ch + 1 < 16) {
            const uint32_t nb = smb + (uint32_t)(s ^ 1) * 4 * TILE_B;
            const int k0 = (ch + 1) * 64;
            #pragma unroll
            for (int l = 0; l < 4; l++) {
                const int r = lr + l * 32;
                const size_t ga = (size_t)(m0 + r) * DD + k0 + lc8;
                const size_t gb = (size_t)(n0 + r) * DD + k0 + lc8;
                const uint32_t so = lso + (uint32_t)(l * 32 * TSTRIDE) * 2;
                CP_ASYNC16(nb + 0*TILE_B + so, &g_hn_hi[ga]);
                CP_ASYNC16(nb + 1*TILE_B + so, &g_hn_lo[ga]);
                CP_ASYNC16(nb + 2*TILE_B + so, &Whi[gb]);
                CP_ASYNC16(nb + 3*TILE_B + so, &Wlo[gb]);
            }
            CP_COMMIT();
        }
        #pragma unroll
        for (int ks = 0; ks < 4; ks++) {
            uint32_t ah[4][4], al[4][4];
            #pragma unroll
            for (int mi = 0; mi < 4; mi++) {
                const uint32_t off = (uint32_t)((m_base + mi*16 + a_rr) * TSTRIDE + ks*16 + a_kk) * 2;
                LDMX4(ah[mi][0], ah[mi][1], ah[mi][2], ah[mi][3], sb + 0*TILE_B + off);
                LDMX4(al[mi][0], al[mi][1], al[mi][2], al[mi][3], sb + 1*TILE_B + off);
            }
            uint32_t bh[4][2], bl[4][2];
            #pragma unroll
            for (int ni = 0; ni < 2; ni++) {
                const uint32_t off = (uint32_t)((n_base + ni*16 + b_nofs + b_rr) * TSTRIDE + ks*16 + b_kofs) * 2;
                LDMX4(bh[2*ni][0], bh[2*ni][1], bh[2*ni+1][0], bh[2*ni+1][1], sb + 2*TILE_B + off);
                LDMX4(bl[2*ni][0], bl[2*ni][1], bl[2*ni+1][0], bl[2*ni+1][1], sb + 3*TILE_B + off);
            }
            #pragma unroll
            for (int mi = 0; mi < 4; mi++)
                #pragma unroll
                for (int nj = 0; nj < 4; nj++) {
                    MMA16816(acc[mi][nj], ah[mi], bh[nj]);
                    MMA16816(acc[mi][nj], ah[mi], bl[nj]);
                    MMA16816(acc[mi][nj], al[mi], bh[nj]);
                }
        }
        if (ch + 1 < 16) CP_WAIT0();
        __syncthreads();
    }

    float* C = z ? g_v : g_q;
    __nv_bfloat16* Ch = z ? g_v_hi : g_q_hi;
    __nv_bfloat16* Cl = z ? g_v_lo : g_q_lo;
    const float* bias = z ? bv : bq;
    #pragma unroll
    for (int mi = 0; mi < 4; mi++) {
        const int row0 = m0 + m_base + mi*16 + (lane >> 2);
        #pragma unroll
        for (int nj = 0; nj < 4; nj++) {
            const int col = n0 + n_base + nj*8 + (lane & 3) * 2;
            const float b0 = bias[col], b1 = bias[col + 1];
            float2 v0 = { acc[mi][nj][0] + b0, acc[mi][nj][1] + b1 };
            float2 v1 = { acc[mi][nj][2] + b0, acc[mi][nj][3] + b1 };
            *(float2*)(&C[(size_t)row0 * DD + col]) = v0;
            *(float2*)(&C[(size_t)(row0 + 8) * DD + col]) = v1;
            __nv_bfloat16 h0 = __float2bfloat16(v0.x), h1 = __float2bfloat16(v0.y);
            __nv_bfloat16 h2 = __float2bfloat16(v1.x), h3 = __float2bfloat16(v1.y);
            *(__nv_bfloat162*)(&Ch[(size_t)row0 * DD + col]) = __nv_bfloat162(h0, h1);
            *(__nv_bfloat162*)(&Ch[(size_t)(row0 + 8) * DD + col]) = __nv_bfloat162(h2, h3);
            *(__nv_bfloat162*)(&Cl[(size_t)row0 * DD + col]) = __nv_bfloat162(
                __float2bfloat16(v0.x - __bfloat162float(h0)),
                __float2bfloat16(v0.y - __bfloat162float(h1)));
            *(__nv_bfloat162*)(&Cl[(size_t)(row0 + 8) * DD + col]) = __nv_bfloat162(
                __float2bfloat16(v1.x - __bfloat162float(h2)),
                __float2bfloat16(v1.y - __bfloat162float(h3)));
        }
    }
}

// ---------------- 3a) routing score partials (split-K, 8 x 128) -------------
__global__ void __launch_bounds__(256) route_part_kernel(const float* __restrict__ state0) {
    __shared__ float sQ[128][65];
    __shared__ float sS[32][65];
    const int kt = blockIdx.x, c = blockIdx.y, b = blockIdx.z;
    const int tid = threadIdx.x;
    const int t  = tid >> 1;
    const int sh = (tid & 1) * 16;
    float acc[16];
    #pragma unroll
    for (int j = 0; j < 16; j++) acc[j] = 0.f;
    #pragma unroll
    for (int ki = 0; ki < 2; ki++) {
        const int k0 = kt * 128 + ki * 64;
        #pragma unroll
        for (int l = 0; l < 8; l++) {
            const int f4 = tid + l * 256;
            const int r  = f4 >> 4;
            const int kc = (f4 & 15) << 2;
            float4 a4 = *(const float4*)(&g_q[(size_t)(b*TT + c*CN + r)*DD + k0 + kc]);
            sQ[r][kc+0] = a4.x; sQ[r][kc+1] = a4.y; sQ[r][kc+2] = a4.z; sQ[r][kc+3] = a4.w;
        }
        #pragma unroll
        for (int l = 0; l < 2; l++) {
            const int f4 = tid + l * 256;
            const int r  = f4 >> 4;
            const int kc = (f4 & 15) << 2;
            float4 s4 = *(const float4*)(&state0[(size_t)(b*SS + r)*DD + k0 + kc]);
            sS[r][kc+0] = s4.x; sS[r][kc+1] = s4.y; sS[r][kc+2] = s4.z; sS[r][kc+3] = s4.w;
        }
        __syncthreads();
        for (int k = 0; k < 64; k++) {
            const float qv = sQ[t][k];
            #pragma unroll
            for (int sj = 0; sj < 16; sj++) acc[sj] += qv * sS[sh + sj][k];
        }
        __syncthreads();
    }
    const int base = ((b*NCH + c)*8 + kt)*CN*SS + t*SS + sh;
    #pragma unroll
    for (int sj = 0; sj < 16; sj++) g_wsp[base + sj] = acc[sj];
}

// ---------------- 3b) reduce partials + softmax -> w ------------------------
__global__ void __launch_bounds__(128) route_red_kernel() {
    const int c = blockIdx.x, b = blockIdx.y;
    const int t = threadIdx.x;
    const int base = ((b*NCH + c)*8)*CN*SS + t*SS;
    float sc[SS];
    #pragma unroll
    for (int s = 0; s < SS; s++) {
        float sum = 0.f;
        #pragma unroll
        for (int kt = 0; kt < 8; kt++) sum += g_wsp[base + kt*CN*SS + s];
        sc[s] = sum * RSCALE;
    }
    float mx = -1e30f;
    #pragma unroll
    for (int s = 0; s < SS; s++) mx = fmaxf(mx, sc[s]);
    float sum = 0.f;
    #pragma unroll
    for (int s = 0; s < SS; s++) { sc[s] = expf(sc[s] - mx); sum += sc[s]; }
    const float inv = 1.f / sum;
    const int ob = (b*TT + c*CN + t)*SS;
    #pragma unroll
    for (int s = 0; s < SS; s++) g_w[ob + s] = sc[s] * inv;
}

// ---------------- 4) per-chunk update U --------------------------------------
__global__ void __launch_bounds__(256) u_kernel() {
    __shared__ float sV[128*64];
    __shared__ float sPw[128];
    const int dt = blockIdx.x, c = blockIdx.y, b = blockIdx.z;
    const int tid = threadIdx.x;
    if (tid < 128) sPw[tid] = powf(AVAL, (float)tid);
    #pragma unroll
    for (int l = 0; l < 8; l++) {
        const int f4 = tid + l * 256;
        const int r  = f4 >> 4;
        const int kc = (f4 & 15) << 2;
        float4 v4 = *(const float4*)(&g_v[(size_t)(b*TT + c*CN + r)*DD + dt*64 + kc]);
        sV[r*64 + kc+0] = v4.x; sV[r*64 + kc+1] = v4.y; sV[r*64 + kc+2] = v4.z; sV[r*64 + kc+3] = v4.w;
    }
    __syncthreads();
    const int s  = tid & 31;
    const int d0 = (tid >> 5) << 3;
    float acc[8];
    #pragma unroll
    for (int j = 0; j < 8; j++) acc[j] = 0.f;
    const float* wrow = &g_w[(b*TT + c*CN)*SS + s];
    for (int tau = 0; tau < CN; tau++) {
        const float wd = ALPHA * sPw[127 - tau] * wrow[tau*SS];
        #pragma unroll
        for (int j = 0; j < 8; j++) acc[j] += wd * sV[tau*64 + d0 + j];
    }
    const int ob = ((b*NCH + c)*SS + s)*DD + dt*64 + d0;
    #pragma unroll
    for (int j = 0; j < 8; j++) g_U[ob + j] = acc[j];
}

// ---------------- 5) sequential chunk scan (also emits Ms bf16 hi/lo) -------
__global__ void __launch_bounds__(256) scan_kernel(const float* __restrict__ state0,
                                                   float* __restrict__ outF) {
    const int idx = blockIdx.x * 256 + threadIdx.x;
    const int b = idx / (SS*DD);
    const int sd = idx - b*SS*DD;
    float m = state0[idx];
    const float dc = powf(AVAL, (float)CN);
    #pragma unroll
    for (int c = 0; c < NCH; c++) {
        const int o = (b*NCH + c)*SS*DD + sd;
        g_Ms[o] = m;
        __nv_bfloat16 hi = __float2bfloat16(m);
        g_Ms_hi[o] = hi;
        g_Ms_lo[o] = __float2bfloat16(m - __bfloat162float(hi));
        m = dc * m + g_U[o];
    }
    outF[idx] = m;
}

// ---------------- 6) R1 via HMMA: P = q@v^T, QM = q@Ms^T (full K) -----------
// grid (NCH, BB), 8 warps 2x4. P warp tile 64x32; QM warp tile 64x8.
#define R1_QH 0
#define R1_QL (R1_QH + TILE_B)
#define R1_VH (R1_QL + TILE_B)
#define R1_VL (R1_VH + TILE_B)
#define R1_MH (R1_VL + TILE_B)
#define R1_ML (R1_MH + 32*TSTRIDE*2)
#define R1_SMEM (R1_ML + 32*TSTRIDE*2)
__global__ void __launch_bounds__(256) r1_tc_kernel() {
    extern __shared__ char sm1c[];
    const uint32_t smb = smem_u32(sm1c);
    const int c = blockIdx.x, b = blockIdx.y;
    const int tid = threadIdx.x;
    const int wid = tid >> 5, lane = tid & 31;
    const int m_base = (wid >> 2) * 64;
    const int n_base = (wid & 3) * 32;
    const int nq_base = (wid & 3) * 8;

    float accP[4][4][4];
    float accQ[4][4];
    #pragma unroll
    for (int mi = 0; mi < 4; mi++) {
        #pragma unroll
        for (int r = 0; r < 4; r++) accQ[mi][r] = 0.f;
        #pragma unroll
        for (int nj = 0; nj < 4; nj++)
            #pragma unroll
            for (int r = 0; r < 4; r++) accP[mi][nj][r] = 0.f;
    }

    const int a_rr = lane & 15;
    const int a_kk = (lane >> 4) * 8;
    const int b_g  = lane >> 3;
    const int b_rr = lane & 7;
    const int b_nofs = (b_g >> 1) * 8;
    const int b_kofs = (b_g & 1) * 8;
    const int m_rr = lane & 7;              // LDMX2 row for Ms
    const int m_kofs = ((lane >> 3) & 1) * 8;

    for (int ch = 0; ch < 16; ch++) {
        const int k0 = ch * 64;
        #pragma unroll
        for (int l = 0; l < 4; l++) {
            const int idx = tid + l * 256;
            const int r = idx >> 3, c8 = (idx & 7) * 8;
            const uint32_t so = (uint32_t)(r * TSTRIDE + c8) * 2;
            const size_t gq = (size_t)(b*TT + c*CN + r)*DD + k0 + c8;
            *(uint4*)(sm1c + R1_QH + so) = *(const uint4*)(&g_q_hi[gq]);
            *(uint4*)(sm1c + R1_QL + so) = *(const uint4*)(&g_q_lo[gq]);
            *(uint4*)(sm1c + R1_VH + so) = *(const uint4*)(&g_v_hi[gq]);
            *(uint4*)(sm1c + R1_VL + so) = *(const uint4*)(&g_v_lo[gq]);
        }
        {
            const int r = tid >> 3, c8 = (tid & 7) * 8;
            const uint32_t so = (uint32_t)(r * TSTRIDE + c8) * 2;
            const size_t gm = (size_t)((b*NCH + c)*SS + r)*DD + k0 + c8;
            *(uint4*)(sm1c + R1_MH + so) = *(const uint4*)(&g_Ms_hi[gm]);
            *(uint4*)(sm1c + R1_ML + so) = *(const uint4*)(&g_Ms_lo[gm]);
        }
        __syncthreads();
        #pragma unroll
        for (int ks = 0; ks < 4; ks++) {
            uint32_t ah[4][4], al[4][4];
            #pragma unroll
            for (int mi = 0; mi < 4; mi++) {
                const uint32_t off = (uint32_t)((m_base + mi*16 + a_rr) * TSTRIDE + ks*16 + a_kk) * 2;
                LDMX4(ah[mi][0], ah[mi][1], ah[mi][2], ah[mi][3], smb + R1_QH + off);
                LDMX4(al[mi][0], al[mi][1], al[mi][2], al[mi][3], smb + R1_QL + off);
            }
            uint32_t bh[4][2], bl[4][2];
            #pragma unroll
            for (int ni = 0; ni < 2; ni++) {
                const uint32_t off = (uint32_t)((n_base + ni*16 + b_nofs + b_rr) * TSTRIDE + ks*16 + b_kofs) * 2;
                LDMX4(bh[2*ni][0], bh[2*ni][1], bh[2*ni+1][0], bh[2*ni+1][1], smb + R1_VH + off);
                LDMX4(bl[2*ni][0], bl[2*ni][1], bl[2*ni+1][0], bl[2*ni+1][1], smb + R1_VL + off);
            }
            uint32_t mh2[2], ml2[2];
            {
                const uint32_t off = (uint32_t)((nq_base + m_rr) * TSTRIDE + ks*16 + m_kofs) * 2;
                LDMX2(mh2[0], mh2[1], smb + R1_MH + off);
                LDMX2(ml2[0], ml2[1], smb + R1_ML + off);
            }
            #pragma unroll
            for (int mi = 0; mi < 4; mi++) {
                #pragma unroll
                for (int nj = 0; nj < 4; nj++) {
                    MMA16816(accP[mi][nj], ah[mi], bh[nj]);
                    MMA16816(accP[mi][nj], ah[mi], bl[nj]);
                    MMA16816(accP[mi][nj], al[mi], bh[nj]);
                }
                MMA16816(accQ[mi], ah[mi], mh2);
                MMA16816(accQ[mi], ah[mi], ml2);
                MMA16816(accQ[mi], al[mi], mh2);
            }
        }
        __syncthreads();
    }

    // epilogue: decay/mask/scale, write g_P and g_QM
    const int r0 = lane >> 2, c0 = (lane & 3) * 2;
    const int pb = (b*NCH + c)*CN;
    #pragma unroll
    for (int mi = 0; mi < 4; mi++) {
        #pragma unroll
        for (int half = 0; half < 2; half++) {
            const int t = m_base + mi*16 + r0 + half*8;
            const float pwq = RSCALE * powf(AVAL, (float)(t + 1));
            #pragma unroll
            for (int nj = 0; nj < 4; nj++) {
                const int tau0 = n_base + nj*8 + c0;
                const float v0 = accP[mi][nj][half*2 + 0];
                const float v1 = accP[mi][nj][half*2 + 1];
                float o0 = (tau0     <= t) ? ALPHA * powf(AVAL, (float)(t - tau0))     * v0 : 0.f;
                float o1 = (tau0 + 1 <= t) ? ALPHA * powf(AVAL, (float)(t - tau0 - 1)) * v1 : 0.f;
                *(float2*)(&g_P[(size_t)(pb + t)*CN + tau0]) = make_float2(o0, o1);
            }
            const int s0 = nq_base + c0;
            float q0 = pwq * accQ[mi][half*2 + 0];
            float q1 = pwq * accQ[mi][half*2 + 1];
            *(float2*)(&g_QM[(size_t)(pb + t)*SS + s0]) = make_float2(q0, q1);
        }
    }
}

// ---------------- 7) R2: scores, softmax, G ---------------------------------
#define R2_SMEM ((128*129 + 128*33*2 + 132)*4)
__global__ void __launch_bounds__(256) r2_kernel() {
    extern __shared__ float sm2[];
    float* sP  = sm2;
    float* sW  = sP + 128*129;
    float* sA  = sW + 128*33;
    float* sPw = sA + 128*33;
    const int c = blockIdx.x, b = blockIdx.y;
    const int tid = threadIdx.x;
    if (tid < 132) sPw[tid] = powf(AVAL, (float)tid);
    __syncthreads();
    const int pbase = ((b*NCH + c)*CN)*CN;
    for (int e = tid; e < CN*CN; e += 256) {
        sP[(e >> 7)*129 + (e & 127)] = g_P[pbase + e];
    }
    const int qbase = ((b*NCH + c)*CN)*SS;
    for (int e = tid; e < CN*SS; e += 256) {
        sA[(e >> 5)*33 + (e & 31)] = g_QM[qbase + e];
    }
    for (int e = tid; e < CN*SS; e += 256) {
        const int t = e >> 5, s = e & 31;
        sW[t*33 + s] = g_w[(b*TT + c*CN + t)*SS + s];
    }
    __syncthreads();
    {
        const int t  = tid >> 1;
        const int s0 = (tid & 1) * 16;
        float r[16];
        #pragma unroll
        for (int sj = 0; sj < 16; sj++) r[sj] = 0.f;
        for (int tau = 0; tau <= t; tau++) {
            const float p = sP[t*129 + tau];
            #pragma unroll
            for (int sj = 0; sj < 16; sj++) r[sj] += p * sW[tau*33 + s0 + sj];
        }
        __syncthreads();
        #pragma unroll
        for (int sj = 0; sj < 16; sj++) sA[t*33 + s0 + sj] += RSCALE * r[sj];
    }
    __syncthreads();
    if (tid < 128) {
        const int t = tid;
        float mx = -1e30f;
        #pragma unroll
        for (int s = 0; s < SS; s++) mx = fmaxf(mx, sA[t*33 + s]);
        float ev[SS]; float sum = 0.f;
        #pragma unroll
        for (int s = 0; s < SS; s++) { ev[s] = expf(sA[t*33 + s] - mx); sum += ev[s]; }
        const float inv = 1.f / sum;
        const float pw = sPw[t + 1];
        const int ab = ((b*NCH + c)*CN + t)*SS;
        #pragma unroll
        for (int s = 0; s < SS; s++) {
            const float a = ev[s] * inv;
            sA[t*33 + s] = a;
            g_at[ab + s] = pw * a;
        }
    }
    __syncthreads();
    const int ty = tid >> 4, tx = tid & 15;
    const int gbase = ((b*NCH + c)*CN)*CN;
    #pragma unroll
    for (int i = 0; i < 8; i++) {
        const int t = ty*8 + i;
        #pragma unroll
        for (int j = 0; j < 8; j++) {
            const int tau = tx*8 + j;
            float g = 0.f;
            if (tau <= t) {
                #pragma unroll
                for (int s = 0; s < SS; s++) g += sA[t*33 + s] * sW[tau*33 + s];
                g *= ALPHA * sPw[t - tau];
            }
            g_G[gbase + t*CN + tau] = g;
        }
    }
}

// ---------------- 8) R3: ctx = G@v + (a^{t+1}attn)@Ms -----------------------
#define R3_SMEM ((128*129*2 + 32*129 + 128*33)*4)
__global__ void __launch_bounds__(256) r3_kernel(float* __restrict__ outC) {
    extern __shared__ float sm3[];
    float* sG  = sm3;
    float* sV  = sG + 128*129;
    float* sM  = sV + 128*129;
    float* sAt = sM + 32*129;
    const int dt = blockIdx.x, c = blockIdx.y, b = blockIdx.z;
    const int tid = threadIdx.x;
    const int ty = tid >> 4, tx = tid & 15;
    #pragma unroll
    for (int l = 0; l < 16; l++) {
        const int f4 = tid + l * 256;
        const int r  = f4 >> 5;
        const int kc = (f4 & 31) << 2;
        float4 gg = *(const float4*)(&g_G[((b*NCH + c)*CN + r)*CN + kc]);
        sG[r*129 + kc+0] = gg.x; sG[r*129 + kc+1] = gg.y; sG[r*129 + kc+2] = gg.z; sG[r*129 + kc+3] = gg.w;
        float4 v4 = *(const float4*)(&g_v[(size_t)(b*TT + c*CN + r)*DD + dt*128 + kc]);
        sV[r*129 + kc+0] = v4.x; sV[r*129 + kc+1] = v4.y; sV[r*129 + kc+2] = v4.z; sV[r*129 + kc+3] = v4.w;
    }
    #pragma unroll
    for (int l = 0; l < 4; l++) {
        const int f4 = tid + l * 256;
        const int r  = f4 >> 5;
        const int kc = (f4 & 31) << 2;
        float4 m4 = *(const float4*)(&g_Ms[((b*NCH + c)*SS + r)*DD + dt*128 + kc]);
        sM[r*129 + kc+0] = m4.x; sM[r*129 + kc+1] = m4.y; sM[r*129 + kc+2] = m4.z; sM[r*129 + kc+3] = m4.w;
    }
    #pragma unroll
    for (int l = 0; l < 4; l++) {
        const int f4 = tid + l * 256;
        const int r  = f4 >> 3;
        const int sc = (f4 & 7) << 2;
        float4 a4 = *(const float4*)(&g_at[((b*NCH + c)*CN + r)*SS + sc]);
        sAt[r*33 + sc+0] = a4.x; sAt[r*33 + sc+1] = a4.y; sAt[r*33 + sc+2] = a4.z; sAt[r*33 + sc+3] = a4.w;
    }
    __syncthreads();
    float acc[8][8];
    #pragma unroll
    for (int i = 0; i < 8; i++)
        #pragma unroll
        for (int j = 0; j < 8; j++) acc[i][j] = 0.f;
    const float* gb = sG + (ty*8)*129;
    for (int tau = 0; tau < 128; tau++) {
        float ar[8], br[8];
        #pragma unroll
        for (int i = 0; i < 8; i++) ar[i] = gb[i*129 + tau];
        #pragma unroll
        for (int j = 0; j < 8; j++) br[j] = sV[tau*129 + tx*8 + j];
        #pragma unroll
        for (int i = 0; i < 8; i++)
            #pragma unroll
            for (int j = 0; j < 8; j++) acc[i][j] += ar[i] * br[j];
    }
    const float* ab = sAt + (ty*8)*33;
    for (int s = 0; s < SS; s++) {
        float ar[8], br[8];
        #pragma unroll
        for (int i = 0; i < 8; i++) ar[i] = ab[i*33 + s];
        #pragma unroll
        for (int j = 0; j < 8; j++) br[j] = sM[s*129 + tx*8 + j];
        #pragma unroll
        for (int i = 0; i < 8; i++)
            #pragma unroll
            for (int j = 0; j < 8; j++) acc[i][j] += ar[i] * br[j];
    }
    #pragma unroll
    for (int i = 0; i < 8; i++) {
        const int row = b*TT + c*CN + ty*8 + i;
        #pragma unroll
        for (int j = 0; j < 8; j++)
            outC[(size_t)row*DD + dt*128 + tx*8 + j] = acc[i][j];
    }
}

extern "C" void kernel_launch(void* const* d_in, const int* in_sizes, int n_in,
                              void* d_out, int out_size) {
    (void)in_sizes; (void)n_in; (void)out_size;
    const float* h      = (const float*)d_in[0];
    const float* state0 = (const float*)d_in[1];
    const float* gamma  = (const float*)d_in[2];
    const float* beta   = (const float*)d_in[3];
    const float* Wq     = (const float*)d_in[4];
    const float* bq     = (const float*)d_in[5];
    const float* Wv     = (const float*)d_in[6];
    const float* bv     = (const float*)d_in[7];
    float* out = (float*)d_out;
    float* outCtx   = out;
    float* outFinal = out + (size_t)BB*TT*DD;

    cudaFuncSetAttribute(gemm_tc_kernel, cudaFuncAttributeMaxDynamicSharedMemorySize, GEMM_SMEM);
    cudaFuncSetAttribute(r1_tc_kernel, cudaFuncAttributeMaxDynamicSharedMemorySize, R1_SMEM);
    cudaFuncSetAttribute(r2_kernel, cudaFuncAttributeMaxDynamicSharedMemorySize, R2_SMEM);
    cudaFuncSetAttribute(r3_kernel, cudaFuncAttributeMaxDynamicSharedMemorySize, R3_SMEM);

    ln_kernel<<<BB*TT, 256>>>(h, gamma, beta);
    convw_kernel<<<2*DD*DD/1024, 256>>>(Wq, Wv);
    gemm_tc_kernel<<<dim3(DD/128, BB*TT/128, 2), 256, GEMM_SMEM>>>(bq, bv);
    route_part_kernel<<<dim3(8, NCH, BB), 256>>>(state0);
    route_red_kernel<<<dim3(NCH, BB), 128>>>();
    u_kernel<<<dim3(16, NCH, BB), 256>>>();
    scan_kernel<<<BB*SS*DD/256, 256>>>(state0, outFinal);
    r1_tc_kernel<<<dim3(NCH, BB), 256, R1_SMEM>>>();
    r2_kernel<<<dim3(NCH, BB), 256, R2_SMEM>>>();
    r3_kernel<<<dim3(DD/128, NCH, BB), 256, R3_SMEM>>>(outCtx);
}

// round 9
// speedup vs baseline: 1.1197x; 1.1197x over previous
#include <cuda_runtime.h>
#include <cuda_bf16.h>
#include <math.h>
#include <stdint.h>

#define BB 2
#define TT 2048
#define DD 1024
#define SS 32
#define CN 128
#define NCH 16
#define ALPHA 0.05f
#define AVAL 0.95f
#define RSCALE 0.03125f
#define LNEPS 1e-5f

// scratch (device globals)
__device__ __nv_bfloat16 g_hn_hi[BB*TT*DD];
__device__ __nv_bfloat16 g_hn_lo[BB*TT*DD];
__device__ __nv_bfloat16 g_W_hi [2*DD*DD];
__device__ __nv_bfloat16 g_W_lo [2*DD*DD];
__device__ float g_v  [BB*TT*DD];
__device__ __nv_bfloat16 g_q_hi[BB*TT*DD];
__device__ __nv_bfloat16 g_q_lo[BB*TT*DD];
__device__ __nv_bfloat16 g_v_hi[BB*TT*DD];
__device__ __nv_bfloat16 g_v_lo[BB*TT*DD];
__device__ float g_w  [BB*TT*SS];
__device__ float g_wsp[BB*NCH*8*CN*SS];
__device__ float g_U  [BB*NCH*SS*DD];
__device__ float g_Ms [BB*NCH*SS*DD];
__device__ __nv_bfloat16 g_Ms_hi[BB*NCH*SS*DD];
__device__ __nv_bfloat16 g_Ms_lo[BB*NCH*SS*DD];
__device__ float g_Pp [4*BB*NCH*CN*CN];
__device__ float g_QMp[4*BB*NCH*CN*SS];
__device__ float g_P  [BB*NCH*CN*CN];
__device__ float g_QM [BB*NCH*CN*SS];
__device__ float g_G  [BB*NCH*CN*CN];
__device__ float g_at [BB*NCH*CN*SS];

// ---------------- helpers ----------------------------------------------------
__device__ __forceinline__ uint32_t smem_u32(const void* p) {
    uint32_t a;
    asm("{ .reg .u64 t; cvta.to.shared.u64 t, %1; cvt.u32.u64 %0, t; }" : "=r"(a) : "l"(p));
    return a;
}
#define LDMX4(r0, r1, r2, r3, addr) \
    asm volatile("ldmatrix.sync.aligned.m8n8.x4.shared.b16 {%0,%1,%2,%3}, [%4];" \
        : "=r"(r0), "=r"(r1), "=r"(r2), "=r"(r3) : "r"(addr))
#define LDMX2(r0, r1, addr) \
    asm volatile("ldmatrix.sync.aligned.m8n8.x2.shared.b16 {%0,%1}, [%2];" \
        : "=r"(r0), "=r"(r1) : "r"(addr))
#define MMA16816(d, a, b) \
    asm volatile("mma.sync.aligned.m16n8k16.row.col.f32.bf16.bf16.f32 " \
        "{%0,%1,%2,%3}, {%4,%5,%6,%7}, {%8,%9}, {%0,%1,%2,%3};" \
        : "+f"((d)[0]), "+f"((d)[1]), "+f"((d)[2]), "+f"((d)[3]) \
        : "r"((a)[0]), "r"((a)[1]), "r"((a)[2]), "r"((a)[3]), "r"((b)[0]), "r"((b)[1]))
#define CP_ASYNC16(smaddr, gptr) \
    asm volatile("cp.async.cg.shared.global [%0], [%1], 16;" :: "r"(smaddr), "l"(gptr) : "memory")
#define CP_COMMIT() asm volatile("cp.async.commit_group;" ::: "memory")
#define CP_WAIT0()  asm volatile("cp.async.wait_group 0;" ::: "memory")

// ---------------- 1) LayerNorm -> bf16 hi/lo --------------------------------
__global__ void __launch_bounds__(256) ln_kernel(const float* __restrict__ h,
                                                 const float* __restrict__ gamma,
                                                 const float* __restrict__ beta) {
    __shared__ float sx[DD];
    __shared__ float sred[256];
    const int row = blockIdx.x;
    const float* hr = h + (size_t)row * DD;
    const int tid = threadIdx.x;
    float lsum = 0.f;
    for (int i = tid; i < DD; i += 256) { float x = hr[i]; sx[i] = x; lsum += x; }
    sred[tid] = lsum; __syncthreads();
    #pragma unroll
    for (int s = 128; s > 0; s >>= 1) { if (tid < s) sred[tid] += sred[tid + s]; __syncthreads(); }
    const float mu = sred[0] * (1.0f / DD);
    __syncthreads();
    float lvar = 0.f;
    for (int i = tid; i < DD; i += 256) { float d = sx[i] - mu; lvar += d * d; }
    sred[tid] = lvar; __syncthreads();
    #pragma unroll
    for (int s = 128; s > 0; s >>= 1) { if (tid < s) sred[tid] += sred[tid + s]; __syncthreads(); }
    const float rstd = rsqrtf(sred[0] * (1.0f / DD) + LNEPS);
    __nv_bfloat16* ohi = g_hn_hi + (size_t)row * DD;
    __nv_bfloat16* olo = g_hn_lo + (size_t)row * DD;
    for (int i = tid; i < DD; i += 256) {
        float y = (sx[i] - mu) * rstd * gamma[i] + beta[i];
        __nv_bfloat16 hi = __float2bfloat16(y);
        ohi[i] = hi;
        olo[i] = __float2bfloat16(y - __bfloat162float(hi));
    }
}

// ---------------- 1b) W -> bf16 hi/lo ---------------------------------------
__global__ void __launch_bounds__(256) convw_kernel(const float* __restrict__ Wq,
                                                    const float* __restrict__ Wv) {
    const size_t base = ((size_t)blockIdx.x * 256 + threadIdx.x) * 4;
    const float* W = (base < (size_t)DD*DD) ? Wq : Wv;
    const size_t off = (base < (size_t)DD*DD) ? base : base - (size_t)DD*DD;
    float4 x = *(const float4*)(&W[off]);
    __nv_bfloat16 h0 = __float2bfloat16(x.x), h1 = __float2bfloat16(x.y);
    __nv_bfloat16 h2 = __float2bfloat16(x.z), h3 = __float2bfloat16(x.w);
    *(__nv_bfloat162*)(&g_W_hi[base + 0]) = __nv_bfloat162(h0, h1);
    *(__nv_bfloat162*)(&g_W_hi[base + 2]) = __nv_bfloat162(h2, h3);
    *(__nv_bfloat162*)(&g_W_lo[base + 0]) = __nv_bfloat162(
        __float2bfloat16(x.x - __bfloat162float(h0)), __float2bfloat16(x.y - __bfloat162float(h1)));
    *(__nv_bfloat162*)(&g_W_lo[base + 2]) = __nv_bfloat162(
        __float2bfloat16(x.z - __bfloat162float(h2)), __float2bfloat16(x.w - __bfloat162float(h3)));
}

// ---------------- 2) q/v projection: mma.sync bf16, cp.async 2-stage --------
#define TSTRIDE 72
#define TILE_B (128*TSTRIDE*2)
#define GEMM_SMEM (8*TILE_B)
__global__ void __launch_bounds__(256) gemm_tc_kernel(const float* __restrict__ bq,
                                                      const float* __restrict__ bv) {
    extern __shared__ char smc[];
    const uint32_t smb = smem_u32(smc);
    const int tid = threadIdx.x;
    const int wid = tid >> 5, lane = tid & 31;
    const int n0 = blockIdx.x * 128;
    const int m0 = blockIdx.y * 128;
    const int z  = blockIdx.z;
    const __nv_bfloat16* Whi = g_W_hi + (size_t)z * DD * DD;
    const __nv_bfloat16* Wlo = g_W_lo + (size_t)z * DD * DD;
    const int m_base = (wid >> 2) * 64;
    const int n_base = (wid & 3) * 32;

    float acc[4][4][4];
    #pragma unroll
    for (int mi = 0; mi < 4; mi++)
        #pragma unroll
        for (int nj = 0; nj < 4; nj++)
            #pragma unroll
            for (int r = 0; r < 4; r++) acc[mi][nj][r] = 0.f;

    const int a_rr = lane & 15;
    const int a_kk = (lane >> 4) * 8;
    const int b_g  = lane >> 3;
    const int b_rr = lane & 7;
    const int b_nofs = (b_g >> 1) * 8;
    const int b_kofs = (b_g & 1) * 8;

    const int lr = tid >> 3, lc8 = (tid & 7) * 8;
    const uint32_t lso = (uint32_t)(lr * TSTRIDE + lc8) * 2;

    #pragma unroll
    for (int l = 0; l < 4; l++) {
        const int r = lr + l * 32;
        const size_t ga = (size_t)(m0 + r) * DD + lc8;
        const size_t gb = (size_t)(n0 + r) * DD + lc8;
        const uint32_t so = lso + (uint32_t)(l * 32 * TSTRIDE) * 2;
        CP_ASYNC16(smb + 0*TILE_B + so, &g_hn_hi[ga]);
        CP_ASYNC16(smb + 1*TILE_B + so, &g_hn_lo[ga]);
        CP_ASYNC16(smb + 2*TILE_B + so, &Whi[gb]);
        CP_ASYNC16(smb + 3*TILE_B + so, &Wlo[gb]);
    }
    CP_COMMIT(); CP_WAIT0(); __syncthreads();

    for (int ch = 0; ch < 16; ch++) {
        const int s = ch & 1;
        const uint32_t sb = smb + (uint32_t)s * 4 * TILE_B;
        if (ch + 1 < 16) {
            const uint32_t nb = smb + (uint32_t)(s ^ 1) * 4 * TILE_B;
            const int k0 = (ch + 1) * 64;
            #pragma unroll
            for (int l = 0; l < 4; l++) {
                const int r = lr + l * 32;
                const size_t ga = (size_t)(m0 + r) * DD + k0 + lc8;
                const size_t gb = (size_t)(n0 + r) * DD + k0 + lc8;
                const uint32_t so = lso + (uint32_t)(l * 32 * TSTRIDE) * 2;
                CP_ASYNC16(nb + 0*TILE_B + so, &g_hn_hi[ga]);
                CP_ASYNC16(nb + 1*TILE_B + so, &g_hn_lo[ga]);
                CP_ASYNC16(nb + 2*TILE_B + so, &Whi[gb]);
                CP_ASYNC16(nb + 3*TILE_B + so, &Wlo[gb]);
            }
            CP_COMMIT();
        }
        #pragma unroll
        for (int ks = 0; ks < 4; ks++) {
            uint32_t ah[4][4], al[4][4];
            #pragma unroll
            for (int mi = 0; mi < 4; mi++) {
                const uint32_t off = (uint32_t)((m_base + mi*16 + a_rr) * TSTRIDE + ks*16 + a_kk) * 2;
                LDMX4(ah[mi][0], ah[mi][1], ah[mi][2], ah[mi][3], sb + 0*TILE_B + off);
                LDMX4(al[mi][0], al[mi][1], al[mi][2], al[mi][3], sb + 1*TILE_B + off);
            }
            uint32_t bh[4][2], bl[4][2];
            #pragma unroll
            for (int ni = 0; ni < 2; ni++) {
                const uint32_t off = (uint32_t)((n_base + ni*16 + b_nofs + b_rr) * TSTRIDE + ks*16 + b_kofs) * 2;
                LDMX4(bh[2*ni][0], bh[2*ni][1], bh[2*ni+1][0], bh[2*ni+1][1], sb + 2*TILE_B + off);
                LDMX4(bl[2*ni][0], bl[2*ni][1], bl[2*ni+1][0], bl[2*ni+1][1], sb + 3*TILE_B + off);
            }
            #pragma unroll
            for (int mi = 0; mi < 4; mi++)
                #pragma unroll
                for (int nj = 0; nj < 4; nj++) {
                    MMA16816(acc[mi][nj], ah[mi], bh[nj]);
                    MMA16816(acc[mi][nj], ah[mi], bl[nj]);
                    MMA16816(acc[mi][nj], al[mi], bh[nj]);
                }
        }
        if (ch + 1 < 16) CP_WAIT0();
        __syncthreads();
    }

    __nv_bfloat16* Ch = z ? g_v_hi : g_q_hi;
    __nv_bfloat16* Cl = z ? g_v_lo : g_q_lo;
    const float* bias = z ? bv : bq;
    #pragma unroll
    for (int mi = 0; mi < 4; mi++) {
        const int row0 = m0 + m_base + mi*16 + (lane >> 2);
        #pragma unroll
        for (int nj = 0; nj < 4; nj++) {
            const int col = n0 + n_base + nj*8 + (lane & 3) * 2;
            const float b0 = bias[col], b1 = bias[col + 1];
            float2 v0 = { acc[mi][nj][0] + b0, acc[mi][nj][1] + b1 };
            float2 v1 = { acc[mi][nj][2] + b0, acc[mi][nj][3] + b1 };
            if (z) {
                *(float2*)(&g_v[(size_t)row0 * DD + col]) = v0;
                *(float2*)(&g_v[(size_t)(row0 + 8) * DD + col]) = v1;
            }
            __nv_bfloat16 h0 = __float2bfloat16(v0.x), h1 = __float2bfloat16(v0.y);
            __nv_bfloat16 h2 = __float2bfloat16(v1.x), h3 = __float2bfloat16(v1.y);
            *(__nv_bfloat162*)(&Ch[(size_t)row0 * DD + col]) = __nv_bfloat162(h0, h1);
            *(__nv_bfloat162*)(&Ch[(size_t)(row0 + 8) * DD + col]) = __nv_bfloat162(h2, h3);
            *(__nv_bfloat162*)(&Cl[(size_t)row0 * DD + col]) = __nv_bfloat162(
                __float2bfloat16(v0.x - __bfloat162float(h0)),
                __float2bfloat16(v0.y - __bfloat162float(h1)));
            *(__nv_bfloat162*)(&Cl[(size_t)(row0 + 8) * DD + col]) = __nv_bfloat162(
                __float2bfloat16(v1.x - __bfloat162float(h2)),
                __float2bfloat16(v1.y - __bfloat162float(h3)));
        }
    }
}

// ---------------- 3a) routing score partials (split-K, 8 x 128) -------------
__global__ void __launch_bounds__(256) route_part_kernel(const float* __restrict__ state0) {
    __shared__ float sQ[128][65];
    __shared__ float sS[32][65];
    const int kt = blockIdx.x, c = blockIdx.y, b = blockIdx.z;
    const int tid = threadIdx.x;
    const int t  = tid >> 1;
    const int sh = (tid & 1) * 16;
    float acc[16];
    #pragma unroll
    for (int j = 0; j < 16; j++) acc[j] = 0.f;
    #pragma unroll
    for (int ki = 0; ki < 2; ki++) {
        const int k0 = kt * 128 + ki * 64;
        #pragma unroll
        for (int l = 0; l < 8; l++) {
            const int f4 = tid + l * 256;
            const int r  = f4 >> 4;
            const int kc = (f4 & 15) << 2;
            const size_t gq = (size_t)(b*TT + c*CN + r)*DD + k0 + kc;
            float4 hi4; float4 lo4;
            {
                __nv_bfloat162 a0 = *(const __nv_bfloat162*)(&g_q_hi[gq + 0]);
                __nv_bfloat162 a1 = *(const __nv_bfloat162*)(&g_q_hi[gq + 2]);
                __nv_bfloat162 l0 = *(const __nv_bfloat162*)(&g_q_lo[gq + 0]);
                __nv_bfloat162 l1 = *(const __nv_bfloat162*)(&g_q_lo[gq + 2]);
                hi4.x = __bfloat162float(a0.x); hi4.y = __bfloat162float(a0.y);
                hi4.z = __bfloat162float(a1.x); hi4.w = __bfloat162float(a1.y);
                lo4.x = __bfloat162float(l0.x); lo4.y = __bfloat162float(l0.y);
                lo4.z = __bfloat162float(l1.x); lo4.w = __bfloat162float(l1.y);
            }
            sQ[r][kc+0] = hi4.x + lo4.x; sQ[r][kc+1] = hi4.y + lo4.y;
            sQ[r][kc+2] = hi4.z + lo4.z; sQ[r][kc+3] = hi4.w + lo4.w;
        }
        #pragma unroll
        for (int l = 0; l < 2; l++) {
            const int f4 = tid + l * 256;
            const int r  = f4 >> 4;
            const int kc = (f4 & 15) << 2;
            float4 s4 = *(const float4*)(&state0[(size_t)(b*SS + r)*DD + k0 + kc]);
            sS[r][kc+0] = s4.x; sS[r][kc+1] = s4.y; sS[r][kc+2] = s4.z; sS[r][kc+3] = s4.w;
        }
        __syncthreads();
        for (int k = 0; k < 64; k++) {
            const float qv = sQ[t][k];
            #pragma unroll
            for (int sj = 0; sj < 16; sj++) acc[sj] += qv * sS[sh + sj][k];
        }
        __syncthreads();
    }
    const int base = ((b*NCH + c)*8 + kt)*CN*SS + t*SS + sh;
    #pragma unroll
    for (int sj = 0; sj < 16; sj++) g_wsp[base + sj] = acc[sj];
}

// ---------------- 3b) reduce partials + softmax -> w ------------------------
__global__ void __launch_bounds__(128) route_red_kernel() {
    const int c = blockIdx.x, b = blockIdx.y;
    const int t = threadIdx.x;
    const int base = ((b*NCH + c)*8)*CN*SS + t*SS;
    float sc[SS];
    #pragma unroll
    for (int s = 0; s < SS; s++) {
        float sum = 0.f;
        #pragma unroll
        for (int kt = 0; kt < 8; kt++) sum += g_wsp[base + kt*CN*SS + s];
        sc[s] = sum * RSCALE;
    }
    float mx = -1e30f;
    #pragma unroll
    for (int s = 0; s < SS; s++) mx = fmaxf(mx, sc[s]);
    float sum = 0.f;
    #pragma unroll
    for (int s = 0; s < SS; s++) { sc[s] = expf(sc[s] - mx); sum += sc[s]; }
    const float inv = 1.f / sum;
    const int ob = (b*TT + c*CN + t)*SS;
    #pragma unroll
    for (int s = 0; s < SS; s++) g_w[ob + s] = sc[s] * inv;
}

// ---------------- 4) per-chunk update U --------------------------------------
__global__ void __launch_bounds__(256) u_kernel() {
    __shared__ float sV[128*64];
    __shared__ float sPw[128];
    const int dt = blockIdx.x, c = blockIdx.y, b = blockIdx.z;
    const int tid = threadIdx.x;
    if (tid < 128) sPw[tid] = powf(AVAL, (float)tid);
    #pragma unroll
    for (int l = 0; l < 8; l++) {
        const int f4 = tid + l * 256;
        const int r  = f4 >> 4;
        const int kc = (f4 & 15) << 2;
        float4 v4 = *(const float4*)(&g_v[(size_t)(b*TT + c*CN + r)*DD + dt*64 + kc]);
        sV[r*64 + kc+0] = v4.x; sV[r*64 + kc+1] = v4.y; sV[r*64 + kc+2] = v4.z; sV[r*64 + kc+3] = v4.w;
    }
    __syncthreads();
    const int s  = tid & 31;
    const int d0 = (tid >> 5) << 3;
    float acc[8];
    #pragma unroll
    for (int j = 0; j < 8; j++) acc[j] = 0.f;
    const float* wrow = &g_w[(b*TT + c*CN)*SS + s];
    for (int tau = 0; tau < CN; tau++) {
        const float wd = ALPHA * sPw[127 - tau] * wrow[tau*SS];
        #pragma unroll
        for (int j = 0; j < 8; j++) acc[j] += wd * sV[tau*64 + d0 + j];
    }
    const int ob = ((b*NCH + c)*SS + s)*DD + dt*64 + d0;
    #pragma unroll
    for (int j = 0; j < 8; j++) g_U[ob + j] = acc[j];
}

// ---------------- 5) sequential chunk scan (also emits Ms bf16 hi/lo) -------
__global__ void __launch_bounds__(256) scan_kernel(const float* __restrict__ state0,
                                                   float* __restrict__ outF) {
    const int idx = blockIdx.x * 256 + threadIdx.x;
    const int b = idx / (SS*DD);
    const int sd = idx - b*SS*DD;
    float m = state0[idx];
    const float dc = powf(AVAL, (float)CN);
    #pragma unroll
    for (int c = 0; c < NCH; c++) {
        const int o = (b*NCH + c)*SS*DD + sd;
        g_Ms[o] = m;
        __nv_bfloat16 hi = __float2bfloat16(m);
        g_Ms_hi[o] = hi;
        g_Ms_lo[o] = __float2bfloat16(m - __bfloat162float(hi));
        m = dc * m + g_U[o];
    }
    outF[idx] = m;
}

// ---------------- 6) R1 via HMMA split-K: P = q@v^T, QM = q@Ms^T ------------
// grid (4, NCH, BB); each CTA covers K slice of 256 (4 chunks of 64).
#define R1_QH 0
#define R1_QL (R1_QH + TILE_B)
#define R1_VH (R1_QL + TILE_B)
#define R1_VL (R1_VH + TILE_B)
#define R1_MH (R1_VL + TILE_B)
#define R1_ML (R1_MH + 32*TSTRIDE*2)
#define R1_SMEM (R1_ML + 32*TSTRIDE*2)
__global__ void __launch_bounds__(256) r1_tc_kernel() {
    extern __shared__ char sm1c[];
    const uint32_t smb = smem_u32(sm1c);
    const int kt = blockIdx.x, c = blockIdx.y, b = blockIdx.z;
    const int tid = threadIdx.x;
    const int wid = tid >> 5, lane = tid & 31;
    const int m_base = (wid >> 2) * 64;
    const int n_base = (wid & 3) * 32;
    const int nq_base = (wid & 3) * 8;

    float accP[4][4][4];
    float accQ[4][4];
    #pragma unroll
    for (int mi = 0; mi < 4; mi++) {
        #pragma unroll
        for (int r = 0; r < 4; r++) accQ[mi][r] = 0.f;
        #pragma unroll
        for (int nj = 0; nj < 4; nj++)
            #pragma unroll
            for (int r = 0; r < 4; r++) accP[mi][nj][r] = 0.f;
    }

    const int a_rr = lane & 15;
    const int a_kk = (lane >> 4) * 8;
    const int b_g  = lane >> 3;
    const int b_rr = lane & 7;
    const int b_nofs = (b_g >> 1) * 8;
    const int b_kofs = (b_g & 1) * 8;
    const int m_rr = lane & 7;
    const int m_kofs = ((lane >> 3) & 1) * 8;

    for (int ch = 0; ch < 4; ch++) {
        const int k0 = (kt * 4 + ch) * 64;
        #pragma unroll
        for (int l = 0; l < 4; l++) {
            const int idx = tid + l * 256;
            const int r = idx >> 3, c8 = (idx & 7) * 8;
            const uint32_t so = (uint32_t)(r * TSTRIDE + c8) * 2;
            const size_t gq = (size_t)(b*TT + c*CN + r)*DD + k0 + c8;
            *(uint4*)(sm1c + R1_QH + so) = *(const uint4*)(&g_q_hi[gq]);
            *(uint4*)(sm1c + R1_QL + so) = *(const uint4*)(&g_q_lo[gq]);
            *(uint4*)(sm1c + R1_VH + so) = *(const uint4*)(&g_v_hi[gq]);
            *(uint4*)(sm1c + R1_VL + so) = *(const uint4*)(&g_v_lo[gq]);
        }
        {
            const int r = tid >> 3, c8 = (tid & 7) * 8;
            const uint32_t so = (uint32_t)(r * TSTRIDE + c8) * 2;
            const size_t gm = (size_t)((b*NCH + c)*SS + r)*DD + k0 + c8;
            *(uint4*)(sm1c + R1_MH + so) = *(const uint4*)(&g_Ms_hi[gm]);
            *(uint4*)(sm1c + R1_ML + so) = *(const uint4*)(&g_Ms_lo[gm]);
        }
        __syncthreads();
        #pragma unroll
        for (int ks = 0; ks < 4; ks++) {
            uint32_t ah[4][4], al[4][4];
            #pragma unroll
            for (int mi = 0; mi < 4; mi++) {
                const uint32_t off = (uint32_t)((m_base + mi*16 + a_rr) * TSTRIDE + ks*16 + a_kk) * 2;
                LDMX4(ah[mi][0], ah[mi][1], ah[mi][2], ah[mi][3], smb + R1_QH + off);
                LDMX4(al[mi][0], al[mi][1], al[mi][2], al[mi][3], smb + R1_QL + off);
            }
            uint32_t bh[4][2], bl[4][2];
            #pragma unroll
            for (int ni = 0; ni < 2; ni++) {
                const uint32_t off = (uint32_t)((n_base + ni*16 + b_nofs + b_rr) * TSTRIDE + ks*16 + b_kofs) * 2;
                LDMX4(bh[2*ni][0], bh[2*ni][1], bh[2*ni+1][0], bh[2*ni+1][1], smb + R1_VH + off);
                LDMX4(bl[2*ni][0], bl[2*ni][1], bl[2*ni+1][0], bl[2*ni+1][1], smb + R1_VL + off);
            }
            uint32_t mh2[2], ml2[2];
            {
                const uint32_t off = (uint32_t)((nq_base + m_rr) * TSTRIDE + ks*16 + m_kofs) * 2;
                LDMX2(mh2[0], mh2[1], smb + R1_MH + off);
                LDMX2(ml2[0], ml2[1], smb + R1_ML + off);
            }
            #pragma unroll
            for (int mi = 0; mi < 4; mi++) {
                #pragma unroll
                for (int nj = 0; nj < 4; nj++) {
                    MMA16816(accP[mi][nj], ah[mi], bh[nj]);
                    MMA16816(accP[mi][nj], ah[mi], bl[nj]);
                    MMA16816(accP[mi][nj], al[mi], bh[nj]);
                }
                MMA16816(accQ[mi], ah[mi], mh2);
                MMA16816(accQ[mi], ah[mi], ml2);
                MMA16816(accQ[mi], al[mi], mh2);
            }
        }
        __syncthreads();
    }

    // epilogue: write raw partials for this K slice
    const int r0 = lane >> 2, c0 = (lane & 3) * 2;
    const size_t pb = ((size_t)kt*BB*NCH + (size_t)(b*NCH + c))*CN;
    #pragma unroll
    for (int mi = 0; mi < 4; mi++) {
        #pragma unroll
        for (int half = 0; half < 2; half++) {
            const int t = m_base + mi*16 + r0 + half*8;
            #pragma unroll
            for (int nj = 0; nj < 4; nj++) {
                const int tau0 = n_base + nj*8 + c0;
                *(float2*)(&g_Pp[(pb + t)*CN + tau0]) =
                    make_float2(accP[mi][nj][half*2 + 0], accP[mi][nj][half*2 + 1]);
            }
            const int s0 = nq_base + c0;
            *(float2*)(&g_QMp[(pb + t)*SS + s0]) =
                make_float2(accQ[mi][half*2 + 0], accQ[mi][half*2 + 1]);
        }
    }
}

// ---------------- 6b) reduce split-K partials, apply decay/mask/scale -------
__global__ void __launch_bounds__(128) reduce_p_kernel() {
    const int t = blockIdx.x, c = blockIdx.y, b = blockIdx.z;
    const int tau = threadIdx.x;
    const size_t base = ((size_t)(b*NCH + c)*CN + t);
    float sum = 0.f;
    #pragma unroll
    for (int kt = 0; kt < 4; kt++)
        sum += g_Pp[((size_t)kt*BB*NCH*CN + base)*CN + tau];
    const float out = (tau <= t) ? ALPHA * powf(AVAL, (float)(t - tau)) * sum : 0.f;
    g_P[base*CN + tau] = out;
    if (tau < SS) {
        float s2 = 0.f;
        #pragma unroll
        for (int kt = 0; kt < 4; kt++)
            s2 += g_QMp[((size_t)kt*BB*NCH*CN + base)*SS + tau];
        g_QM[base*SS + tau] = RSCALE * powf(AVAL, (float)(t + 1)) * s2;
    }
}

// ---------------- 7) R2: scores, softmax, G ---------------------------------
#define R2_SMEM ((128*129 + 128*33*2 + 132)*4)
__global__ void __launch_bounds__(256) r2_kernel() {
    extern __shared__ float sm2[];
    float* sP  = sm2;
    float* sW  = sP + 128*129;
    float* sA  = sW + 128*33;
    float* sPw = sA + 128*33;
    const int c = blockIdx.x, b = blockIdx.y;
    const int tid = threadIdx.x;
    if (tid < 132) sPw[tid] = powf(AVAL, (float)tid);
    __syncthreads();
    const int pbase = ((b*NCH + c)*CN)*CN;
    for (int e = tid; e < CN*CN; e += 256) {
        sP[(e >> 7)*129 + (e & 127)] = g_P[pbase + e];
    }
    const int qbase = ((b*NCH + c)*CN)*SS;
    for (int e = tid; e < CN*SS; e += 256) {
        sA[(e >> 5)*33 + (e & 31)] = g_QM[qbase + e];
    }
    for (int e = tid; e < CN*SS; e += 256) {
        const int t = e >> 5, s = e & 31;
        sW[t*33 + s] = g_w[(b*TT + c*CN + t)*SS + s];
    }
    __syncthreads();
    {
        const int t  = tid >> 1;
        const int s0 = (tid & 1) * 16;
        float r[16];
        #pragma unroll
        for (int sj = 0; sj < 16; sj++) r[sj] = 0.f;
        for (int tau = 0; tau <= t; tau++) {
            const float p = sP[t*129 + tau];
            #pragma unroll
            for (int sj = 0; sj < 16; sj++) r[sj] += p * sW[tau*33 + s0 + sj];
        }
        __syncthreads();
        #pragma unroll
        for (int sj = 0; sj < 16; sj++) sA[t*33 + s0 + sj] += RSCALE * r[sj];
    }
    __syncthreads();
    if (tid < 128) {
        const int t = tid;
        float mx = -1e30f;
        #pragma unroll
        for (int s = 0; s < SS; s++) mx = fmaxf(mx, sA[t*33 + s]);
        float ev[SS]; float sum = 0.f;
        #pragma unroll
        for (int s = 0; s < SS; s++) { ev[s] = expf(sA[t*33 + s] - mx); sum += ev[s]; }
        const float inv = 1.f / sum;
        const float pw = sPw[t + 1];
        const int ab = ((b*NCH + c)*CN + t)*SS;
        #pragma unroll
        for (int s = 0; s < SS; s++) {
            const float a = ev[s] * inv;
            sA[t*33 + s] = a;
            g_at[ab + s] = pw * a;
        }
    }
    __syncthreads();
    const int ty = tid >> 4, tx = tid & 15;
    const int gbase = ((b*NCH + c)*CN)*CN;
    #pragma unroll
    for (int i = 0; i < 8; i++) {
        const int t = ty*8 + i;
        #pragma unroll
        for (int j = 0; j < 8; j++) {
            const int tau = tx*8 + j;
            float g = 0.f;
            if (tau <= t) {
                #pragma unroll
                for (int s = 0; s < SS; s++) g += sA[t*33 + s] * sW[tau*33 + s];
                g *= ALPHA * sPw[t - tau];
            }
            g_G[gbase + t*CN + tau] = g;
        }
    }
}

// ---------------- 8) R3: ctx = G@v + (a^{t+1}attn)@Ms -----------------------
#define R3_SMEM ((128*129*2 + 32*129 + 128*33)*4)
__global__ void __launch_bounds__(256) r3_kernel(float* __restrict__ outC) {
    extern __shared__ float sm3[];
    float* sG  = sm3;
    float* sV  = sG + 128*129;
    float* sM  = sV + 128*129;
    float* sAt = sM + 32*129;
    const int dt = blockIdx.x, c = blockIdx.y, b = blockIdx.z;
    const int tid = threadIdx.x;
    const int ty = tid >> 4, tx = tid & 15;
    #pragma unroll
    for (int l = 0; l < 16; l++) {
        const int f4 = tid + l * 256;
        const int r  = f4 >> 5;
        const int kc = (f4 & 31) << 2;
        float4 gg = *(const float4*)(&g_G[((b*NCH + c)*CN + r)*CN + kc]);
        sG[r*129 + kc+0] = gg.x; sG[r*129 + kc+1] = gg.y; sG[r*129 + kc+2] = gg.z; sG[r*129 + kc+3] = gg.w;
        float4 v4 = *(const float4*)(&g_v[(size_t)(b*TT + c*CN + r)*DD + dt*128 + kc]);
        sV[r*129 + kc+0] = v4.x; sV[r*129 + kc+1] = v4.y; sV[r*129 + kc+2] = v4.z; sV[r*129 + kc+3] = v4.w;
    }
    #pragma unroll
    for (int l = 0; l < 4; l++) {
        const int f4 = tid + l * 256;
        const int r  = f4 >> 5;
        const int kc = (f4 & 31) << 2;
        float4 m4 = *(const float4*)(&g_Ms[((b*NCH + c)*SS + r)*DD + dt*128 + kc]);
        sM[r*129 + kc+0] = m4.x; sM[r*129 + kc+1] = m4.y; sM[r*129 + kc+2] = m4.z; sM[r*129 + kc+3] = m4.w;
    }
    #pragma unroll
    for (int l = 0; l < 4; l++) {
        const int f4 = tid + l * 256;
        const int r  = f4 >> 3;
        const int sc = (f4 & 7) << 2;
        float4 a4 = *(const float4*)(&g_at[((b*NCH + c)*CN + r)*SS + sc]);
        sAt[r*33 + sc+0] = a4.x; sAt[r*33 + sc+1] = a4.y; sAt[r*33 + sc+2] = a4.z; sAt[r*33 + sc+3] = a4.w;
    }
    __syncthreads();
    float acc[8][8];
    #pragma unroll
    for (int i = 0; i < 8; i++)
        #pragma unroll
        for (int j = 0; j < 8; j++) acc[i][j] = 0.f;
    const float* gb = sG + (ty*8)*129;
    for (int tau = 0; tau < 128; tau++) {
        float ar[8], br[8];
        #pragma unroll
        for (int i = 0; i < 8; i++) ar[i] = gb[i*129 + tau];
        #pragma unroll
        for (int j = 0; j < 8; j++) br[j] = sV[tau*129 + tx*8 + j];
        #pragma unroll
        for (int i = 0; i < 8; i++)
            #pragma unroll
            for (int j = 0; j < 8; j++) acc[i][j] += ar[i] * br[j];
    }
    const float* ab = sAt + (ty*8)*33;
    for (int s = 0; s < SS; s++) {
        float ar[8], br[8];
        #pragma unroll
        for (int i = 0; i < 8; i++) ar[i] = ab[i*33 + s];
        #pragma unroll
        for (int j = 0; j < 8; j++) br[j] = sM[s*129 + tx*8 + j];
        #pragma unroll
        for (int i = 0; i < 8; i++)
            #pragma unroll
            for (int j = 0; j < 8; j++) acc[i][j] += ar[i] * br[j];
    }
    #pragma unroll
    for (int i = 0; i < 8; i++) {
        const int row = b*TT + c*CN + ty*8 + i;
        #pragma unroll
        for (int j = 0; j < 8; j++)
            outC[(size_t)row*DD + dt*128 + tx*8 + j] = acc[i][j];
    }
}

extern "C" void kernel_launch(void* const* d_in, const int* in_sizes, int n_in,
                              void* d_out, int out_size) {
    (void)in_sizes; (void)n_in; (void)out_size;
    const float* h      = (const float*)d_in[0];
    const float* state0 = (const float*)d_in[1];
    const float* gamma  = (const float*)d_in[2];
    const float* beta   = (const float*)d_in[3];
    const float* Wq     = (const float*)d_in[4];
    const float* bq     = (const float*)d_in[5];
    const float* Wv     = (const float*)d_in[6];
    const float* bv     = (const float*)d_in[7];
    float* out = (float*)d_out;
    float* outCtx   = out;
    float* outFinal = out + (size_t)BB*TT*DD;

    cudaFuncSetAttribute(gemm_tc_kernel, cudaFuncAttributeMaxDynamicSharedMemorySize, GEMM_SMEM);
    cudaFuncSetAttribute(r1_tc_kernel, cudaFuncAttributeMaxDynamicSharedMemorySize, R1_SMEM);
    cudaFuncSetAttribute(r2_kernel, cudaFuncAttributeMaxDynamicSharedMemorySize, R2_SMEM);
    cudaFuncSetAttribute(r3_kernel, cudaFuncAttributeMaxDynamicSharedMemorySize, R3_SMEM);

    ln_kernel<<<BB*TT, 256>>>(h, gamma, beta);
    convw_kernel<<<2*DD*DD/1024, 256>>>(Wq, Wv);
    gemm_tc_kernel<<<dim3(DD/128, BB*TT/128, 2), 256, GEMM_SMEM>>>(bq, bv);
    route_part_kernel<<<dim3(8, NCH, BB), 256>>>(state0);
    route_red_kernel<<<dim3(NCH, BB), 128>>>();
    u_kernel<<<dim3(16, NCH, BB), 256>>>();
    scan_kernel<<<BB*SS*DD/256, 256>>>(state0, outFinal);
    r1_tc_kernel<<<dim3(4, NCH, BB), 256, R1_SMEM>>>();
    reduce_p_kernel<<<dim3(CN, NCH, BB), 128>>>();
    r2_kernel<<<dim3(NCH, BB), 256, R2_SMEM>>>();
    r3_kernel<<<dim3(DD/128, NCH, BB), 256, R3_SMEM>>>(outCtx);
}

// round 11
// speedup vs baseline: 1.4207x; 1.2688x over previous
#include <cuda_runtime.h>
#include <cuda_bf16.h>
#include <math.h>
#include <stdint.h>

#define BB 2
#define TT 2048
#define DD 1024
#define SS 32
#define CN 128
#define NCH 16
#define ALPHA 0.05f
#define AVAL 0.95f
#define RSCALE 0.03125f
#define LNEPS 1e-5f

// scratch (device globals; 16B-aligned for vectorized access)
__device__ __align__(16) __nv_bfloat16 g_hn_hi[BB*TT*DD];
__device__ __align__(16) __nv_bfloat16 g_hn_lo[BB*TT*DD];
__device__ __align__(16) __nv_bfloat16 g_W_hi [2*DD*DD];
__device__ __align__(16) __nv_bfloat16 g_W_lo [2*DD*DD];
__device__ __align__(16) float g_v  [BB*TT*DD];
__device__ __align__(16) __nv_bfloat16 g_q_hi[BB*TT*DD];
__device__ __align__(16) __nv_bfloat16 g_q_lo[BB*TT*DD];
__device__ __align__(16) __nv_bfloat16 g_v_hi[BB*TT*DD];
__device__ __align__(16) __nv_bfloat16 g_v_lo[BB*TT*DD];
__device__ __align__(16) float g_w  [BB*TT*SS];
__device__ __align__(16) float g_wsp[BB*NCH*8*CN*SS];
__device__ __align__(16) float g_U  [BB*NCH*SS*DD];
__device__ __align__(16) __nv_bfloat16 g_Ms_hi[BB*NCH*SS*DD];
__device__ __align__(16) __nv_bfloat16 g_Ms_lo[BB*NCH*SS*DD];
__device__ __align__(16) float g_Pp [4*BB*NCH*CN*CN];
__device__ __align__(16) float g_QMp[4*BB*NCH*CN*SS];
__device__ __align__(16) float g_P  [BB*NCH*CN*CN];
__device__ __align__(16) float g_QM [BB*NCH*CN*SS];
__device__ __align__(16) __nv_bfloat16 g_G_hi [BB*NCH*CN*CN];
__device__ __align__(16) __nv_bfloat16 g_G_lo [BB*NCH*CN*CN];
__device__ __align__(16) __nv_bfloat16 g_at_hi[BB*NCH*CN*SS];
__device__ __align__(16) __nv_bfloat16 g_at_lo[BB*NCH*CN*SS];

// ---------------- helpers ----------------------------------------------------
__device__ __forceinline__ uint32_t smem_u32(const void* p) {
    uint32_t a;
    asm("{ .reg .u64 t; cvta.to.shared.u64 t, %1; cvt.u32.u64 %0, t; }" : "=r"(a) : "l"(p));
    return a;
}
#define LDMX4(r0, r1, r2, r3, addr) \
    asm volatile("ldmatrix.sync.aligned.m8n8.x4.shared.b16 {%0,%1,%2,%3}, [%4];" \
        : "=r"(r0), "=r"(r1), "=r"(r2), "=r"(r3) : "r"(addr))
#define LDMX4T(r0, r1, r2, r3, addr) \
    asm volatile("ldmatrix.sync.aligned.m8n8.x4.trans.shared.b16 {%0,%1,%2,%3}, [%4];" \
        : "=r"(r0), "=r"(r1), "=r"(r2), "=r"(r3) : "r"(addr))
#define LDMX2(r0, r1, addr) \
    asm volatile("ldmatrix.sync.aligned.m8n8.x2.shared.b16 {%0,%1}, [%2];" \
        : "=r"(r0), "=r"(r1) : "r"(addr))
#define MMA16816(d, a, b) \
    asm volatile("mma.sync.aligned.m16n8k16.row.col.f32.bf16.bf16.f32 " \
        "{%0,%1,%2,%3}, {%4,%5,%6,%7}, {%8,%9}, {%0,%1,%2,%3};" \
        : "+f"((d)[0]), "+f"((d)[1]), "+f"((d)[2]), "+f"((d)[3]) \
        : "r"((a)[0]), "r"((a)[1]), "r"((a)[2]), "r"((a)[3]), "r"((b)[0]), "r"((b)[1]))
#define CP_ASYNC16(smaddr, gptr) \
    asm volatile("cp.async.cg.shared.global [%0], [%1], 16;" :: "r"(smaddr), "l"(gptr) : "memory")
#define CP_COMMIT() asm volatile("cp.async.commit_group;" ::: "memory")
#define CP_WAIT0()  asm volatile("cp.async.wait_group 0;" ::: "memory")

// ---------------- 1) LayerNorm -> bf16 hi/lo --------------------------------
__global__ void __launch_bounds__(256) ln_kernel(const float* __restrict__ h,
                                                 const float* __restrict__ gamma,
                                                 const float* __restrict__ beta) {
    __shared__ float sx[DD];
    __shared__ float sred[256];
    const int row = blockIdx.x;
    const float* hr = h + (size_t)row * DD;
    const int tid = threadIdx.x;
    float lsum = 0.f;
    for (int i = tid; i < DD; i += 256) { float x = hr[i]; sx[i] = x; lsum += x; }
    sred[tid] = lsum; __syncthreads();
    #pragma unroll
    for (int s = 128; s > 0; s >>= 1) { if (tid < s) sred[tid] += sred[tid + s]; __syncthreads(); }
    const float mu = sred[0] * (1.0f / DD);
    __syncthreads();
    float lvar = 0.f;
    for (int i = tid; i < DD; i += 256) { float d = sx[i] - mu; lvar += d * d; }
    sred[tid] = lvar; __syncthreads();
    #pragma unroll
    for (int s = 128; s > 0; s >>= 1) { if (tid < s) sred[tid] += sred[tid + s]; __syncthreads(); }
    const float rstd = rsqrtf(sred[0] * (1.0f / DD) + LNEPS);
    __nv_bfloat16* ohi = g_hn_hi + (size_t)row * DD;
    __nv_bfloat16* olo = g_hn_lo + (size_t)row * DD;
    for (int i = tid; i < DD; i += 256) {
        float y = (sx[i] - mu) * rstd * gamma[i] + beta[i];
        __nv_bfloat16 hi = __float2bfloat16(y);
        ohi[i] = hi;
        olo[i] = __float2bfloat16(y - __bfloat162float(hi));
    }
}

// ---------------- 1b) W -> bf16 hi/lo ---------------------------------------
__global__ void __launch_bounds__(256) convw_kernel(const float* __restrict__ Wq,
                                                    const float* __restrict__ Wv) {
    const size_t base = ((size_t)blockIdx.x * 256 + threadIdx.x) * 4;
    const float* W = (base < (size_t)DD*DD) ? Wq : Wv;
    const size_t off = (base < (size_t)DD*DD) ? base : base - (size_t)DD*DD;
    float4 x = *(const float4*)(&W[off]);
    __nv_bfloat16 h0 = __float2bfloat16(x.x), h1 = __float2bfloat16(x.y);
    __nv_bfloat16 h2 = __float2bfloat16(x.z), h3 = __float2bfloat16(x.w);
    *(__nv_bfloat162*)(&g_W_hi[base + 0]) = __nv_bfloat162(h0, h1);
    *(__nv_bfloat162*)(&g_W_hi[base + 2]) = __nv_bfloat162(h2, h3);
    *(__nv_bfloat162*)(&g_W_lo[base + 0]) = __nv_bfloat162(
        __float2bfloat16(x.x - __bfloat162float(h0)), __float2bfloat16(x.y - __bfloat162float(h1)));
    *(__nv_bfloat162*)(&g_W_lo[base + 2]) = __nv_bfloat162(
        __float2bfloat16(x.z - __bfloat162float(h2)), __float2bfloat16(x.w - __bfloat162float(h3)));
}

// ---------------- 2) q/v projection: mma.sync bf16, cp.async 2-stage --------
#define TSTRIDE 72
#define TILE_B (128*TSTRIDE*2)
#define GEMM_SMEM (8*TILE_B)
__global__ void __launch_bounds__(256) gemm_tc_kernel(const float* __restrict__ bq,
                                                      const float* __restrict__ bv) {
    extern __shared__ char smc[];
    const uint32_t smb = smem_u32(smc);
    const int tid = threadIdx.x;
    const int wid = tid >> 5, lane = tid & 31;
    const int n0 = blockIdx.x * 128;
    const int m0 = blockIdx.y * 128;
    const int z  = blockIdx.z;
    const __nv_bfloat16* Whi = g_W_hi + (size_t)z * DD * DD;
    const __nv_bfloat16* Wlo = g_W_lo + (size_t)z * DD * DD;
    const int m_base = (wid >> 2) * 64;
    const int n_base = (wid & 3) * 32;

    float acc[4][4][4];
    #pragma unroll
    for (int mi = 0; mi < 4; mi++)
        #pragma unroll
        for (int nj = 0; nj < 4; nj++)
            #pragma unroll
            for (int r = 0; r < 4; r++) acc[mi][nj][r] = 0.f;

    const int a_rr = lane & 15;
    const int a_kk = (lane >> 4) * 8;
    const int b_g  = lane >> 3;
    const int b_rr = lane & 7;
    const int b_nofs = (b_g >> 1) * 8;
    const int b_kofs = (b_g & 1) * 8;

    const int lr = tid >> 3, lc8 = (tid & 7) * 8;
    const uint32_t lso = (uint32_t)(lr * TSTRIDE + lc8) * 2;

    #pragma unroll
    for (int l = 0; l < 4; l++) {
        const int r = lr + l * 32;
        const size_t ga = (size_t)(m0 + r) * DD + lc8;
        const size_t gb = (size_t)(n0 + r) * DD + lc8;
        const uint32_t so = lso + (uint32_t)(l * 32 * TSTRIDE) * 2;
        CP_ASYNC16(smb + 0*TILE_B + so, &g_hn_hi[ga]);
        CP_ASYNC16(smb + 1*TILE_B + so, &g_hn_lo[ga]);
        CP_ASYNC16(smb + 2*TILE_B + so, &Whi[gb]);
        CP_ASYNC16(smb + 3*TILE_B + so, &Wlo[gb]);
    }
    CP_COMMIT(); CP_WAIT0(); __syncthreads();

    for (int ch = 0; ch < 16; ch++) {
        const int s = ch & 1;
        const uint32_t sb = smb + (uint32_t)s * 4 * TILE_B;
        if (ch + 1 < 16) {
            const uint32_t nb = smb + (uint32_t)(s ^ 1) * 4 * TILE_B;
            const int k0 = (ch + 1) * 64;
            #pragma unroll
            for (int l = 0; l < 4; l++) {
                const int r = lr + l * 32;
                const size_t ga = (size_t)(m0 + r) * DD + k0 + lc8;
                const size_t gb = (size_t)(n0 + r) * DD + k0 + lc8;
                const uint32_t so = lso + (uint32_t)(l * 32 * TSTRIDE) * 2;
                CP_ASYNC16(nb + 0*TILE_B + so, &g_hn_hi[ga]);
                CP_ASYNC16(nb + 1*TILE_B + so, &g_hn_lo[ga]);
                CP_ASYNC16(nb + 2*TILE_B + so, &Whi[gb]);
                CP_ASYNC16(nb + 3*TILE_B + so, &Wlo[gb]);
            }
            CP_COMMIT();
        }
        #pragma unroll
        for (int ks = 0; ks < 4; ks++) {
            uint32_t ah[4][4], al[4][4];
            #pragma unroll
            for (int mi = 0; mi < 4; mi++) {
                const uint32_t off = (uint32_t)((m_base + mi*16 + a_rr) * TSTRIDE + ks*16 + a_kk) * 2;
                LDMX4(ah[mi][0], ah[mi][1], ah[mi][2], ah[mi][3], sb + 0*TILE_B + off);
                LDMX4(al[mi][0], al[mi][1], al[mi][2], al[mi][3], sb + 1*TILE_B + off);
            }
            uint32_t bh[4][2], bl[4][2];
            #pragma unroll
            for (int ni = 0; ni < 2; ni++) {
                const uint32_t off = (uint32_t)((n_base + ni*16 + b_nofs + b_rr) * TSTRIDE + ks*16 + b_kofs) * 2;
                LDMX4(bh[2*ni][0], bh[2*ni][1], bh[2*ni+1][0], bh[2*ni+1][1], sb + 2*TILE_B + off);
                LDMX4(bl[2*ni][0], bl[2*ni][1], bl[2*ni+1][0], bl[2*ni+1][1], sb + 3*TILE_B + off);
            }
            #pragma unroll
            for (int mi = 0; mi < 4; mi++)
                #pragma unroll
                for (int nj = 0; nj < 4; nj++) {
                    MMA16816(acc[mi][nj], ah[mi], bh[nj]);
                    MMA16816(acc[mi][nj], ah[mi], bl[nj]);
                    MMA16816(acc[mi][nj], al[mi], bh[nj]);
                }
        }
        if (ch + 1 < 16) CP_WAIT0();
        __syncthreads();
    }

    __nv_bfloat16* Ch = z ? g_v_hi : g_q_hi;
    __nv_bfloat16* Cl = z ? g_v_lo : g_q_lo;
    const float* bias = z ? bv : bq;
    #pragma unroll
    for (int mi = 0; mi < 4; mi++) {
        const int row0 = m0 + m_base + mi*16 + (lane >> 2);
        #pragma unroll
        for (int nj = 0; nj < 4; nj++) {
            const int col = n0 + n_base + nj*8 + (lane & 3) * 2;
            const float b0 = bias[col], b1 = bias[col + 1];
            float2 v0 = { acc[mi][nj][0] + b0, acc[mi][nj][1] + b1 };
            float2 v1 = { acc[mi][nj][2] + b0, acc[mi][nj][3] + b1 };
            if (z) {
                *(float2*)(&g_v[(size_t)row0 * DD + col]) = v0;
                *(float2*)(&g_v[(size_t)(row0 + 8) * DD + col]) = v1;
            }
            __nv_bfloat16 h0 = __float2bfloat16(v0.x), h1 = __float2bfloat16(v0.y);
            __nv_bfloat16 h2 = __float2bfloat16(v1.x), h3 = __float2bfloat16(v1.y);
            *(__nv_bfloat162*)(&Ch[(size_t)row0 * DD + col]) = __nv_bfloat162(h0, h1);
            *(__nv_bfloat162*)(&Ch[(size_t)(row0 + 8) * DD + col]) = __nv_bfloat162(h2, h3);
            *(__nv_bfloat162*)(&Cl[(size_t)row0 * DD + col]) = __nv_bfloat162(
                __float2bfloat16(v0.x - __bfloat162float(h0)),
                __float2bfloat16(v0.y - __bfloat162float(h1)));
            *(__nv_bfloat162*)(&Cl[(size_t)(row0 + 8) * DD + col]) = __nv_bfloat162(
                __float2bfloat16(v1.x - __bfloat162float(h2)),
                __float2bfloat16(v1.y - __bfloat162float(h3)));
        }
    }
}

// ---------------- 3a) routing score partials (split-K, 8 x 128) -------------
__global__ void __launch_bounds__(256) route_part_kernel(const float* __restrict__ state0) {
    __shared__ float sQ[128][65];
    __shared__ float sS[32][65];
    const int kt = blockIdx.x, c = blockIdx.y, b = blockIdx.z;
    const int tid = threadIdx.x;
    const int t  = tid >> 1;
    const int sh = (tid & 1) * 16;
    float acc[16];
    #pragma unroll
    for (int j = 0; j < 16; j++) acc[j] = 0.f;
    #pragma unroll
    for (int ki = 0; ki < 2; ki++) {
        const int k0 = kt * 128 + ki * 64;
        #pragma unroll
        for (int l = 0; l < 8; l++) {
            const int f4 = tid + l * 256;
            const int r  = f4 >> 4;
            const int kc = (f4 & 15) << 2;
            const size_t gq = (size_t)(b*TT + c*CN + r)*DD + k0 + kc;
            __nv_bfloat162 a0 = *(const __nv_bfloat162*)(&g_q_hi[gq + 0]);
            __nv_bfloat162 a1 = *(const __nv_bfloat162*)(&g_q_hi[gq + 2]);
            __nv_bfloat162 l0 = *(const __nv_bfloat162*)(&g_q_lo[gq + 0]);
            __nv_bfloat162 l1 = *(const __nv_bfloat162*)(&g_q_lo[gq + 2]);
            sQ[r][kc+0] = __bfloat162float(a0.x) + __bfloat162float(l0.x);
            sQ[r][kc+1] = __bfloat162float(a0.y) + __bfloat162float(l0.y);
            sQ[r][kc+2] = __bfloat162float(a1.x) + __bfloat162float(l1.x);
            sQ[r][kc+3] = __bfloat162float(a1.y) + __bfloat162float(l1.y);
        }
        #pragma unroll
        for (int l = 0; l < 2; l++) {
            const int f4 = tid + l * 256;
            const int r  = f4 >> 4;
            const int kc = (f4 & 15) << 2;
            float4 s4 = *(const float4*)(&state0[(size_t)(b*SS + r)*DD + k0 + kc]);
            sS[r][kc+0] = s4.x; sS[r][kc+1] = s4.y; sS[r][kc+2] = s4.z; sS[r][kc+3] = s4.w;
        }
        __syncthreads();
        for (int k = 0; k < 64; k++) {
            const float qv = sQ[t][k];
            #pragma unroll
            for (int sj = 0; sj < 16; sj++) acc[sj] += qv * sS[sh + sj][k];
        }
        __syncthreads();
    }
    const int base = ((b*NCH + c)*8 + kt)*CN*SS + t*SS + sh;
    #pragma unroll
    for (int sj = 0; sj < 16; sj++) g_wsp[base + sj] = acc[sj];
}

// ---------------- 3b) reduce partials + softmax -> w ------------------------
__global__ void __launch_bounds__(128) route_red_kernel() {
    const int c = blockIdx.x, b = blockIdx.y;
    const int t = threadIdx.x;
    const int base = ((b*NCH + c)*8)*CN*SS + t*SS;
    float sc[SS];
    #pragma unroll
    for (int s = 0; s < SS; s++) {
        float sum = 0.f;
        #pragma unroll
        for (int kt = 0; kt < 8; kt++) sum += g_wsp[base + kt*CN*SS + s];
        sc[s] = sum * RSCALE;
    }
    float mx = -1e30f;
    #pragma unroll
    for (int s = 0; s < SS; s++) mx = fmaxf(mx, sc[s]);
    float sum = 0.f;
    #pragma unroll
    for (int s = 0; s < SS; s++) { sc[s] = expf(sc[s] - mx); sum += sc[s]; }
    const float inv = 1.f / sum;
    const int ob = (b*TT + c*CN + t)*SS;
    #pragma unroll
    for (int s = 0; s < SS; s++) g_w[ob + s] = sc[s] * inv;
}

// ---------------- 4) per-chunk update U --------------------------------------
__global__ void __launch_bounds__(256) u_kernel() {
    __shared__ float sV[128*64];
    __shared__ float sPw[128];
    const int dt = blockIdx.x, c = blockIdx.y, b = blockIdx.z;
    const int tid = threadIdx.x;
    if (tid < 128) sPw[tid] = powf(AVAL, (float)tid);
    #pragma unroll
    for (int l = 0; l < 8; l++) {
        const int f4 = tid + l * 256;
        const int r  = f4 >> 4;
        const int kc = (f4 & 15) << 2;
        float4 v4 = *(const float4*)(&g_v[(size_t)(b*TT + c*CN + r)*DD + dt*64 + kc]);
        sV[r*64 + kc+0] = v4.x; sV[r*64 + kc+1] = v4.y; sV[r*64 + kc+2] = v4.z; sV[r*64 + kc+3] = v4.w;
    }
    __syncthreads();
    const int s  = tid & 31;
    const int d0 = (tid >> 5) << 3;
    float acc[8];
    #pragma unroll
    for (int j = 0; j < 8; j++) acc[j] = 0.f;
    const float* wrow = &g_w[(b*TT + c*CN)*SS + s];
    for (int tau = 0; tau < CN; tau++) {
        const float wd = ALPHA * sPw[127 - tau] * wrow[tau*SS];
        #pragma unroll
        for (int j = 0; j < 8; j++) acc[j] += wd * sV[tau*64 + d0 + j];
    }
    const int ob = ((b*NCH + c)*SS + s)*DD + dt*64 + d0;
    #pragma unroll
    for (int j = 0; j < 8; j++) g_U[ob + j] = acc[j];
}

// ---------------- 5) sequential chunk scan (emits Ms bf16 hi/lo) ------------
__global__ void __launch_bounds__(256) scan_kernel(const float* __restrict__ state0,
                                                   float* __restrict__ outF) {
    const int idx = blockIdx.x * 256 + threadIdx.x;
    const int b = idx / (SS*DD);
    const int sd = idx - b*SS*DD;
    float m = state0[idx];
    const float dc = powf(AVAL, (float)CN);
    #pragma unroll
    for (int c = 0; c < NCH; c++) {
        const int o = (b*NCH + c)*SS*DD + sd;
        __nv_bfloat16 hi = __float2bfloat16(m);
        g_Ms_hi[o] = hi;
        g_Ms_lo[o] = __float2bfloat16(m - __bfloat162float(hi));
        m = dc * m + g_U[o];
    }
    outF[idx] = m;
}

// ---------------- 6) R1 via HMMA split-K: P = q@v^T, QM = q@Ms^T ------------
#define R1_QH 0
#define R1_QL (R1_QH + TILE_B)
#define R1_VH (R1_QL + TILE_B)
#define R1_VL (R1_VH + TILE_B)
#define R1_MH (R1_VL + TILE_B)
#define R1_ML (R1_MH + 32*TSTRIDE*2)
#define R1_SMEM (R1_ML + 32*TSTRIDE*2)
__global__ void __launch_bounds__(256) r1_tc_kernel() {
    extern __shared__ char sm1c[];
    const uint32_t smb = smem_u32(sm1c);
    const int kt = blockIdx.x, c = blockIdx.y, b = blockIdx.z;
    const int tid = threadIdx.x;
    const int wid = tid >> 5, lane = tid & 31;
    const int m_base = (wid >> 2) * 64;
    const int n_base = (wid & 3) * 32;
    const int nq_base = (wid & 3) * 8;

    float accP[4][4][4];
    float accQ[4][4];
    #pragma unroll
    for (int mi = 0; mi < 4; mi++) {
        #pragma unroll
        for (int r = 0; r < 4; r++) accQ[mi][r] = 0.f;
        #pragma unroll
        for (int nj = 0; nj < 4; nj++)
            #pragma unroll
            for (int r = 0; r < 4; r++) accP[mi][nj][r] = 0.f;
    }

    const int a_rr = lane & 15;
    const int a_kk = (lane >> 4) * 8;
    const int b_g  = lane >> 3;
    const int b_rr = lane & 7;
    const int b_nofs = (b_g >> 1) * 8;
    const int b_kofs = (b_g & 1) * 8;
    const int m_rr = lane & 7;
    const int m_kofs = ((lane >> 3) & 1) * 8;

    for (int ch = 0; ch < 4; ch++) {
        const int k0 = (kt * 4 + ch) * 64;
        #pragma unroll
        for (int l = 0; l < 4; l++) {
            const int idx = tid + l * 256;
            const int r = idx >> 3, c8 = (idx & 7) * 8;
            const uint32_t so = (uint32_t)(r * TSTRIDE + c8) * 2;
            const size_t gq = (size_t)(b*TT + c*CN + r)*DD + k0 + c8;
            *(uint4*)(sm1c + R1_QH + so) = *(const uint4*)(&g_q_hi[gq]);
            *(uint4*)(sm1c + R1_QL + so) = *(const uint4*)(&g_q_lo[gq]);
            *(uint4*)(sm1c + R1_VH + so) = *(const uint4*)(&g_v_hi[gq]);
            *(uint4*)(sm1c + R1_VL + so) = *(const uint4*)(&g_v_lo[gq]);
        }
        {
            const int r = tid >> 3, c8 = (tid & 7) * 8;
            const uint32_t so = (uint32_t)(r * TSTRIDE + c8) * 2;
            const size_t gm = (size_t)((b*NCH + c)*SS + r)*DD + k0 + c8;
            *(uint4*)(sm1c + R1_MH + so) = *(const uint4*)(&g_Ms_hi[gm]);
            *(uint4*)(sm1c + R1_ML + so) = *(const uint4*)(&g_Ms_lo[gm]);
        }
        __syncthreads();
        #pragma unroll
        for (int ks = 0; ks < 4; ks++) {
            uint32_t ah[4][4], al[4][4];
            #pragma unroll
            for (int mi = 0; mi < 4; mi++) {
                const uint32_t off = (uint32_t)((m_base + mi*16 + a_rr) * TSTRIDE + ks*16 + a_kk) * 2;
                LDMX4(ah[mi][0], ah[mi][1], ah[mi][2], ah[mi][3], smb + R1_QH + off);
                LDMX4(al[mi][0], al[mi][1], al[mi][2], al[mi][3], smb + R1_QL + off);
            }
            uint32_t bh[4][2], bl[4][2];
            #pragma unroll
            for (int ni = 0; ni < 2; ni++) {
                const uint32_t off = (uint32_t)((n_base + ni*16 + b_nofs + b_rr) * TSTRIDE + ks*16 + b_kofs) * 2;
                LDMX4(bh[2*ni][0], bh[2*ni][1], bh[2*ni+1][0], bh[2*ni+1][1], smb + R1_VH + off);
                LDMX4(bl[2*ni][0], bl[2*ni][1], bl[2*ni+1][0], bl[2*ni+1][1], smb + R1_VL + off);
            }
            uint32_t mh2[2], ml2[2];
            {
                const uint32_t off = (uint32_t)((nq_base + m_rr) * TSTRIDE + ks*16 + m_kofs) * 2;
                LDMX2(mh2[0], mh2[1], smb + R1_MH + off);
                LDMX2(ml2[0], ml2[1], smb + R1_ML + off);
            }
            #pragma unroll
            for (int mi = 0; mi < 4; mi++) {
                #pragma unroll
                for (int nj = 0; nj < 4; nj++) {
                    MMA16816(accP[mi][nj], ah[mi], bh[nj]);
                    MMA16816(accP[mi][nj], ah[mi], bl[nj]);
                    MMA16816(accP[mi][nj], al[mi], bh[nj]);
                }
                MMA16816(accQ[mi], ah[mi], mh2);
                MMA16816(accQ[mi], ah[mi], ml2);
                MMA16816(accQ[mi], al[mi], mh2);
            }
        }
        __syncthreads();
    }

    const int r0 = lane >> 2, c0 = (lane & 3) * 2;
    const size_t pb = ((size_t)kt*BB*NCH + (size_t)(b*NCH + c))*CN;
    #pragma unroll
    for (int mi = 0; mi < 4; mi++) {
        #pragma unroll
        for (int half = 0; half < 2; half++) {
            const int t = m_base + mi*16 + r0 + half*8;
            #pragma unroll
            for (int nj = 0; nj < 4; nj++) {
                const int tau0 = n_base + nj*8 + c0;
                *(float2*)(&g_Pp[(pb + t)*CN + tau0]) =
                    make_float2(accP[mi][nj][half*2 + 0], accP[mi][nj][half*2 + 1]);
            }
            const int s0 = nq_base + c0;
            *(float2*)(&g_QMp[(pb + t)*SS + s0]) =
                make_float2(accQ[mi][half*2 + 0], accQ[mi][half*2 + 1]);
        }
    }
}

// ---------------- 6b) reduce split-K partials, apply decay/mask/scale -------
__global__ void __launch_bounds__(128) reduce_p_kernel() {
    const int t = blockIdx.x, c = blockIdx.y, b = blockIdx.z;
    const int tau = threadIdx.x;
    const size_t base = ((size_t)(b*NCH + c)*CN + t);
    float sum = 0.f;
    #pragma unroll
    for (int kt = 0; kt < 4; kt++)
        sum += g_Pp[((size_t)kt*BB*NCH*CN + base)*CN + tau];
    const float out = (tau <= t) ? ALPHA * powf(AVAL, (float)(t - tau)) * sum : 0.f;
    g_P[base*CN + tau] = out;
    if (tau < SS) {
        float s2 = 0.f;
        #pragma unroll
        for (int kt = 0; kt < 4; kt++)
            s2 += g_QMp[((size_t)kt*BB*NCH*CN + base)*SS + tau];
        g_QM[base*SS + tau] = RSCALE * powf(AVAL, (float)(t + 1)) * s2;
    }
}

// ---------------- 7) R2: scores, softmax, G (emits bf16 hi/lo) ---------------
#define R2_SMEM ((128*129 + 128*33*2 + 132)*4)
__global__ void __launch_bounds__(256) r2_kernel() {
    extern __shared__ float sm2[];
    float* sP  = sm2;
    float* sW  = sP + 128*129;
    float* sA  = sW + 128*33;
    float* sPw = sA + 128*33;
    const int c = blockIdx.x, b = blockIdx.y;
    const int tid = threadIdx.x;
    if (tid < 132) sPw[tid] = powf(AVAL, (float)tid);
    __syncthreads();
    const int pbase = ((b*NCH + c)*CN)*CN;
    for (int e = tid; e < CN*CN; e += 256) {
        sP[(e >> 7)*129 + (e & 127)] = g_P[pbase + e];
    }
    const int qbase = ((b*NCH + c)*CN)*SS;
    for (int e = tid; e < CN*SS; e += 256) {
        sA[(e >> 5)*33 + (e & 31)] = g_QM[qbase + e];
    }
    for (int e = tid; e < CN*SS; e += 256) {
        const int t = e >> 5, s = e & 31;
        sW[t*33 + s] = g_w[(b*TT + c*CN + t)*SS + s];
    }
    __syncthreads();
    {
        const int t  = tid >> 1;
        const int s0 = (tid & 1) * 16;
        float r[16];
        #pragma unroll
        for (int sj = 0; sj < 16; sj++) r[sj] = 0.f;
        for (int tau = 0; tau <= t; tau++) {
            const float p = sP[t*129 + tau];
            #pragma unroll
            for (int sj = 0; sj < 16; sj++) r[sj] += p * sW[tau*33 + s0 + sj];
        }
        __syncthreads();
        #pragma unroll
        for (int sj = 0; sj < 16; sj++) sA[t*33 + s0 + sj] += RSCALE * r[sj];
    }
    __syncthreads();
    if (tid < 128) {
        const int t = tid;
        float mx = -1e30f;
        #pragma unroll
        for (int s = 0; s < SS; s++) mx = fmaxf(mx, sA[t*33 + s]);
        float ev[SS]; float sum = 0.f;
        #pragma unroll
        for (int s = 0; s < SS; s++) { ev[s] = expf(sA[t*33 + s] - mx); sum += ev[s]; }
        const float inv = 1.f / sum;
        const float pw = sPw[t + 1];
        const int ab = ((b*NCH + c)*CN + t)*SS;
        #pragma unroll
        for (int s = 0; s < SS; s++) {
            const float a = ev[s] * inv;
            sA[t*33 + s] = a;
            const float av = pw * a;
            __nv_bfloat16 hi = __float2bfloat16(av);
            g_at_hi[ab + s] = hi;
            g_at_lo[ab + s] = __float2bfloat16(av - __bfloat162float(hi));
        }
    }
    __syncthreads();
    const int ty = tid >> 4, tx = tid & 15;
    const int gbase = ((b*NCH + c)*CN)*CN;
    #pragma unroll
    for (int i = 0; i < 8; i++) {
        const int t = ty*8 + i;
        #pragma unroll
        for (int j = 0; j < 8; j++) {
            const int tau = tx*8 + j;
            float g = 0.f;
            if (tau <= t) {
                #pragma unroll
                for (int s = 0; s < SS; s++) g += sA[t*33 + s] * sW[tau*33 + s];
                g *= ALPHA * sPw[t - tau];
            }
            __nv_bfloat16 hi = __float2bfloat16(g);
            g_G_hi[gbase + t*CN + tau] = hi;
            g_G_lo[gbase + t*CN + tau] = __float2bfloat16(g - __bfloat162float(hi));
        }
    }
}

// ---------------- 8) R3 via HMMA: ctx = G@v + at@Ms --------------------------
// 128-wide tiles use stride VSTR=136 (272B rows, 16B multiple); at uses ATSTR=40.
#define VSTR 136
#define ATSTR 40
#define R3_TILE (128*VSTR*2)
#define R3_GH 0
#define R3_GL (R3_GH + R3_TILE)
#define R3_VH (R3_GL + R3_TILE)
#define R3_VL (R3_VH + R3_TILE)
#define R3_AH (R3_VL + R3_TILE)
#define R3_AL (R3_AH + 128*ATSTR*2)
#define R3_MH (R3_AL + 128*ATSTR*2)
#define R3_ML (R3_MH + 32*VSTR*2)
#define R3_SMEM (R3_ML + 32*VSTR*2)
__global__ void __launch_bounds__(256) r3_tc_kernel(float* __restrict__ outC) {
    extern __shared__ char sm3c[];
    const uint32_t smb = smem_u32(sm3c);
    const int dt = blockIdx.x, c = blockIdx.y, b = blockIdx.z;
    const int tid = threadIdx.x;
    const int wid = tid >> 5, lane = tid & 31;
    const int m_base = (wid >> 2) * 64;
    const int n_base = (wid & 3) * 32;

    // stage G (128x128) and v slice (128x128) at stride VSTR
    #pragma unroll
    for (int l = 0; l < 8; l++) {
        const int idx = tid + l * 256;
        const int r = idx >> 4, c8 = (idx & 15) * 8;
        const uint32_t so = (uint32_t)(r * VSTR + c8) * 2;
        const size_t gg = ((size_t)(b*NCH + c)*CN + r)*CN + c8;
        *(uint4*)(sm3c + R3_GH + so) = *(const uint4*)(&g_G_hi[gg]);
        *(uint4*)(sm3c + R3_GL + so) = *(const uint4*)(&g_G_lo[gg]);
        const size_t gv = (size_t)(b*TT + c*CN + r)*DD + dt*128 + c8;
        *(uint4*)(sm3c + R3_VH + so) = *(const uint4*)(&g_v_hi[gv]);
        *(uint4*)(sm3c + R3_VL + so) = *(const uint4*)(&g_v_lo[gv]);
    }
    // stage at (128x32, stride ATSTR) and Ms slice (32x128, stride VSTR)
    #pragma unroll
    for (int l = 0; l < 2; l++) {
        const int idx = tid + l * 256;
        {
            const int r = idx >> 2, s8 = (idx & 3) * 8;
            const uint32_t so = (uint32_t)(r * ATSTR + s8) * 2;
            const size_t ga = ((size_t)(b*NCH + c)*CN + r)*SS + s8;
            *(uint4*)(sm3c + R3_AH + so) = *(const uint4*)(&g_at_hi[ga]);
            *(uint4*)(sm3c + R3_AL + so) = *(const uint4*)(&g_at_lo[ga]);
        }
        {
            const int r = idx >> 4, c8 = (idx & 15) * 8;
            const uint32_t so = (uint32_t)(r * VSTR + c8) * 2;
            const size_t gm = ((size_t)(b*NCH + c)*SS + r)*DD + dt*128 + c8;
            *(uint4*)(sm3c + R3_MH + so) = *(const uint4*)(&g_Ms_hi[gm]);
            *(uint4*)(sm3c + R3_ML + so) = *(const uint4*)(&g_Ms_lo[gm]);
        }
    }
    __syncthreads();

    float acc[4][4][4];
    #pragma unroll
    for (int mi = 0; mi < 4; mi++)
        #pragma unroll
        for (int nj = 0; nj < 4; nj++)
            #pragma unroll
            for (int r = 0; r < 4; r++) acc[mi][nj][r] = 0.f;

    const int a_rr = lane & 15;
    const int a_kk = (lane >> 4) * 8;
    const int tb_g  = lane >> 3;
    const int tb_rr = lane & 7;
    const int t_koff = (tb_g & 1) * 8;
    const int t_noff = (tb_g >> 1) * 8;

    // term 1: G @ v  (k = tau, 8 chunks of 16)
    #pragma unroll
    for (int ks = 0; ks < 8; ks++) {
        uint32_t ah[4][4], al[4][4];
        #pragma unroll
        for (int mi = 0; mi < 4; mi++) {
            const uint32_t off = (uint32_t)((m_base + mi*16 + a_rr) * VSTR + ks*16 + a_kk) * 2;
            LDMX4(ah[mi][0], ah[mi][1], ah[mi][2], ah[mi][3], smb + R3_GH + off);
            LDMX4(al[mi][0], al[mi][1], al[mi][2], al[mi][3], smb + R3_GL + off);
        }
        uint32_t bh[4][2], bl[4][2];
        #pragma unroll
        for (int ni = 0; ni < 2; ni++) {
            const uint32_t off = (uint32_t)((ks*16 + t_koff + tb_rr) * VSTR + n_base + ni*16 + t_noff) * 2;
            LDMX4T(bh[2*ni][0], bh[2*ni][1], bh[2*ni+1][0], bh[2*ni+1][1], smb + R3_VH + off);
            LDMX4T(bl[2*ni][0], bl[2*ni][1], bl[2*ni+1][0], bl[2*ni+1][1], smb + R3_VL + off);
        }
        #pragma unroll
        for (int mi = 0; mi < 4; mi++)
            #pragma unroll
            for (int nj = 0; nj < 4; nj++) {
                MMA16816(acc[mi][nj], ah[mi], bh[nj]);
                MMA16816(acc[mi][nj], ah[mi], bl[nj]);
                MMA16816(acc[mi][nj], al[mi], bh[nj]);
            }
    }
    // term 2: at @ Ms  (k = s, 2 chunks of 16)
    #pragma unroll
    for (int ks = 0; ks < 2; ks++) {
        uint32_t ah[4][4], al[4][4];
        #pragma unroll
        for (int mi = 0; mi < 4; mi++) {
            const uint32_t off = (uint32_t)((m_base + mi*16 + a_rr) * ATSTR + ks*16 + a_kk) * 2;
            LDMX4(ah[mi][0], ah[mi][1], ah[mi][2], ah[mi][3], smb + R3_AH + off);
            LDMX4(al[mi][0], al[mi][1], al[mi][2], al[mi][3], smb + R3_AL + off);
        }
        uint32_t bh[4][2], bl[4][2];
        #pragma unroll
        for (int ni = 0; ni < 2; ni++) {
            const uint32_t off = (uint32_t)((ks*16 + t_koff + tb_rr) * VSTR + n_base + ni*16 + t_noff) * 2;
            LDMX4T(bh[2*ni][0], bh[2*ni][1], bh[2*ni+1][0], bh[2*ni+1][1], smb + R3_MH + off);
            LDMX4T(bl[2*ni][0], bl[2*ni][1], bl[2*ni+1][0], bl[2*ni+1][1], smb + R3_ML + off);
        }
        #pragma unroll
        for (int mi = 0; mi < 4; mi++)
            #pragma unroll
            for (int nj = 0; nj < 4; nj++) {
                MMA16816(acc[mi][nj], ah[mi], bh[nj]);
                MMA16816(acc[mi][nj], ah[mi], bl[nj]);
                MMA16816(acc[mi][nj], al[mi], bh[nj]);
            }
    }

    #pragma unroll
    for (int mi = 0; mi < 4; mi++) {
        const int row0 = b*TT + c*CN + m_base + mi*16 + (lane >> 2);
        #pragma unroll
        for (int nj = 0; nj < 4; nj++) {
            const int col = dt*128 + n_base + nj*8 + (lane & 3) * 2;
            *(float2*)(&outC[(size_t)row0 * DD + col]) = make_float2(acc[mi][nj][0], acc[mi][nj][1]);
            *(float2*)(&outC[(size_t)(row0 + 8) * DD + col]) = make_float2(acc[mi][nj][2], acc[mi][nj][3]);
        }
    }
}

extern "C" void kernel_launch(void* const* d_in, const int* in_sizes, int n_in,
                              void* d_out, int out_size) {
    (void)in_sizes; (void)n_in; (void)out_size;
    const float* h      = (const float*)d_in[0];
    const float* state0 = (const float*)d_in[1];
    const float* gamma  = (const float*)d_in[2];
    const float* beta   = (const float*)d_in[3];
    const float* Wq     = (const float*)d_in[4];
    const float* bq     = (const float*)d_in[5];
    const float* Wv     = (const float*)d_in[6];
    const float* bv     = (const float*)d_in[7];
    float* out = (float*)d_out;
    float* outCtx   = out;
    float* outFinal = out + (size_t)BB*TT*DD;

    cudaFuncSetAttribute(gemm_tc_kernel, cudaFuncAttributeMaxDynamicSharedMemorySize, GEMM_SMEM);
    cudaFuncSetAttribute(r1_tc_kernel, cudaFuncAttributeMaxDynamicSharedMemorySize, R1_SMEM);
    cudaFuncSetAttribute(r2_kernel, cudaFuncAttributeMaxDynamicSharedMemorySize, R2_SMEM);
    cudaFuncSetAttribute(r3_tc_kernel, cudaFuncAttributeMaxDynamicSharedMemorySize, R3_SMEM);

    ln_kernel<<<BB*TT, 256>>>(h, gamma, beta);
    convw_kernel<<<2*DD*DD/1024, 256>>>(Wq, Wv);
    gemm_tc_kernel<<<dim3(DD/128, BB*TT/128, 2), 256, GEMM_SMEM>>>(bq, bv);
    route_part_kernel<<<dim3(8, NCH, BB), 256>>>(state0);
    route_red_kernel<<<dim3(NCH, BB), 128>>>();
    u_kernel<<<dim3(16, NCH, BB), 256>>>();
    scan_kernel<<<BB*SS*DD/256, 256>>>(state0, outFinal);
    r1_tc_kernel<<<dim3(4, NCH, BB), 256, R1_SMEM>>>();
    reduce_p_kernel<<<dim3(CN, NCH, BB), 128>>>();
    r2_kernel<<<dim3(NCH, BB), 256, R2_SMEM>>>();
    r3_tc_kernel<<<dim3(DD/128, NCH, BB), 256, R3_SMEM>>>(outCtx);
}

// round 12
// speedup vs baseline: 1.5609x; 1.0987x over previous
#include <cuda_runtime.h>
#include <cuda_bf16.h>
#include <math.h>
#include <stdint.h>

#define BB 2
#define TT 2048
#define DD 1024
#define SS 32
#define CN 128
#define NCH 16
#define ALPHA 0.05f
#define AVAL 0.95f
#define RSCALE 0.03125f
#define LNEPS 1e-5f

// scratch (device globals; 16B-aligned for vectorized access)
__device__ __align__(16) __nv_bfloat16 g_hn_hi[BB*TT*DD];
__device__ __align__(16) __nv_bfloat16 g_hn_lo[BB*TT*DD];
__device__ __align__(16) __nv_bfloat16 g_W_hi [2*DD*DD];
__device__ __align__(16) __nv_bfloat16 g_W_lo [2*DD*DD];
__device__ __align__(16) __nv_bfloat16 g_q_hi[BB*TT*DD];
__device__ __align__(16) __nv_bfloat16 g_q_lo[BB*TT*DD];
__device__ __align__(16) __nv_bfloat16 g_v_hi[BB*TT*DD];
__device__ __align__(16) __nv_bfloat16 g_v_lo[BB*TT*DD];
__device__ __align__(16) __nv_bfloat16 g_s0_hi[BB*SS*DD];
__device__ __align__(16) __nv_bfloat16 g_s0_lo[BB*SS*DD];
__device__ __align__(16) float g_w  [BB*TT*SS];
__device__ __align__(16) float g_wsp[4*BB*NCH*CN*SS];
__device__ __align__(16) __nv_bfloat16 g_wdT_hi[BB*NCH*SS*CN];
__device__ __align__(16) __nv_bfloat16 g_wdT_lo[BB*NCH*SS*CN];
__device__ __align__(16) float g_U  [BB*NCH*SS*DD];
__device__ __align__(16) __nv_bfloat16 g_Ms_hi[BB*NCH*SS*DD];
__device__ __align__(16) __nv_bfloat16 g_Ms_lo[BB*NCH*SS*DD];
__device__ __align__(16) float g_Pp [4*BB*NCH*CN*CN];
__device__ __align__(16) float g_QMp[4*BB*NCH*CN*SS];
__device__ __align__(16) float g_P  [BB*NCH*CN*CN];
__device__ __align__(16) float g_QM [BB*NCH*CN*SS];
__device__ __align__(16) __nv_bfloat16 g_G_hi [BB*NCH*CN*CN];
__device__ __align__(16) __nv_bfloat16 g_G_lo [BB*NCH*CN*CN];
__device__ __align__(16) __nv_bfloat16 g_at_hi[BB*NCH*CN*SS];
__device__ __align__(16) __nv_bfloat16 g_at_lo[BB*NCH*CN*SS];

// ---------------- helpers ----------------------------------------------------
__device__ __forceinline__ uint32_t smem_u32(const void* p) {
    uint32_t a;
    asm("{ .reg .u64 t; cvta.to.shared.u64 t, %1; cvt.u32.u64 %0, t; }" : "=r"(a) : "l"(p));
    return a;
}
#define LDMX4(r0, r1, r2, r3, addr) \
    asm volatile("ldmatrix.sync.aligned.m8n8.x4.shared.b16 {%0,%1,%2,%3}, [%4];" \
        : "=r"(r0), "=r"(r1), "=r"(r2), "=r"(r3) : "r"(addr))
#define LDMX4T(r0, r1, r2, r3, addr) \
    asm volatile("ldmatrix.sync.aligned.m8n8.x4.trans.shared.b16 {%0,%1,%2,%3}, [%4];" \
        : "=r"(r0), "=r"(r1), "=r"(r2), "=r"(r3) : "r"(addr))
#define LDMX2(r0, r1, addr) \
    asm volatile("ldmatrix.sync.aligned.m8n8.x2.shared.b16 {%0,%1}, [%2];" \
        : "=r"(r0), "=r"(r1) : "r"(addr))
#define MMA16816(d, a, b) \
    asm volatile("mma.sync.aligned.m16n8k16.row.col.f32.bf16.bf16.f32 " \
        "{%0,%1,%2,%3}, {%4,%5,%6,%7}, {%8,%9}, {%0,%1,%2,%3};" \
        : "+f"((d)[0]), "+f"((d)[1]), "+f"((d)[2]), "+f"((d)[3]) \
        : "r"((a)[0]), "r"((a)[1]), "r"((a)[2]), "r"((a)[3]), "r"((b)[0]), "r"((b)[1]))
#define CP_ASYNC16(smaddr, gptr) \
    asm volatile("cp.async.cg.shared.global [%0], [%1], 16;" :: "r"(smaddr), "l"(gptr) : "memory")
#define CP_COMMIT() asm volatile("cp.async.commit_group;" ::: "memory")
#define CP_WAIT0()  asm volatile("cp.async.wait_group 0;" ::: "memory")

__device__ __forceinline__ void split_store(__nv_bfloat16* hi, __nv_bfloat16* lo,
                                            size_t idx, float v) {
    __nv_bfloat16 h = __float2bfloat16(v);
    hi[idx] = h;
    lo[idx] = __float2bfloat16(v - __bfloat162float(h));
}

// ---------------- 1) LayerNorm -> bf16 hi/lo --------------------------------
__global__ void __launch_bounds__(256) ln_kernel(const float* __restrict__ h,
                                                 const float* __restrict__ gamma,
                                                 const float* __restrict__ beta) {
    __shared__ float sx[DD];
    __shared__ float sred[256];
    const int row = blockIdx.x;
    const float* hr = h + (size_t)row * DD;
    const int tid = threadIdx.x;
    float lsum = 0.f;
    for (int i = tid; i < DD; i += 256) { float x = hr[i]; sx[i] = x; lsum += x; }
    sred[tid] = lsum; __syncthreads();
    #pragma unroll
    for (int s = 128; s > 0; s >>= 1) { if (tid < s) sred[tid] += sred[tid + s]; __syncthreads(); }
    const float mu = sred[0] * (1.0f / DD);
    __syncthreads();
    float lvar = 0.f;
    for (int i = tid; i < DD; i += 256) { float d = sx[i] - mu; lvar += d * d; }
    sred[tid] = lvar; __syncthreads();
    #pragma unroll
    for (int s = 128; s > 0; s >>= 1) { if (tid < s) sred[tid] += sred[tid + s]; __syncthreads(); }
    const float rstd = rsqrtf(sred[0] * (1.0f / DD) + LNEPS);
    __nv_bfloat16* ohi = g_hn_hi + (size_t)row * DD;
    __nv_bfloat16* olo = g_hn_lo + (size_t)row * DD;
    for (int i = tid; i < DD; i += 256) {
        float y = (sx[i] - mu) * rstd * gamma[i] + beta[i];
        __nv_bfloat16 hi = __float2bfloat16(y);
        ohi[i] = hi;
        olo[i] = __float2bfloat16(y - __bfloat162float(hi));
    }
}

// ---------------- 1b) W -> bf16 hi/lo ---------------------------------------
__global__ void __launch_bounds__(256) convw_kernel(const float* __restrict__ Wq,
                                                    const float* __restrict__ Wv) {
    const size_t base = ((size_t)blockIdx.x * 256 + threadIdx.x) * 4;
    const float* W = (base < (size_t)DD*DD) ? Wq : Wv;
    const size_t off = (base < (size_t)DD*DD) ? base : base - (size_t)DD*DD;
    float4 x = *(const float4*)(&W[off]);
    split_store(g_W_hi, g_W_lo, base + 0, x.x);
    split_store(g_W_hi, g_W_lo, base + 1, x.y);
    split_store(g_W_hi, g_W_lo, base + 2, x.z);
    split_store(g_W_hi, g_W_lo, base + 3, x.w);
}

// ---------------- 1c) state0 -> bf16 hi/lo ----------------------------------
__global__ void __launch_bounds__(256) convs_kernel(const float* __restrict__ s0) {
    const size_t base = ((size_t)blockIdx.x * 256 + threadIdx.x) * 4;
    float4 x = *(const float4*)(&s0[base]);
    split_store(g_s0_hi, g_s0_lo, base + 0, x.x);
    split_store(g_s0_hi, g_s0_lo, base + 1, x.y);
    split_store(g_s0_hi, g_s0_lo, base + 2, x.z);
    split_store(g_s0_hi, g_s0_lo, base + 3, x.w);
}

// ---------------- 2) q/v projection: mma.sync bf16, cp.async 2-stage --------
#define TSTRIDE 72
#define TILE_B (128*TSTRIDE*2)
#define GEMM_SMEM (8*TILE_B)
__global__ void __launch_bounds__(256) gemm_tc_kernel(const float* __restrict__ bq,
                                                      const float* __restrict__ bv) {
    extern __shared__ char smc[];
    const uint32_t smb = smem_u32(smc);
    const int tid = threadIdx.x;
    const int wid = tid >> 5, lane = tid & 31;
    const int n0 = blockIdx.x * 128;
    const int m0 = blockIdx.y * 128;
    const int z  = blockIdx.z;
    const __nv_bfloat16* Whi = g_W_hi + (size_t)z * DD * DD;
    const __nv_bfloat16* Wlo = g_W_lo + (size_t)z * DD * DD;
    const int m_base = (wid >> 2) * 64;
    const int n_base = (wid & 3) * 32;

    float acc[4][4][4];
    #pragma unroll
    for (int mi = 0; mi < 4; mi++)
        #pragma unroll
        for (int nj = 0; nj < 4; nj++)
            #pragma unroll
            for (int r = 0; r < 4; r++) acc[mi][nj][r] = 0.f;

    const int a_rr = lane & 15;
    const int a_kk = (lane >> 4) * 8;
    const int b_g  = lane >> 3;
    const int b_rr = lane & 7;
    const int b_nofs = (b_g >> 1) * 8;
    const int b_kofs = (b_g & 1) * 8;

    const int lr = tid >> 3, lc8 = (tid & 7) * 8;
    const uint32_t lso = (uint32_t)(lr * TSTRIDE + lc8) * 2;

    #pragma unroll
    for (int l = 0; l < 4; l++) {
        const int r = lr + l * 32;
        const size_t ga = (size_t)(m0 + r) * DD + lc8;
        const size_t gb = (size_t)(n0 + r) * DD + lc8;
        const uint32_t so = lso + (uint32_t)(l * 32 * TSTRIDE) * 2;
        CP_ASYNC16(smb + 0*TILE_B + so, &g_hn_hi[ga]);
        CP_ASYNC16(smb + 1*TILE_B + so, &g_hn_lo[ga]);
        CP_ASYNC16(smb + 2*TILE_B + so, &Whi[gb]);
        CP_ASYNC16(smb + 3*TILE_B + so, &Wlo[gb]);
    }
    CP_COMMIT(); CP_WAIT0(); __syncthreads();

    for (int ch = 0; ch < 16; ch++) {
        const int s = ch & 1;
        const uint32_t sb = smb + (uint32_t)s * 4 * TILE_B;
        if (ch + 1 < 16) {
            const uint32_t nb = smb + (uint32_t)(s ^ 1) * 4 * TILE_B;
            const int k0 = (ch + 1) * 64;
            #pragma unroll
            for (int l = 0; l < 4; l++) {
                const int r = lr + l * 32;
                const size_t ga = (size_t)(m0 + r) * DD + k0 + lc8;
                const size_t gb = (size_t)(n0 + r) * DD + k0 + lc8;
                const uint32_t so = lso + (uint32_t)(l * 32 * TSTRIDE) * 2;
                CP_ASYNC16(nb + 0*TILE_B + so, &g_hn_hi[ga]);
                CP_ASYNC16(nb + 1*TILE_B + so, &g_hn_lo[ga]);
                CP_ASYNC16(nb + 2*TILE_B + so, &Whi[gb]);
                CP_ASYNC16(nb + 3*TILE_B + so, &Wlo[gb]);
            }
            CP_COMMIT();
        }
        #pragma unroll
        for (int ks = 0; ks < 4; ks++) {
            uint32_t ah[4][4], al[4][4];
            #pragma unroll
            for (int mi = 0; mi < 4; mi++) {
                const uint32_t off = (uint32_t)((m_base + mi*16 + a_rr) * TSTRIDE + ks*16 + a_kk) * 2;
                LDMX4(ah[mi][0], ah[mi][1], ah[mi][2], ah[mi][3], sb + 0*TILE_B + off);
                LDMX4(al[mi][0], al[mi][1], al[mi][2], al[mi][3], sb + 1*TILE_B + off);
            }
            uint32_t bh[4][2], bl[4][2];
            #pragma unroll
            for (int ni = 0; ni < 2; ni++) {
                const uint32_t off = (uint32_t)((n_base + ni*16 + b_nofs + b_rr) * TSTRIDE + ks*16 + b_kofs) * 2;
                LDMX4(bh[2*ni][0], bh[2*ni][1], bh[2*ni+1][0], bh[2*ni+1][1], sb + 2*TILE_B + off);
                LDMX4(bl[2*ni][0], bl[2*ni][1], bl[2*ni+1][0], bl[2*ni+1][1], sb + 3*TILE_B + off);
            }
            #pragma unroll
            for (int mi = 0; mi < 4; mi++)
                #pragma unroll
                for (int nj = 0; nj < 4; nj++) {
                    MMA16816(acc[mi][nj], ah[mi], bh[nj]);
                    MMA16816(acc[mi][nj], ah[mi], bl[nj]);
                    MMA16816(acc[mi][nj], al[mi], bh[nj]);
                }
        }
        if (ch + 1 < 16) CP_WAIT0();
        __syncthreads();
    }

    __nv_bfloat16* Ch = z ? g_v_hi : g_q_hi;
    __nv_bfloat16* Cl = z ? g_v_lo : g_q_lo;
    const float* bias = z ? bv : bq;
    #pragma unroll
    for (int mi = 0; mi < 4; mi++) {
        const int row0 = m0 + m_base + mi*16 + (lane >> 2);
        #pragma unroll
        for (int nj = 0; nj < 4; nj++) {
            const int col = n0 + n_base + nj*8 + (lane & 3) * 2;
            const float b0 = bias[col], b1 = bias[col + 1];
            float2 v0 = { acc[mi][nj][0] + b0, acc[mi][nj][1] + b1 };
            float2 v1 = { acc[mi][nj][2] + b0, acc[mi][nj][3] + b1 };
            __nv_bfloat16 h0 = __float2bfloat16(v0.x), h1 = __float2bfloat16(v0.y);
            __nv_bfloat16 h2 = __float2bfloat16(v1.x), h3 = __float2bfloat16(v1.y);
            *(__nv_bfloat162*)(&Ch[(size_t)row0 * DD + col]) = __nv_bfloat162(h0, h1);
            *(__nv_bfloat162*)(&Ch[(size_t)(row0 + 8) * DD + col]) = __nv_bfloat162(h2, h3);
            *(__nv_bfloat162*)(&Cl[(size_t)row0 * DD + col]) = __nv_bfloat162(
                __float2bfloat16(v0.x - __bfloat162float(h0)),
                __float2bfloat16(v0.y - __bfloat162float(h1)));
            *(__nv_bfloat162*)(&Cl[(size_t)(row0 + 8) * DD + col]) = __nv_bfloat162(
                __float2bfloat16(v1.x - __bfloat162float(h2)),
                __float2bfloat16(v1.y - __bfloat162float(h3)));
        }
    }
}

// ---------------- 3a) route via HMMA split-K: scores = q @ state0^T ---------
#define RT_QH 0
#define RT_QL (RT_QH + TILE_B)
#define RT_SH (RT_QL + TILE_B)
#define RT_SL (RT_SH + 32*TSTRIDE*2)
#define RT_SMEM (RT_SL + 32*TSTRIDE*2)
__global__ void __launch_bounds__(256) route_tc_kernel() {
    extern __shared__ char smr[];
    const uint32_t smb = smem_u32(smr);
    const int kt = blockIdx.x, c = blockIdx.y, b = blockIdx.z;
    const int tid = threadIdx.x;
    const int wid = tid >> 5, lane = tid & 31;
    const int m_base = (wid >> 2) * 64;
    const int nq_base = (wid & 3) * 8;

    float accQ[4][4];
    #pragma unroll
    for (int mi = 0; mi < 4; mi++)
        #pragma unroll
        for (int r = 0; r < 4; r++) accQ[mi][r] = 0.f;

    const int a_rr = lane & 15;
    const int a_kk = (lane >> 4) * 8;
    const int m_rr = lane & 7;
    const int m_kofs = ((lane >> 3) & 1) * 8;

    for (int ch = 0; ch < 4; ch++) {
        const int k0 = (kt * 4 + ch) * 64;
        #pragma unroll
        for (int l = 0; l < 4; l++) {
            const int idx = tid + l * 256;
            const int r = idx >> 3, c8 = (idx & 7) * 8;
            const uint32_t so = (uint32_t)(r * TSTRIDE + c8) * 2;
            const size_t gq = (size_t)(b*TT + c*CN + r)*DD + k0 + c8;
            *(uint4*)(smr + RT_QH + so) = *(const uint4*)(&g_q_hi[gq]);
            *(uint4*)(smr + RT_QL + so) = *(const uint4*)(&g_q_lo[gq]);
        }
        {
            const int r = tid >> 3, c8 = (tid & 7) * 8;
            const uint32_t so = (uint32_t)(r * TSTRIDE + c8) * 2;
            const size_t gs = (size_t)(b*SS + r)*DD + k0 + c8;
            *(uint4*)(smr + RT_SH + so) = *(const uint4*)(&g_s0_hi[gs]);
            *(uint4*)(smr + RT_SL + so) = *(const uint4*)(&g_s0_lo[gs]);
        }
        __syncthreads();
        #pragma unroll
        for (int ks = 0; ks < 4; ks++) {
            uint32_t ah[4][4], al[4][4];
            #pragma unroll
            for (int mi = 0; mi < 4; mi++) {
                const uint32_t off = (uint32_t)((m_base + mi*16 + a_rr) * TSTRIDE + ks*16 + a_kk) * 2;
                LDMX4(ah[mi][0], ah[mi][1], ah[mi][2], ah[mi][3], smb + RT_QH + off);
                LDMX4(al[mi][0], al[mi][1], al[mi][2], al[mi][3], smb + RT_QL + off);
            }
            uint32_t mh2[2], ml2[2];
            {
                const uint32_t off = (uint32_t)((nq_base + m_rr) * TSTRIDE + ks*16 + m_kofs) * 2;
                LDMX2(mh2[0], mh2[1], smb + RT_SH + off);
                LDMX2(ml2[0], ml2[1], smb + RT_SL + off);
            }
            #pragma unroll
            for (int mi = 0; mi < 4; mi++) {
                MMA16816(accQ[mi], ah[mi], mh2);
                MMA16816(accQ[mi], ah[mi], ml2);
                MMA16816(accQ[mi], al[mi], mh2);
            }
        }
        __syncthreads();
    }

    const int r0 = lane >> 2, c0 = (lane & 3) * 2;
    const size_t pb = ((size_t)kt*BB*NCH + (size_t)(b*NCH + c))*CN;
    #pragma unroll
    for (int mi = 0; mi < 4; mi++) {
        #pragma unroll
        for (int half = 0; half < 2; half++) {
            const int t = m_base + mi*16 + r0 + half*8;
            const int s0 = nq_base + c0;
            *(float2*)(&g_wsp[(pb + t)*SS + s0]) =
                make_float2(accQ[mi][half*2 + 0], accQ[mi][half*2 + 1]);
        }
    }
}

// ---------------- 3b) reduce + softmax -> w; emit wdT bf16 hi/lo ------------
__global__ void __launch_bounds__(128) route_red_kernel() {
    const int c = blockIdx.x, b = blockIdx.y;
    const int t = threadIdx.x;
    const size_t bc = (size_t)(b*NCH + c);
    float sc[SS];
    #pragma unroll
    for (int s = 0; s < SS; s++) {
        float sum = 0.f;
        #pragma unroll
        for (int kt = 0; kt < 4; kt++)
            sum += g_wsp[((size_t)kt*BB*NCH + bc)*CN*SS + t*SS + s];
        sc[s] = sum * RSCALE;
    }
    float mx = -1e30f;
    #pragma unroll
    for (int s = 0; s < SS; s++) mx = fmaxf(mx, sc[s]);
    float sum = 0.f;
    #pragma unroll
    for (int s = 0; s < SS; s++) { sc[s] = expf(sc[s] - mx); sum += sc[s]; }
    const float inv = 1.f / sum;
    const int ob = (b*TT + c*CN + t)*SS;
    const float pw = ALPHA * powf(AVAL, (float)(127 - t));
    #pragma unroll
    for (int s = 0; s < SS; s++) {
        const float w = sc[s] * inv;
        g_w[ob + s] = w;
        const float wd = pw * w;
        split_store(g_wdT_hi, g_wdT_lo, (bc*SS + s)*CN + t, wd);
    }
}

// ---------------- 4) U = wdT @ v via HMMA -----------------------------------
#define UVSTR 136
#define U_WH 0
#define U_WL (U_WH + 32*UVSTR*2)
#define U_VH (U_WL + 32*UVSTR*2)
#define U_VL (U_VH + 128*UVSTR*2)
#define U_SMEM (U_VL + 128*UVSTR*2)
__global__ void __launch_bounds__(256) u_tc_kernel() {
    extern __shared__ char smu[];
    const uint32_t smb = smem_u32(smu);
    const int dt = blockIdx.x, c = blockIdx.y, b = blockIdx.z;
    const int tid = threadIdx.x;
    const int wid = tid >> 5, lane = tid & 31;
    const int m_base = (wid >> 2) * 16;      // s tile (0 or 16)
    const int n_base = (wid & 3) * 32;       // d tile within 128
    const size_t bc = (size_t)(b*NCH + c);

    // stage wdT (32 x 128, stride UVSTR)
    #pragma unroll
    for (int l = 0; l < 2; l++) {
        const int idx = tid + l * 256;
        const int r = idx >> 4, c8 = (idx & 15) * 8;
        const uint32_t so = (uint32_t)(r * UVSTR + c8) * 2;
        const size_t gw = (bc*SS + r)*CN + c8;
        *(uint4*)(smu + U_WH + so) = *(const uint4*)(&g_wdT_hi[gw]);
        *(uint4*)(smu + U_WL + so) = *(const uint4*)(&g_wdT_lo[gw]);
    }
    // stage v slice (128 x 128, stride UVSTR)
    #pragma unroll
    for (int l = 0; l < 8; l++) {
        const int idx = tid + l * 256;
        const int r = idx >> 4, c8 = (idx & 15) * 8;
        const uint32_t so = (uint32_t)(r * UVSTR + c8) * 2;
        const size_t gv = (size_t)(b*TT + c*CN + r)*DD + dt*128 + c8;
        *(uint4*)(smu + U_VH + so) = *(const uint4*)(&g_v_hi[gv]);
        *(uint4*)(smu + U_VL + so) = *(const uint4*)(&g_v_lo[gv]);
    }
    __syncthreads();

    float acc[4][4];
    #pragma unroll
    for (int nj = 0; nj < 4; nj++)
        #pragma unroll
        for (int r = 0; r < 4; r++) acc[nj][r] = 0.f;

    const int a_rr = lane & 15;
    const int a_kk = (lane >> 4) * 8;
    const int tb_g  = lane >> 3;
    const int tb_rr = lane & 7;
    const int t_koff = (tb_g & 1) * 8;
    const int t_noff = (tb_g >> 1) * 8;

    #pragma unroll
    for (int ks = 0; ks < 8; ks++) {
        uint32_t ah[4], al[4];
        {
            const uint32_t off = (uint32_t)((m_base + a_rr) * UVSTR + ks*16 + a_kk) * 2;
            LDMX4(ah[0], ah[1], ah[2], ah[3], smb + U_WH + off);
            LDMX4(al[0], al[1], al[2], al[3], smb + U_WL + off);
        }
        uint32_t bh[4][2], bl[4][2];
        #pragma unroll
        for (int ni = 0; ni < 2; ni++) {
            const uint32_t off = (uint32_t)((ks*16 + t_koff + tb_rr) * UVSTR + n_base + ni*16 + t_noff) * 2;
            LDMX4T(bh[2*ni][0], bh[2*ni][1], bh[2*ni+1][0], bh[2*ni+1][1], smb + U_VH + off);
            LDMX4T(bl[2*ni][0], bl[2*ni][1], bl[2*ni+1][0], bl[2*ni+1][1], smb + U_VL + off);
        }
        #pragma unroll
        for (int nj = 0; nj < 4; nj++) {
            MMA16816(acc[nj], ah, bh[nj]);
            MMA16816(acc[nj], ah, bl[nj]);
            MMA16816(acc[nj], al, bh[nj]);
        }
    }

    const int r0 = lane >> 2, c0 = (lane & 3) * 2;
    #pragma unroll
    for (int half = 0; half < 2; half++) {
        const int s = m_base + r0 + half*8;
        #pragma unroll
        for (int nj = 0; nj < 4; nj++) {
            const int col = dt*128 + n_base + nj*8 + c0;
            *(float2*)(&g_U[(bc*SS + s)*DD + col]) =
                make_float2(acc[nj][half*2 + 0], acc[nj][half*2 + 1]);
        }
    }
}

// ---------------- 5) sequential chunk scan (emits Ms bf16 hi/lo) ------------
__global__ void __launch_bounds__(256) scan_kernel(const float* __restrict__ state0,
                                                   float* __restrict__ outF) {
    const int idx = blockIdx.x * 256 + threadIdx.x;
    const int b = idx / (SS*DD);
    const int sd = idx - b*SS*DD;
    float m = state0[idx];
    const float dc = powf(AVAL, (float)CN);
    #pragma unroll
    for (int c = 0; c < NCH; c++) {
        const int o = (b*NCH + c)*SS*DD + sd;
        __nv_bfloat16 hi = __float2bfloat16(m);
        g_Ms_hi[o] = hi;
        g_Ms_lo[o] = __float2bfloat16(m - __bfloat162float(hi));
        m = dc * m + g_U[o];
    }
    outF[idx] = m;
}

// ---------------- 6) R1 via HMMA split-K: P = q@v^T, QM = q@Ms^T ------------
#define R1_QH 0
#define R1_QL (R1_QH + TILE_B)
#define R1_VH (R1_QL + TILE_B)
#define R1_VL (R1_VH + TILE_B)
#define R1_MH (R1_VL + TILE_B)
#define R1_ML (R1_MH + 32*TSTRIDE*2)
#define R1_SMEM (R1_ML + 32*TSTRIDE*2)
__global__ void __launch_bounds__(256) r1_tc_kernel() {
    extern __shared__ char sm1c[];
    const uint32_t smb = smem_u32(sm1c);
    const int kt = blockIdx.x, c = blockIdx.y, b = blockIdx.z;
    const int tid = threadIdx.x;
    const int wid = tid >> 5, lane = tid & 31;
    const int m_base = (wid >> 2) * 64;
    const int n_base = (wid & 3) * 32;
    const int nq_base = (wid & 3) * 8;

    float accP[4][4][4];
    float accQ[4][4];
    #pragma unroll
    for (int mi = 0; mi < 4; mi++) {
        #pragma unroll
        for (int r = 0; r < 4; r++) accQ[mi][r] = 0.f;
        #pragma unroll
        for (int nj = 0; nj < 4; nj++)
            #pragma unroll
            for (int r = 0; r < 4; r++) accP[mi][nj][r] = 0.f;
    }

    const int a_rr = lane & 15;
    const int a_kk = (lane >> 4) * 8;
    const int b_g  = lane >> 3;
    const int b_rr = lane & 7;
    const int b_nofs = (b_g >> 1) * 8;
    const int b_kofs = (b_g & 1) * 8;
    const int m_rr = lane & 7;
    const int m_kofs = ((lane >> 3) & 1) * 8;

    for (int ch = 0; ch < 4; ch++) {
        const int k0 = (kt * 4 + ch) * 64;
        #pragma unroll
        for (int l = 0; l < 4; l++) {
            const int idx = tid + l * 256;
            const int r = idx >> 3, c8 = (idx & 7) * 8;
            const uint32_t so = (uint32_t)(r * TSTRIDE + c8) * 2;
            const size_t gq = (size_t)(b*TT + c*CN + r)*DD + k0 + c8;
            *(uint4*)(sm1c + R1_QH + so) = *(const uint4*)(&g_q_hi[gq]);
            *(uint4*)(sm1c + R1_QL + so) = *(const uint4*)(&g_q_lo[gq]);
            *(uint4*)(sm1c + R1_VH + so) = *(const uint4*)(&g_v_hi[gq]);
            *(uint4*)(sm1c + R1_VL + so) = *(const uint4*)(&g_v_lo[gq]);
        }
        {
            const int r = tid >> 3, c8 = (tid & 7) * 8;
            const uint32_t so = (uint32_t)(r * TSTRIDE + c8) * 2;
            const size_t gm = (size_t)((b*NCH + c)*SS + r)*DD + k0 + c8;
            *(uint4*)(sm1c + R1_MH + so) = *(const uint4*)(&g_Ms_hi[gm]);
            *(uint4*)(sm1c + R1_ML + so) = *(const uint4*)(&g_Ms_lo[gm]);
        }
        __syncthreads();
        #pragma unroll
        for (int ks = 0; ks < 4; ks++) {
            uint32_t ah[4][4], al[4][4];
            #pragma unroll
            for (int mi = 0; mi < 4; mi++) {
                const uint32_t off = (uint32_t)((m_base + mi*16 + a_rr) * TSTRIDE + ks*16 + a_kk) * 2;
                LDMX4(ah[mi][0], ah[mi][1], ah[mi][2], ah[mi][3], smb + R1_QH + off);
                LDMX4(al[mi][0], al[mi][1], al[mi][2], al[mi][3], smb + R1_QL + off);
            }
            uint32_t bh[4][2], bl[4][2];
            #pragma unroll
            for (int ni = 0; ni < 2; ni++) {
                const uint32_t off = (uint32_t)((n_base + ni*16 + b_nofs + b_rr) * TSTRIDE + ks*16 + b_kofs) * 2;
                LDMX4(bh[2*ni][0], bh[2*ni][1], bh[2*ni+1][0], bh[2*ni+1][1], smb + R1_VH + off);
                LDMX4(bl[2*ni][0], bl[2*ni][1], bl[2*ni+1][0], bl[2*ni+1][1], smb + R1_VL + off);
            }
            uint32_t mh2[2], ml2[2];
            {
                const uint32_t off = (uint32_t)((nq_base + m_rr) * TSTRIDE + ks*16 + m_kofs) * 2;
                LDMX2(mh2[0], mh2[1], smb + R1_MH + off);
                LDMX2(ml2[0], ml2[1], smb + R1_ML + off);
            }
            #pragma unroll
            for (int mi = 0; mi < 4; mi++) {
                #pragma unroll
                for (int nj = 0; nj < 4; nj++) {
                    MMA16816(accP[mi][nj], ah[mi], bh[nj]);
                    MMA16816(accP[mi][nj], ah[mi], bl[nj]);
                    MMA16816(accP[mi][nj], al[mi], bh[nj]);
                }
                MMA16816(accQ[mi], ah[mi], mh2);
                MMA16816(accQ[mi], ah[mi], ml2);
                MMA16816(accQ[mi], al[mi], mh2);
            }
        }
        __syncthreads();
    }

    const int r0 = lane >> 2, c0 = (lane & 3) * 2;
    const size_t pb = ((size_t)kt*BB*NCH + (size_t)(b*NCH + c))*CN;
    #pragma unroll
    for (int mi = 0; mi < 4; mi++) {
        #pragma unroll
        for (int half = 0; half < 2; half++) {
            const int t = m_base + mi*16 + r0 + half*8;
            #pragma unroll
            for (int nj = 0; nj < 4; nj++) {
                const int tau0 = n_base + nj*8 + c0;
                *(float2*)(&g_Pp[(pb + t)*CN + tau0]) =
                    make_float2(accP[mi][nj][half*2 + 0], accP[mi][nj][half*2 + 1]);
            }
            const int s0 = nq_base + c0;
            *(float2*)(&g_QMp[(pb + t)*SS + s0]) =
                make_float2(accQ[mi][half*2 + 0], accQ[mi][half*2 + 1]);
        }
    }
}

// ---------------- 6b) reduce split-K partials, apply decay/mask/scale -------
__global__ void __launch_bounds__(128) reduce_p_kernel() {
    const int t = blockIdx.x, c = blockIdx.y, b = blockIdx.z;
    const int tau = threadIdx.x;
    const size_t base = ((size_t)(b*NCH + c)*CN + t);
    float sum = 0.f;
    #pragma unroll
    for (int kt = 0; kt < 4; kt++)
        sum += g_Pp[((size_t)kt*BB*NCH*CN + base)*CN + tau];
    const float out = (tau <= t) ? ALPHA * powf(AVAL, (float)(t - tau)) * sum : 0.f;
    g_P[base*CN + tau] = out;
    if (tau < SS) {
        float s2 = 0.f;
        #pragma unroll
        for (int kt = 0; kt < 4; kt++)
            s2 += g_QMp[((size_t)kt*BB*NCH*CN + base)*SS + tau];
        g_QM[base*SS + tau] = RSCALE * powf(AVAL, (float)(t + 1)) * s2;
    }
}

// ---------------- 7) R2: scores, softmax, G (emits bf16 hi/lo) ---------------
#define R2_SMEM ((128*129 + 128*33*2 + 132)*4)
__global__ void __launch_bounds__(256) r2_kernel() {
    extern __shared__ float sm2[];
    float* sP  = sm2;
    float* sW  = sP + 128*129;
    float* sA  = sW + 128*33;
    float* sPw = sA + 128*33;
    const int c = blockIdx.x, b = blockIdx.y;
    const int tid = threadIdx.x;
    if (tid < 132) sPw[tid] = powf(AVAL, (float)tid);
    __syncthreads();
    const int pbase = ((b*NCH + c)*CN)*CN;
    for (int e = tid; e < CN*CN; e += 256) {
        sP[(e >> 7)*129 + (e & 127)] = g_P[pbase + e];
    }
    const int qbase = ((b*NCH + c)*CN)*SS;
    for (int e = tid; e < CN*SS; e += 256) {
        sA[(e >> 5)*33 + (e & 31)] = g_QM[qbase + e];
    }
    for (int e = tid; e < CN*SS; e += 256) {
        const int t = e >> 5, s = e & 31;
        sW[t*33 + s] = g_w[(b*TT + c*CN + t)*SS + s];
    }
    __syncthreads();
    {
        const int t  = tid >> 1;
        const int s0 = (tid & 1) * 16;
        float r[16];
        #pragma unroll
        for (int sj = 0; sj < 16; sj++) r[sj] = 0.f;
        for (int tau = 0; tau <= t; tau++) {
            const float p = sP[t*129 + tau];
            #pragma unroll
            for (int sj = 0; sj < 16; sj++) r[sj] += p * sW[tau*33 + s0 + sj];
        }
        __syncthreads();
        #pragma unroll
        for (int sj = 0; sj < 16; sj++) sA[t*33 + s0 + sj] += RSCALE * r[sj];
    }
    __syncthreads();
    if (tid < 128) {
        const int t = tid;
        float mx = -1e30f;
        #pragma unroll
        for (int s = 0; s < SS; s++) mx = fmaxf(mx, sA[t*33 + s]);
        float ev[SS]; float sum = 0.f;
        #pragma unroll
        for (int s = 0; s < SS; s++) { ev[s] = expf(sA[t*33 + s] - mx); sum += ev[s]; }
        const float inv = 1.f / sum;
        const float pw = sPw[t + 1];
        const int ab = ((b*NCH + c)*CN + t)*SS;
        #pragma unroll
        for (int s = 0; s < SS; s++) {
            const float a = ev[s] * inv;
            sA[t*33 + s] = a;
            const float av = pw * a;
            __nv_bfloat16 hi = __float2bfloat16(av);
            g_at_hi[ab + s] = hi;
            g_at_lo[ab + s] = __float2bfloat16(av - __bfloat162float(hi));
        }
    }
    __syncthreads();
    const int ty = tid >> 4, tx = tid & 15;
    const int gbase = ((b*NCH + c)*CN)*CN;
    #pragma unroll
    for (int i = 0; i < 8; i++) {
        const int t = ty*8 + i;
        #pragma unroll
        for (int j = 0; j < 8; j++) {
            const int tau = tx*8 + j;
            float g = 0.f;
            if (tau <= t) {
                #pragma unroll
                for (int s = 0; s < SS; s++) g += sA[t*33 + s] * sW[tau*33 + s];
                g *= ALPHA * sPw[t - tau];
            }
            __nv_bfloat16 hi = __float2bfloat16(g);
            g_G_hi[gbase + t*CN + tau] = hi;
            g_G_lo[gbase + t*CN + tau] = __float2bfloat16(g - __bfloat162float(hi));
        }
    }
}

// ---------------- 8) R3 via HMMA: ctx = G@v + at@Ms --------------------------
#define VSTR 136
#define ATSTR 40
#define R3_TILE (128*VSTR*2)
#define R3_GH 0
#define R3_GL (R3_GH + R3_TILE)
#define R3_VH (R3_GL + R3_TILE)
#define R3_VL (R3_VH + R3_TILE)
#define R3_AH (R3_VL + R3_TILE)
#define R3_AL (R3_AH + 128*ATSTR*2)
#define R3_MH (R3_AL + 128*ATSTR*2)
#define R3_ML (R3_MH + 32*VSTR*2)
#define R3_SMEM (R3_ML + 32*VSTR*2)
__global__ void __launch_bounds__(256) r3_tc_kernel(float* __restrict__ outC) {
    extern __shared__ char sm3c[];
    const uint32_t smb = smem_u32(sm3c);
    const int dt = blockIdx.x, c = blockIdx.y, b = blockIdx.z;
    const int tid = threadIdx.x;
    const int wid = tid >> 5, lane = tid & 31;
    const int m_base = (wid >> 2) * 64;
    const int n_base = (wid & 3) * 32;

    #pragma unroll
    for (int l = 0; l < 8; l++) {
        const int idx = tid + l * 256;
        const int r = idx >> 4, c8 = (idx & 15) * 8;
        const uint32_t so = (uint32_t)(r * VSTR + c8) * 2;
        const size_t gg = ((size_t)(b*NCH + c)*CN + r)*CN + c8;
        *(uint4*)(sm3c + R3_GH + so) = *(const uint4*)(&g_G_hi[gg]);
        *(uint4*)(sm3c + R3_GL + so) = *(const uint4*)(&g_G_lo[gg]);
        const size_t gv = (size_t)(b*TT + c*CN + r)*DD + dt*128 + c8;
        *(uint4*)(sm3c + R3_VH + so) = *(const uint4*)(&g_v_hi[gv]);
        *(uint4*)(sm3c + R3_VL + so) = *(const uint4*)(&g_v_lo[gv]);
    }
    #pragma unroll
    for (int l = 0; l < 2; l++) {
        const int idx = tid + l * 256;
        {
            const int r = idx >> 2, s8 = (idx & 3) * 8;
            const uint32_t so = (uint32_t)(r * ATSTR + s8) * 2;
            const size_t ga = ((size_t)(b*NCH + c)*CN + r)*SS + s8;
            *(uint4*)(sm3c + R3_AH + so) = *(const uint4*)(&g_at_hi[ga]);
            *(uint4*)(sm3c + R3_AL + so) = *(const uint4*)(&g_at_lo[ga]);
        }
        {
            const int r = idx >> 4, c8 = (idx & 15) * 8;
            const uint32_t so = (uint32_t)(r * VSTR + c8) * 2;
            const size_t gm = ((size_t)(b*NCH + c)*SS + r)*DD + dt*128 + c8;
            *(uint4*)(sm3c + R3_MH + so) = *(const uint4*)(&g_Ms_hi[gm]);
            *(uint4*)(sm3c + R3_ML + so) = *(const uint4*)(&g_Ms_lo[gm]);
        }
    }
    __syncthreads();

    float acc[4][4][4];
    #pragma unroll
    for (int mi = 0; mi < 4; mi++)
        #pragma unroll
        for (int nj = 0; nj < 4; nj++)
            #pragma unroll
            for (int r = 0; r < 4; r++) acc[mi][nj][r] = 0.f;

    const int a_rr = lane & 15;
    const int a_kk = (lane >> 4) * 8;
    const int tb_g  = lane >> 3;
    const int tb_rr = lane & 7;
    const int t_koff = (tb_g & 1) * 8;
    const int t_noff = (tb_g >> 1) * 8;

    #pragma unroll
    for (int ks = 0; ks < 8; ks++) {
        uint32_t ah[4][4], al[4][4];
        #pragma unroll
        for (int mi = 0; mi < 4; mi++) {
            const uint32_t off = (uint32_t)((m_base + mi*16 + a_rr) * VSTR + ks*16 + a_kk) * 2;
            LDMX4(ah[mi][0], ah[mi][1], ah[mi][2], ah[mi][3], smb + R3_GH + off);
            LDMX4(al[mi][0], al[mi][1], al[mi][2], al[mi][3], smb + R3_GL + off);
        }
        uint32_t bh[4][2], bl[4][2];
        #pragma unroll
        for (int ni = 0; ni < 2; ni++) {
            const uint32_t off = (uint32_t)((ks*16 + t_koff + tb_rr) * VSTR + n_base + ni*16 + t_noff) * 2;
            LDMX4T(bh[2*ni][0], bh[2*ni][1], bh[2*ni+1][0], bh[2*ni+1][1], smb + R3_VH + off);
            LDMX4T(bl[2*ni][0], bl[2*ni][1], bl[2*ni+1][0], bl[2*ni+1][1], smb + R3_VL + off);
        }
        #pragma unroll
        for (int mi = 0; mi < 4; mi++)
            #pragma unroll
            for (int nj = 0; nj < 4; nj++) {
                MMA16816(acc[mi][nj], ah[mi], bh[nj]);
                MMA16816(acc[mi][nj], ah[mi], bl[nj]);
                MMA16816(acc[mi][nj], al[mi], bh[nj]);
            }
    }
    #pragma unroll
    for (int ks = 0; ks < 2; ks++) {
        uint32_t ah[4][4], al[4][4];
        #pragma unroll
        for (int mi = 0; mi < 4; mi++) {
            const uint32_t off = (uint32_t)((m_base + mi*16 + a_rr) * ATSTR + ks*16 + a_kk) * 2;
            LDMX4(ah[mi][0], ah[mi][1], ah[mi][2], ah[mi][3], smb + R3_AH + off);
            LDMX4(al[mi][0], al[mi][1], al[mi][2], al[mi][3], smb + R3_AL + off);
        }
        uint32_t bh[4][2], bl[4][2];
        #pragma unroll
        for (int ni = 0; ni < 2; ni++) {
            const uint32_t off = (uint32_t)((ks*16 + t_koff + tb_rr) * VSTR + n_base + ni*16 + t_noff) * 2;
            LDMX4T(bh[2*ni][0], bh[2*ni][1], bh[2*ni+1][0], bh[2*ni+1][1], smb + R3_MH + off);
            LDMX4T(bl[2*ni][0], bl[2*ni][1], bl[2*ni+1][0], bl[2*ni+1][1], smb + R3_ML + off);
        }
        #pragma unroll
        for (int mi = 0; mi < 4; mi++)
            #pragma unroll
            for (int nj = 0; nj < 4; nj++) {
                MMA16816(acc[mi][nj], ah[mi], bh[nj]);
                MMA16816(acc[mi][nj], ah[mi], bl[nj]);
                MMA16816(acc[mi][nj], al[mi], bh[nj]);
            }
    }

    #pragma unroll
    for (int mi = 0; mi < 4; mi++) {
        const int row0 = b*TT + c*CN + m_base + mi*16 + (lane >> 2);
        #pragma unroll
        for (int nj = 0; nj < 4; nj++) {
            const int col = dt*128 + n_base + nj*8 + (lane & 3) * 2;
            *(float2*)(&outC[(size_t)row0 * DD + col]) = make_float2(acc[mi][nj][0], acc[mi][nj][1]);
            *(float2*)(&outC[(size_t)(row0 + 8) * DD + col]) = make_float2(acc[mi][nj][2], acc[mi][nj][3]);
        }
    }
}

extern "C" void kernel_launch(void* const* d_in, const int* in_sizes, int n_in,
                              void* d_out, int out_size) {
    (void)in_sizes; (void)n_in; (void)out_size;
    const float* h      = (const float*)d_in[0];
    const float* state0 = (const float*)d_in[1];
    const float* gamma  = (const float*)d_in[2];
    const float* beta   = (const float*)d_in[3];
    const float* Wq     = (const float*)d_in[4];
    const float* bq     = (const float*)d_in[5];
    const float* Wv     = (const float*)d_in[6];
    const float* bv     = (const float*)d_in[7];
    float* out = (float*)d_out;
    float* outCtx   = out;
    float* outFinal = out + (size_t)BB*TT*DD;

    cudaFuncSetAttribute(gemm_tc_kernel, cudaFuncAttributeMaxDynamicSharedMemorySize, GEMM_SMEM);
    cudaFuncSetAttribute(route_tc_kernel, cudaFuncAttributeMaxDynamicSharedMemorySize, RT_SMEM);
    cudaFuncSetAttribute(u_tc_kernel, cudaFuncAttributeMaxDynamicSharedMemorySize, U_SMEM);
    cudaFuncSetAttribute(r1_tc_kernel, cudaFuncAttributeMaxDynamicSharedMemorySize, R1_SMEM);
    cudaFuncSetAttribute(r2_kernel, cudaFuncAttributeMaxDynamicSharedMemorySize, R2_SMEM);
    cudaFuncSetAttribute(r3_tc_kernel, cudaFuncAttributeMaxDynamicSharedMemorySize, R3_SMEM);

    ln_kernel<<<BB*TT, 256>>>(h, gamma, beta);
    convw_kernel<<<2*DD*DD/1024, 256>>>(Wq, Wv);
    convs_kernel<<<BB*SS*DD/1024, 256>>>(state0);
    gemm_tc_kernel<<<dim3(DD/128, BB*TT/128, 2), 256, GEMM_SMEM>>>(bq, bv);
    route_tc_kernel<<<dim3(4, NCH, BB), 256, RT_SMEM>>>();
    route_red_kernel<<<dim3(NCH, BB), 128>>>();
    u_tc_kernel<<<dim3(DD/128, NCH, BB), 256, U_SMEM>>>();
    scan_kernel<<<BB*SS*DD/256, 256>>>(state0, outFinal);
    r1_tc_kernel<<<dim3(4, NCH, BB), 256, R1_SMEM>>>();
    reduce_p_kernel<<<dim3(CN, NCH, BB), 128>>>();
    r2_kernel<<<dim3(NCH, BB), 256, R2_SMEM>>>();
    r3_tc_kernel<<<dim3(DD/128, NCH, BB), 256, R3_SMEM>>>(outCtx);
}

// round 13
// speedup vs baseline: 1.5637x; 1.0018x over previous
#include <cuda_runtime.h>
#include <cuda_bf16.h>
#include <math.h>
#include <stdint.h>

#define BB 2
#define TT 2048
#define DD 1024
#define SS 32
#define CN 128
#define NCH 16
#define ALPHA 0.05f
#define AVAL 0.95f
#define RSCALE 0.03125f
#define LNEPS 1e-5f

// scratch (device globals; 16B-aligned for vectorized access)
__device__ __align__(16) __nv_bfloat16 g_hn_hi[BB*TT*DD];
__device__ __align__(16) __nv_bfloat16 g_hn_lo[BB*TT*DD];
__device__ __align__(16) __nv_bfloat16 g_W_hi [2*DD*DD];
__device__ __align__(16) __nv_bfloat16 g_W_lo [2*DD*DD];
__device__ __align__(16) __nv_bfloat16 g_q_hi[BB*TT*DD];
__device__ __align__(16) __nv_bfloat16 g_q_lo[BB*TT*DD];
__device__ __align__(16) __nv_bfloat16 g_v_hi[BB*TT*DD];
__device__ __align__(16) __nv_bfloat16 g_v_lo[BB*TT*DD];
__device__ __align__(16) __nv_bfloat16 g_s0_hi[BB*SS*DD];
__device__ __align__(16) __nv_bfloat16 g_s0_lo[BB*SS*DD];
__device__ __align__(16) float g_w  [BB*TT*SS];
__device__ __align__(16) float g_wsp[4*BB*NCH*CN*SS];
__device__ __align__(16) __nv_bfloat16 g_wdT_hi[BB*NCH*SS*CN];
__device__ __align__(16) __nv_bfloat16 g_wdT_lo[BB*NCH*SS*CN];
__device__ __align__(16) float g_U  [BB*NCH*SS*DD];
__device__ __align__(16) __nv_bfloat16 g_Ms_hi[BB*NCH*SS*DD];
__device__ __align__(16) __nv_bfloat16 g_Ms_lo[BB*NCH*SS*DD];
__device__ __align__(16) float g_Pp [4*BB*NCH*CN*CN];
__device__ __align__(16) float g_QMp[4*BB*NCH*CN*SS];
__device__ __align__(16) float g_P  [BB*NCH*CN*CN];
__device__ __align__(16) float g_QM [BB*NCH*CN*SS];
__device__ __align__(16) __nv_bfloat16 g_G_hi [BB*NCH*CN*CN];
__device__ __align__(16) __nv_bfloat16 g_G_lo [BB*NCH*CN*CN];
__device__ __align__(16) __nv_bfloat16 g_at_hi[BB*NCH*CN*SS];
__device__ __align__(16) __nv_bfloat16 g_at_lo[BB*NCH*CN*SS];

// ---------------- helpers ----------------------------------------------------
__device__ __forceinline__ uint32_t smem_u32(const void* p) {
    uint32_t a;
    asm("{ .reg .u64 t; cvta.to.shared.u64 t, %1; cvt.u32.u64 %0, t; }" : "=r"(a) : "l"(p));
    return a;
}
#define LDMX4(r0, r1, r2, r3, addr) \
    asm volatile("ldmatrix.sync.aligned.m8n8.x4.shared.b16 {%0,%1,%2,%3}, [%4];" \
        : "=r"(r0), "=r"(r1), "=r"(r2), "=r"(r3) : "r"(addr))
#define LDMX4T(r0, r1, r2, r3, addr) \
    asm volatile("ldmatrix.sync.aligned.m8n8.x4.trans.shared.b16 {%0,%1,%2,%3}, [%4];" \
        : "=r"(r0), "=r"(r1), "=r"(r2), "=r"(r3) : "r"(addr))
#define LDMX2(r0, r1, addr) \
    asm volatile("ldmatrix.sync.aligned.m8n8.x2.shared.b16 {%0,%1}, [%2];" \
        : "=r"(r0), "=r"(r1) : "r"(addr))
#define MMA16816(d, a, b) \
    asm volatile("mma.sync.aligned.m16n8k16.row.col.f32.bf16.bf16.f32 " \
        "{%0,%1,%2,%3}, {%4,%5,%6,%7}, {%8,%9}, {%0,%1,%2,%3};" \
        : "+f"((d)[0]), "+f"((d)[1]), "+f"((d)[2]), "+f"((d)[3]) \
        : "r"((a)[0]), "r"((a)[1]), "r"((a)[2]), "r"((a)[3]), "r"((b)[0]), "r"((b)[1]))
#define CP_ASYNC16(smaddr, gptr) \
    asm volatile("cp.async.cg.shared.global [%0], [%1], 16;" :: "r"(smaddr), "l"(gptr) : "memory")
#define CP_COMMIT() asm volatile("cp.async.commit_group;" ::: "memory")
#define CP_WAIT0()  asm volatile("cp.async.wait_group 0;" ::: "memory")

__device__ __forceinline__ void split_store(__nv_bfloat16* hi, __nv_bfloat16* lo,
                                            size_t idx, float v) {
    __nv_bfloat16 h = __float2bfloat16(v);
    hi[idx] = h;
    lo[idx] = __float2bfloat16(v - __bfloat162float(h));
}

// ---------------- 1) LayerNorm -> bf16 hi/lo --------------------------------
__global__ void __launch_bounds__(256) ln_kernel(const float* __restrict__ h,
                                                 const float* __restrict__ gamma,
                                                 const float* __restrict__ beta) {
    __shared__ float sx[DD];
    __shared__ float sred[256];
    const int row = blockIdx.x;
    const float* hr = h + (size_t)row * DD;
    const int tid = threadIdx.x;
    float lsum = 0.f;
    for (int i = tid; i < DD; i += 256) { float x = hr[i]; sx[i] = x; lsum += x; }
    sred[tid] = lsum; __syncthreads();
    #pragma unroll
    for (int s = 128; s > 0; s >>= 1) { if (tid < s) sred[tid] += sred[tid + s]; __syncthreads(); }
    const float mu = sred[0] * (1.0f / DD);
    __syncthreads();
    float lvar = 0.f;
    for (int i = tid; i < DD; i += 256) { float d = sx[i] - mu; lvar += d * d; }
    sred[tid] = lvar; __syncthreads();
    #pragma unroll
    for (int s = 128; s > 0; s >>= 1) { if (tid < s) sred[tid] += sred[tid + s]; __syncthreads(); }
    const float rstd = rsqrtf(sred[0] * (1.0f / DD) + LNEPS);
    __nv_bfloat16* ohi = g_hn_hi + (size_t)row * DD;
    __nv_bfloat16* olo = g_hn_lo + (size_t)row * DD;
    for (int i = tid; i < DD; i += 256) {
        float y = (sx[i] - mu) * rstd * gamma[i] + beta[i];
        __nv_bfloat16 hi = __float2bfloat16(y);
        ohi[i] = hi;
        olo[i] = __float2bfloat16(y - __bfloat162float(hi));
    }
}

// ---------------- 1b) W -> bf16 hi/lo ---------------------------------------
__global__ void __launch_bounds__(256) convw_kernel(const float* __restrict__ Wq,
                                                    const float* __restrict__ Wv) {
    const size_t base = ((size_t)blockIdx.x * 256 + threadIdx.x) * 4;
    const float* W = (base < (size_t)DD*DD) ? Wq : Wv;
    const size_t off = (base < (size_t)DD*DD) ? base : base - (size_t)DD*DD;
    float4 x = *(const float4*)(&W[off]);
    split_store(g_W_hi, g_W_lo, base + 0, x.x);
    split_store(g_W_hi, g_W_lo, base + 1, x.y);
    split_store(g_W_hi, g_W_lo, base + 2, x.z);
    split_store(g_W_hi, g_W_lo, base + 3, x.w);
}

// ---------------- 1c) state0 -> bf16 hi/lo ----------------------------------
__global__ void __launch_bounds__(256) convs_kernel(const float* __restrict__ s0) {
    const size_t base = ((size_t)blockIdx.x * 256 + threadIdx.x) * 4;
    float4 x = *(const float4*)(&s0[base]);
    split_store(g_s0_hi, g_s0_lo, base + 0, x.x);
    split_store(g_s0_hi, g_s0_lo, base + 1, x.y);
    split_store(g_s0_hi, g_s0_lo, base + 2, x.z);
    split_store(g_s0_hi, g_s0_lo, base + 3, x.w);
}

// ---------------- 2) q/v projection: mma.sync bf16, cp.async 2-stage --------
#define TSTRIDE 72
#define TILE_B (128*TSTRIDE*2)
#define GEMM_SMEM (8*TILE_B)
__global__ void __launch_bounds__(256) gemm_tc_kernel(const float* __restrict__ bq,
                                                      const float* __restrict__ bv) {
    extern __shared__ char smc[];
    const uint32_t smb = smem_u32(smc);
    const int tid = threadIdx.x;
    const int wid = tid >> 5, lane = tid & 31;
    const int n0 = blockIdx.x * 128;
    const int m0 = blockIdx.y * 128;
    const int z  = blockIdx.z;
    const __nv_bfloat16* Whi = g_W_hi + (size_t)z * DD * DD;
    const __nv_bfloat16* Wlo = g_W_lo + (size_t)z * DD * DD;
    const int m_base = (wid >> 2) * 64;
    const int n_base = (wid & 3) * 32;

    float acc[4][4][4];
    #pragma unroll
    for (int mi = 0; mi < 4; mi++)
        #pragma unroll
        for (int nj = 0; nj < 4; nj++)
            #pragma unroll
            for (int r = 0; r < 4; r++) acc[mi][nj][r] = 0.f;

    const int a_rr = lane & 15;
    const int a_kk = (lane >> 4) * 8;
    const int b_g  = lane >> 3;
    const int b_rr = lane & 7;
    const int b_nofs = (b_g >> 1) * 8;
    const int b_kofs = (b_g & 1) * 8;

    const int lr = tid >> 3, lc8 = (tid & 7) * 8;
    const uint32_t lso = (uint32_t)(lr * TSTRIDE + lc8) * 2;

    #pragma unroll
    for (int l = 0; l < 4; l++) {
        const int r = lr + l * 32;
        const size_t ga = (size_t)(m0 + r) * DD + lc8;
        const size_t gb = (size_t)(n0 + r) * DD + lc8;
        const uint32_t so = lso + (uint32_t)(l * 32 * TSTRIDE) * 2;
        CP_ASYNC16(smb + 0*TILE_B + so, &g_hn_hi[ga]);
        CP_ASYNC16(smb + 1*TILE_B + so, &g_hn_lo[ga]);
        CP_ASYNC16(smb + 2*TILE_B + so, &Whi[gb]);
        CP_ASYNC16(smb + 3*TILE_B + so, &Wlo[gb]);
    }
    CP_COMMIT(); CP_WAIT0(); __syncthreads();

    for (int ch = 0; ch < 16; ch++) {
        const int s = ch & 1;
        const uint32_t sb = smb + (uint32_t)s * 4 * TILE_B;
        if (ch + 1 < 16) {
            const uint32_t nb = smb + (uint32_t)(s ^ 1) * 4 * TILE_B;
            const int k0 = (ch + 1) * 64;
            #pragma unroll
            for (int l = 0; l < 4; l++) {
                const int r = lr + l * 32;
                const size_t ga = (size_t)(m0 + r) * DD + k0 + lc8;
                const size_t gb = (size_t)(n0 + r) * DD + k0 + lc8;
                const uint32_t so = lso + (uint32_t)(l * 32 * TSTRIDE) * 2;
                CP_ASYNC16(nb + 0*TILE_B + so, &g_hn_hi[ga]);
                CP_ASYNC16(nb + 1*TILE_B + so, &g_hn_lo[ga]);
                CP_ASYNC16(nb + 2*TILE_B + so, &Whi[gb]);
                CP_ASYNC16(nb + 3*TILE_B + so, &Wlo[gb]);
            }
            CP_COMMIT();
        }
        #pragma unroll
        for (int ks = 0; ks < 4; ks++) {
            uint32_t ah[4][4], al[4][4];
            #pragma unroll
            for (int mi = 0; mi < 4; mi++) {
                const uint32_t off = (uint32_t)((m_base + mi*16 + a_rr) * TSTRIDE + ks*16 + a_kk) * 2;
                LDMX4(ah[mi][0], ah[mi][1], ah[mi][2], ah[mi][3], sb + 0*TILE_B + off);
                LDMX4(al[mi][0], al[mi][1], al[mi][2], al[mi][3], sb + 1*TILE_B + off);
            }
            uint32_t bh[4][2], bl[4][2];
            #pragma unroll
            for (int ni = 0; ni < 2; ni++) {
                const uint32_t off = (uint32_t)((n_base + ni*16 + b_nofs + b_rr) * TSTRIDE + ks*16 + b_kofs) * 2;
                LDMX4(bh[2*ni][0], bh[2*ni][1], bh[2*ni+1][0], bh[2*ni+1][1], sb + 2*TILE_B + off);
                LDMX4(bl[2*ni][0], bl[2*ni][1], bl[2*ni+1][0], bl[2*ni+1][1], sb + 3*TILE_B + off);
            }
            #pragma unroll
            for (int mi = 0; mi < 4; mi++)
                #pragma unroll
                for (int nj = 0; nj < 4; nj++) {
                    MMA16816(acc[mi][nj], ah[mi], bh[nj]);
                    MMA16816(acc[mi][nj], ah[mi], bl[nj]);
                    MMA16816(acc[mi][nj], al[mi], bh[nj]);
                }
        }
        if (ch + 1 < 16) CP_WAIT0();
        __syncthreads();
    }

    __nv_bfloat16* Ch = z ? g_v_hi : g_q_hi;
    __nv_bfloat16* Cl = z ? g_v_lo : g_q_lo;
    const float* bias = z ? bv : bq;
    #pragma unroll
    for (int mi = 0; mi < 4; mi++) {
        const int row0 = m0 + m_base + mi*16 + (lane >> 2);
        #pragma unroll
        for (int nj = 0; nj < 4; nj++) {
            const int col = n0 + n_base + nj*8 + (lane & 3) * 2;
            const float b0 = bias[col], b1 = bias[col + 1];
            float2 v0 = { acc[mi][nj][0] + b0, acc[mi][nj][1] + b1 };
            float2 v1 = { acc[mi][nj][2] + b0, acc[mi][nj][3] + b1 };
            __nv_bfloat16 h0 = __float2bfloat16(v0.x), h1 = __float2bfloat16(v0.y);
            __nv_bfloat16 h2 = __float2bfloat16(v1.x), h3 = __float2bfloat16(v1.y);
            *(__nv_bfloat162*)(&Ch[(size_t)row0 * DD + col]) = __nv_bfloat162(h0, h1);
            *(__nv_bfloat162*)(&Ch[(size_t)(row0 + 8) * DD + col]) = __nv_bfloat162(h2, h3);
            *(__nv_bfloat162*)(&Cl[(size_t)row0 * DD + col]) = __nv_bfloat162(
                __float2bfloat16(v0.x - __bfloat162float(h0)),
                __float2bfloat16(v0.y - __bfloat162float(h1)));
            *(__nv_bfloat162*)(&Cl[(size_t)(row0 + 8) * DD + col]) = __nv_bfloat162(
                __float2bfloat16(v1.x - __bfloat162float(h2)),
                __float2bfloat16(v1.y - __bfloat162float(h3)));
        }
    }
}

// ---------------- 3a) route via HMMA split-K: scores = q @ state0^T ---------
#define RT_QH 0
#define RT_QL (RT_QH + TILE_B)
#define RT_SH (RT_QL + TILE_B)
#define RT_SL (RT_SH + 32*TSTRIDE*2)
#define RT_SMEM (RT_SL + 32*TSTRIDE*2)
__global__ void __launch_bounds__(256) route_tc_kernel() {
    extern __shared__ char smr[];
    const uint32_t smb = smem_u32(smr);
    const int kt = blockIdx.x, c = blockIdx.y, b = blockIdx.z;
    const int tid = threadIdx.x;
    const int wid = tid >> 5, lane = tid & 31;
    const int m_base = (wid >> 2) * 64;
    const int nq_base = (wid & 3) * 8;

    float accQ[4][4];
    #pragma unroll
    for (int mi = 0; mi < 4; mi++)
        #pragma unroll
        for (int r = 0; r < 4; r++) accQ[mi][r] = 0.f;

    const int a_rr = lane & 15;
    const int a_kk = (lane >> 4) * 8;
    const int m_rr = lane & 7;
    const int m_kofs = ((lane >> 3) & 1) * 8;

    for (int ch = 0; ch < 4; ch++) {
        const int k0 = (kt * 4 + ch) * 64;
        #pragma unroll
        for (int l = 0; l < 4; l++) {
            const int idx = tid + l * 256;
            const int r = idx >> 3, c8 = (idx & 7) * 8;
            const uint32_t so = (uint32_t)(r * TSTRIDE + c8) * 2;
            const size_t gq = (size_t)(b*TT + c*CN + r)*DD + k0 + c8;
            *(uint4*)(smr + RT_QH + so) = *(const uint4*)(&g_q_hi[gq]);
            *(uint4*)(smr + RT_QL + so) = *(const uint4*)(&g_q_lo[gq]);
        }
        {
            const int r = tid >> 3, c8 = (tid & 7) * 8;
            const uint32_t so = (uint32_t)(r * TSTRIDE + c8) * 2;
            const size_t gs = (size_t)(b*SS + r)*DD + k0 + c8;
            *(uint4*)(smr + RT_SH + so) = *(const uint4*)(&g_s0_hi[gs]);
            *(uint4*)(smr + RT_SL + so) = *(const uint4*)(&g_s0_lo[gs]);
        }
        __syncthreads();
        #pragma unroll
        for (int ks = 0; ks < 4; ks++) {
            uint32_t ah[4][4], al[4][4];
            #pragma unroll
            for (int mi = 0; mi < 4; mi++) {
                const uint32_t off = (uint32_t)((m_base + mi*16 + a_rr) * TSTRIDE + ks*16 + a_kk) * 2;
                LDMX4(ah[mi][0], ah[mi][1], ah[mi][2], ah[mi][3], smb + RT_QH + off);
                LDMX4(al[mi][0], al[mi][1], al[mi][2], al[mi][3], smb + RT_QL + off);
            }
            uint32_t mh2[2], ml2[2];
            {
                const uint32_t off = (uint32_t)((nq_base + m_rr) * TSTRIDE + ks*16 + m_kofs) * 2;
                LDMX2(mh2[0], mh2[1], smb + RT_SH + off);
                LDMX2(ml2[0], ml2[1], smb + RT_SL + off);
            }
            #pragma unroll
            for (int mi = 0; mi < 4; mi++) {
                MMA16816(accQ[mi], ah[mi], mh2);
                MMA16816(accQ[mi], ah[mi], ml2);
                MMA16816(accQ[mi], al[mi], mh2);
            }
        }
        __syncthreads();
    }

    const int r0 = lane >> 2, c0 = (lane & 3) * 2;
    const size_t pb = ((size_t)kt*BB*NCH + (size_t)(b*NCH + c))*CN;
    #pragma unroll
    for (int mi = 0; mi < 4; mi++) {
        #pragma unroll
        for (int half = 0; half < 2; half++) {
            const int t = m_base + mi*16 + r0 + half*8;
            const int s0 = nq_base + c0;
            *(float2*)(&g_wsp[(pb + t)*SS + s0]) =
                make_float2(accQ[mi][half*2 + 0], accQ[mi][half*2 + 1]);
        }
    }
}

// ---------------- 3b) reduce + softmax -> w; emit wdT bf16 hi/lo ------------
__global__ void __launch_bounds__(128) route_red_kernel() {
    const int c = blockIdx.x, b = blockIdx.y;
    const int t = threadIdx.x;
    const size_t bc = (size_t)(b*NCH + c);
    float sc[SS];
    #pragma unroll
    for (int s = 0; s < SS; s++) {
        float sum = 0.f;
        #pragma unroll
        for (int kt = 0; kt < 4; kt++)
            sum += g_wsp[((size_t)kt*BB*NCH + bc)*CN*SS + t*SS + s];
        sc[s] = sum * RSCALE;
    }
    float mx = -1e30f;
    #pragma unroll
    for (int s = 0; s < SS; s++) mx = fmaxf(mx, sc[s]);
    float sum = 0.f;
    #pragma unroll
    for (int s = 0; s < SS; s++) { sc[s] = expf(sc[s] - mx); sum += sc[s]; }
    const float inv = 1.f / sum;
    const int ob = (b*TT + c*CN + t)*SS;
    const float pw = ALPHA * powf(AVAL, (float)(127 - t));
    #pragma unroll
    for (int s = 0; s < SS; s++) {
        const float w = sc[s] * inv;
        g_w[ob + s] = w;
        const float wd = pw * w;
        split_store(g_wdT_hi, g_wdT_lo, (bc*SS + s)*CN + t, wd);
    }
}

// ---------------- 4) U = wdT @ v via HMMA -----------------------------------
#define UVSTR 136
#define U_WH 0
#define U_WL (U_WH + 32*UVSTR*2)
#define U_VH (U_WL + 32*UVSTR*2)
#define U_VL (U_VH + 128*UVSTR*2)
#define U_SMEM (U_VL + 128*UVSTR*2)
__global__ void __launch_bounds__(256) u_tc_kernel() {
    extern __shared__ char smu[];
    const uint32_t smb = smem_u32(smu);
    const int dt = blockIdx.x, c = blockIdx.y, b = blockIdx.z;
    const int tid = threadIdx.x;
    const int wid = tid >> 5, lane = tid & 31;
    const int m_base = (wid >> 2) * 16;      // s tile (0 or 16)
    const int n_base = (wid & 3) * 32;       // d tile within 128
    const size_t bc = (size_t)(b*NCH + c);

    // stage wdT (32 x 128, stride UVSTR)
    #pragma unroll
    for (int l = 0; l < 2; l++) {
        const int idx = tid + l * 256;
        const int r = idx >> 4, c8 = (idx & 15) * 8;
        const uint32_t so = (uint32_t)(r * UVSTR + c8) * 2;
        const size_t gw = (bc*SS + r)*CN + c8;
        *(uint4*)(smu + U_WH + so) = *(const uint4*)(&g_wdT_hi[gw]);
        *(uint4*)(smu + U_WL + so) = *(const uint4*)(&g_wdT_lo[gw]);
    }
    // stage v slice (128 x 128, stride UVSTR)
    #pragma unroll
    for (int l = 0; l < 8; l++) {
        const int idx = tid + l * 256;
        const int r = idx >> 4, c8 = (idx & 15) * 8;
        const uint32_t so = (uint32_t)(r * UVSTR + c8) * 2;
        const size_t gv = (size_t)(b*TT + c*CN + r)*DD + dt*128 + c8;
        *(uint4*)(smu + U_VH + so) = *(const uint4*)(&g_v_hi[gv]);
        *(uint4*)(smu + U_VL + so) = *(const uint4*)(&g_v_lo[gv]);
    }
    __syncthreads();

    float acc[4][4];
    #pragma unroll
    for (int nj = 0; nj < 4; nj++)
        #pragma unroll
        for (int r = 0; r < 4; r++) acc[nj][r] = 0.f;

    const int a_rr = lane & 15;
    const int a_kk = (lane >> 4) * 8;
    const int tb_g  = lane >> 3;
    const int tb_rr = lane & 7;
    const int t_koff = (tb_g & 1) * 8;
    const int t_noff = (tb_g >> 1) * 8;

    #pragma unroll
    for (int ks = 0; ks < 8; ks++) {
        uint32_t ah[4], al[4];
        {
            const uint32_t off = (uint32_t)((m_base + a_rr) * UVSTR + ks*16 + a_kk) * 2;
            LDMX4(ah[0], ah[1], ah[2], ah[3], smb + U_WH + off);
            LDMX4(al[0], al[1], al[2], al[3], smb + U_WL + off);
        }
        uint32_t bh[4][2], bl[4][2];
        #pragma unroll
        for (int ni = 0; ni < 2; ni++) {
            const uint32_t off = (uint32_t)((ks*16 + t_koff + tb_rr) * UVSTR + n_base + ni*16 + t_noff) * 2;
            LDMX4T(bh[2*ni][0], bh[2*ni][1], bh[2*ni+1][0], bh[2*ni+1][1], smb + U_VH + off);
            LDMX4T(bl[2*ni][0], bl[2*ni][1], bl[2*ni+1][0], bl[2*ni+1][1], smb + U_VL + off);
        }
        #pragma unroll
        for (int nj = 0; nj < 4; nj++) {
            MMA16816(acc[nj], ah, bh[nj]);
            MMA16816(acc[nj], ah, bl[nj]);
            MMA16816(acc[nj], al, bh[nj]);
        }
    }

    const int r0 = lane >> 2, c0 = (lane & 3) * 2;
    #pragma unroll
    for (int half = 0; half < 2; half++) {
        const int s = m_base + r0 + half*8;
        #pragma unroll
        for (int nj = 0; nj < 4; nj++) {
            const int col = dt*128 + n_base + nj*8 + c0;
            *(float2*)(&g_U[(bc*SS + s)*DD + col]) =
                make_float2(acc[nj][half*2 + 0], acc[nj][half*2 + 1]);
        }
    }
}

// ---------------- 5) sequential chunk scan (emits Ms bf16 hi/lo) ------------
__global__ void __launch_bounds__(256) scan_kernel(const float* __restrict__ state0,
                                                   float* __restrict__ outF) {
    const int idx = blockIdx.x * 256 + threadIdx.x;
    const int b = idx / (SS*DD);
    const int sd = idx - b*SS*DD;
    float m = state0[idx];
    const float dc = powf(AVAL, (float)CN);
    #pragma unroll
    for (int c = 0; c < NCH; c++) {
        const int o = (b*NCH + c)*SS*DD + sd;
        __nv_bfloat16 hi = __float2bfloat16(m);
        g_Ms_hi[o] = hi;
        g_Ms_lo[o] = __float2bfloat16(m - __bfloat162float(hi));
        m = dc * m + g_U[o];
    }
    outF[idx] = m;
}

// ---------------- 6) R1 via HMMA split-K: P = q@v^T, QM = q@Ms^T ------------
#define R1_QH 0
#define R1_QL (R1_QH + TILE_B)
#define R1_VH (R1_QL + TILE_B)
#define R1_VL (R1_VH + TILE_B)
#define R1_MH (R1_VL + TILE_B)
#define R1_ML (R1_MH + 32*TSTRIDE*2)
#define R1_SMEM (R1_ML + 32*TSTRIDE*2)
__global__ void __launch_bounds__(256) r1_tc_kernel() {
    extern __shared__ char sm1c[];
    const uint32_t smb = smem_u32(sm1c);
    const int kt = blockIdx.x, c = blockIdx.y, b = blockIdx.z;
    const int tid = threadIdx.x;
    const int wid = tid >> 5, lane = tid & 31;
    const int m_base = (wid >> 2) * 64;
    const int n_base = (wid & 3) * 32;
    const int nq_base = (wid & 3) * 8;

    float accP[4][4][4];
    float accQ[4][4];
    #pragma unroll
    for (int mi = 0; mi < 4; mi++) {
        #pragma unroll
        for (int r = 0; r < 4; r++) accQ[mi][r] = 0.f;
        #pragma unroll
        for (int nj = 0; nj < 4; nj++)
            #pragma unroll
            for (int r = 0; r < 4; r++) accP[mi][nj][r] = 0.f;
    }

    const int a_rr = lane & 15;
    const int a_kk = (lane >> 4) * 8;
    const int b_g  = lane >> 3;
    const int b_rr = lane & 7;
    const int b_nofs = (b_g >> 1) * 8;
    const int b_kofs = (b_g & 1) * 8;
    const int m_rr = lane & 7;
    const int m_kofs = ((lane >> 3) & 1) * 8;

    for (int ch = 0; ch < 4; ch++) {
        const int k0 = (kt * 4 + ch) * 64;
        #pragma unroll
        for (int l = 0; l < 4; l++) {
            const int idx = tid + l * 256;
            const int r = idx >> 3, c8 = (idx & 7) * 8;
            const uint32_t so = (uint32_t)(r * TSTRIDE + c8) * 2;
            const size_t gq = (size_t)(b*TT + c*CN + r)*DD + k0 + c8;
            *(uint4*)(sm1c + R1_QH + so) = *(const uint4*)(&g_q_hi[gq]);
            *(uint4*)(sm1c + R1_QL + so) = *(const uint4*)(&g_q_lo[gq]);
            *(uint4*)(sm1c + R1_VH + so) = *(const uint4*)(&g_v_hi[gq]);
            *(uint4*)(sm1c + R1_VL + so) = *(const uint4*)(&g_v_lo[gq]);
        }
        {
            const int r = tid >> 3, c8 = (tid & 7) * 8;
            const uint32_t so = (uint32_t)(r * TSTRIDE + c8) * 2;
            const size_t gm = (size_t)((b*NCH + c)*SS + r)*DD + k0 + c8;
            *(uint4*)(sm1c + R1_MH + so) = *(const uint4*)(&g_Ms_hi[gm]);
            *(uint4*)(sm1c + R1_ML + so) = *(const uint4*)(&g_Ms_lo[gm]);
        }
        __syncthreads();
        #pragma unroll
        for (int ks = 0; ks < 4; ks++) {
            uint32_t ah[4][4], al[4][4];
            #pragma unroll
            for (int mi = 0; mi < 4; mi++) {
                const uint32_t off = (uint32_t)((m_base + mi*16 + a_rr) * TSTRIDE + ks*16 + a_kk) * 2;
                LDMX4(ah[mi][0], ah[mi][1], ah[mi][2], ah[mi][3], smb + R1_QH + off);
                LDMX4(al[mi][0], al[mi][1], al[mi][2], al[mi][3], smb + R1_QL + off);
            }
            uint32_t bh[4][2], bl[4][2];
            #pragma unroll
            for (int ni = 0; ni < 2; ni++) {
                const uint32_t off = (uint32_t)((n_base + ni*16 + b_nofs + b_rr) * TSTRIDE + ks*16 + b_kofs) * 2;
                LDMX4(bh[2*ni][0], bh[2*ni][1], bh[2*ni+1][0], bh[2*ni+1][1], smb + R1_VH + off);
                LDMX4(bl[2*ni][0], bl[2*ni][1], bl[2*ni+1][0], bl[2*ni+1][1], smb + R1_VL + off);
            }
            uint32_t mh2[2], ml2[2];
            {
                const uint32_t off = (uint32_t)((nq_base + m_rr) * TSTRIDE + ks*16 + m_kofs) * 2;
                LDMX2(mh2[0], mh2[1], smb + R1_MH + off);
                LDMX2(ml2[0], ml2[1], smb + R1_ML + off);
            }
            #pragma unroll
            for (int mi = 0; mi < 4; mi++) {
                #pragma unroll
                for (int nj = 0; nj < 4; nj++) {
                    MMA16816(accP[mi][nj], ah[mi], bh[nj]);
                    MMA16816(accP[mi][nj], ah[mi], bl[nj]);
                    MMA16816(accP[mi][nj], al[mi], bh[nj]);
                }
                MMA16816(accQ[mi], ah[mi], mh2);
                MMA16816(accQ[mi], ah[mi], ml2);
                MMA16816(accQ[mi], al[mi], mh2);
            }
        }
        __syncthreads();
    }

    const int r0 = lane >> 2, c0 = (lane & 3) * 2;
    const size_t pb = ((size_t)kt*BB*NCH + (size_t)(b*NCH + c))*CN;
    #pragma unroll
    for (int mi = 0; mi < 4; mi++) {
        #pragma unroll
        for (int half = 0; half < 2; half++) {
            const int t = m_base + mi*16 + r0 + half*8;
            #pragma unroll
            for (int nj = 0; nj < 4; nj++) {
                const int tau0 = n_base + nj*8 + c0;
                *(float2*)(&g_Pp[(pb + t)*CN + tau0]) =
                    make_float2(accP[mi][nj][half*2 + 0], accP[mi][nj][half*2 + 1]);
            }
            const int s0 = nq_base + c0;
            *(float2*)(&g_QMp[(pb + t)*SS + s0]) =
                make_float2(accQ[mi][half*2 + 0], accQ[mi][half*2 + 1]);
        }
    }
}

// ---------------- 6b) reduce split-K partials, apply decay/mask/scale -------
__global__ void __launch_bounds__(128) reduce_p_kernel() {
    const int t = blockIdx.x, c = blockIdx.y, b = blockIdx.z;
    const int tau = threadIdx.x;
    const size_t base = ((size_t)(b*NCH + c)*CN + t);
    float sum = 0.f;
    #pragma unroll
    for (int kt = 0; kt < 4; kt++)
        sum += g_Pp[((size_t)kt*BB*NCH*CN + base)*CN + tau];
    const float out = (tau <= t) ? ALPHA * powf(AVAL, (float)(t - tau)) * sum : 0.f;
    g_P[base*CN + tau] = out;
    if (tau < SS) {
        float s2 = 0.f;
        #pragma unroll
        for (int kt = 0; kt < 4; kt++)
            s2 += g_QMp[((size_t)kt*BB*NCH*CN + base)*SS + tau];
        g_QM[base*SS + tau] = RSCALE * powf(AVAL, (float)(t + 1)) * s2;
    }
}

// ---------------- 7) R2: scores, softmax, G (emits bf16 hi/lo) ---------------
#define R2_SMEM ((128*129 + 128*33*2 + 132)*4)
__global__ void __launch_bounds__(256) r2_kernel() {
    extern __shared__ float sm2[];
    float* sP  = sm2;
    float* sW  = sP + 128*129;
    float* sA  = sW + 128*33;
    float* sPw = sA + 128*33;
    const int c = blockIdx.x, b = blockIdx.y;
    const int tid = threadIdx.x;
    if (tid < 132) sPw[tid] = powf(AVAL, (float)tid);
    __syncthreads();
    const int pbase = ((b*NCH + c)*CN)*CN;
    for (int e = tid; e < CN*CN; e += 256) {
        sP[(e >> 7)*129 + (e & 127)] = g_P[pbase + e];
    }
    const int qbase = ((b*NCH + c)*CN)*SS;
    for (int e = tid; e < CN*SS; e += 256) {
        sA[(e >> 5)*33 + (e & 31)] = g_QM[qbase + e];
    }
    for (int e = tid; e < CN*SS; e += 256) {
        const int t = e >> 5, s = e & 31;
        sW[t*33 + s] = g_w[(b*TT + c*CN + t)*SS + s];
    }
    __syncthreads();
    {
        const int t  = tid >> 1;
        const int s0 = (tid & 1) * 16;
        float r[16];
        #pragma unroll
        for (int sj = 0; sj < 16; sj++) r[sj] = 0.f;
        for (int tau = 0; tau <= t; tau++) {
            const float p = sP[t*129 + tau];
            #pragma unroll
            for (int sj = 0; sj < 16; sj++) r[sj] += p * sW[tau*33 + s0 + sj];
        }
        __syncthreads();
        #pragma unroll
        for (int sj = 0; sj < 16; sj++) sA[t*33 + s0 + sj] += RSCALE * r[sj];
    }
    __syncthreads();
    if (tid < 128) {
        const int t = tid;
        float mx = -1e30f;
        #pragma unroll
        for (int s = 0; s < SS; s++) mx = fmaxf(mx, sA[t*33 + s]);
        float ev[SS]; float sum = 0.f;
        #pragma unroll
        for (int s = 0; s < SS; s++) { ev[s] = expf(sA[t*33 + s] - mx); sum += ev[s]; }
        const float inv = 1.f / sum;
        const float pw = sPw[t + 1];
        const int ab = ((b*NCH + c)*CN + t)*SS;
        #pragma unroll
        for (int s = 0; s < SS; s++) {
            const float a = ev[s] * inv;
            sA[t*33 + s] = a;
            const float av = pw * a;
            __nv_bfloat16 hi = __float2bfloat16(av);
            g_at_hi[ab + s] = hi;
            g_at_lo[ab + s] = __float2bfloat16(av - __bfloat162float(hi));
        }
    }
    __syncthreads();
    const int ty = tid >> 4, tx = tid & 15;
    const int gbase = ((b*NCH + c)*CN)*CN;
    #pragma unroll
    for (int i = 0; i < 8; i++) {
        const int t = ty*8 + i;
        #pragma unroll
        for (int j = 0; j < 8; j++) {
            const int tau = tx*8 + j;
            float g = 0.f;
            if (tau <= t) {
                #pragma unroll
                for (int s = 0; s < SS; s++) g += sA[t*33 + s] * sW[tau*33 + s];
                g *= ALPHA * sPw[t - tau];
            }
            __nv_bfloat16 hi = __float2bfloat16(g);
            g_G_hi[gbase + t*CN + tau] = hi;
            g_G_lo[gbase + t*CN + tau] = __float2bfloat16(g - __bfloat162float(hi));
        }
    }
}

// ---------------- 8) R3 via HMMA: ctx = G@v + at@Ms --------------------------
#define VSTR 136
#define ATSTR 40
#define R3_TILE (128*VSTR*2)
#define R3_GH 0
#define R3_GL (R3_GH + R3_TILE)
#define R3_VH (R3_GL + R3_TILE)
#define R3_VL (R3_VH + R3_TILE)
#define R3_AH (R3_VL + R3_TILE)
#define R3_AL (R3_AH + 128*ATSTR*2)
#define R3_MH (R3_AL + 128*ATSTR*2)
#define R3_ML (R3_MH + 32*VSTR*2)
#define R3_SMEM (R3_ML + 32*VSTR*2)
__global__ void __launch_bounds__(256) r3_tc_kernel(float* __restrict__ outC) {
    extern __shared__ char sm3c[];
    const uint32_t smb = smem_u32(sm3c);
    const int dt = blockIdx.x, c = blockIdx.y, b = blockIdx.z;
    const int tid = threadIdx.x;
    const int wid = tid >> 5, lane = tid & 31;
    const int m_base = (wid >> 2) * 64;
    const int n_base = (wid & 3) * 32;

    #pragma unroll
    for (int l = 0; l < 8; l++) {
        const int idx = tid + l * 256;
        const int r = idx >> 4, c8 = (idx & 15) * 8;
        const uint32_t so = (uint32_t)(r * VSTR + c8) * 2;
        const size_t gg = ((size_t)(b*NCH + c)*CN + r)*CN + c8;
        *(uint4*)(sm3c + R3_GH + so) = *(const uint4*)(&g_G_hi[gg]);
        *(uint4*)(sm3c + R3_GL + so) = *(const uint4*)(&g_G_lo[gg]);
        const size_t gv = (size_t)(b*TT + c*CN + r)*DD + dt*128 + c8;
        *(uint4*)(sm3c + R3_VH + so) = *(const uint4*)(&g_v_hi[gv]);
        *(uint4*)(sm3c + R3_VL + so) = *(const uint4*)(&g_v_lo[gv]);
    }
    #pragma unroll
    for (int l = 0; l < 2; l++) {
        const int idx = tid + l * 256;
        {
            const int r = idx >> 2, s8 = (idx & 3) * 8;
            const uint32_t so = (uint32_t)(r * ATSTR + s8) * 2;
            const size_t ga = ((size_t)(b*NCH + c)*CN + r)*SS + s8;
            *(uint4*)(sm3c + R3_AH + so) = *(const uint4*)(&g_at_hi[ga]);
            *(uint4*)(sm3c + R3_AL + so) = *(const uint4*)(&g_at_lo[ga]);
        }
        {
            const int r = idx >> 4, c8 = (idx & 15) * 8;
            const uint32_t so = (uint32_t)(r * VSTR + c8) * 2;
            const size_t gm = ((size_t)(b*NCH + c)*SS + r)*DD + dt*128 + c8;
            *(uint4*)(sm3c + R3_MH + so) = *(const uint4*)(&g_Ms_hi[gm]);
            *(uint4*)(sm3c + R3_ML + so) = *(const uint4*)(&g_Ms_lo[gm]);
        }
    }
    __syncthreads();

    float acc[4][4][4];
    #pragma unroll
    for (int mi = 0; mi < 4; mi++)
        #pragma unroll
        for (int nj = 0; nj < 4; nj++)
            #pragma unroll
            for (int r = 0; r < 4; r++) acc[mi][nj][r] = 0.f;

    const int a_rr = lane & 15;
    const int a_kk = (lane >> 4) * 8;
    const int tb_g  = lane >> 3;
    const int tb_rr = lane & 7;
    const int t_koff = (tb_g & 1) * 8;
    const int t_noff = (tb_g >> 1) * 8;

    #pragma unroll
    for (int ks = 0; ks < 8; ks++) {
        uint32_t ah[4][4], al[4][4];
        #pragma unroll
        for (int mi = 0; mi < 4; mi++) {
            const uint32_t off = (uint32_t)((m_base + mi*16 + a_rr) * VSTR + ks*16 + a_kk) * 2;
            LDMX4(ah[mi][0], ah[mi][1], ah[mi][2], ah[mi][3], smb + R3_GH + off);
            LDMX4(al[mi][0], al[mi][1], al[mi][2], al[mi][3], smb + R3_GL + off);
        }
        uint32_t bh[4][2], bl[4][2];
        #pragma unroll
        for (int ni = 0; ni < 2; ni++) {
            const uint32_t off = (uint32_t)((ks*16 + t_koff + tb_rr) * VSTR + n_base + ni*16 + t_noff) * 2;
            LDMX4T(bh[2*ni][0], bh[2*ni][1], bh[2*ni+1][0], bh[2*ni+1][1], smb + R3_VH + off);
            LDMX4T(bl[2*ni][0], bl[2*ni][1], bl[2*ni+1][0], bl[2*ni+1][1], smb + R3_VL + off);
        }
        #pragma unroll
        for (int mi = 0; mi < 4; mi++)
            #pragma unroll
            for (int nj = 0; nj < 4; nj++) {
                MMA16816(acc[mi][nj], ah[mi], bh[nj]);
                MMA16816(acc[mi][nj], ah[mi], bl[nj]);
                MMA16816(acc[mi][nj], al[mi], bh[nj]);
            }
    }
    #pragma unroll
    for (int ks = 0; ks < 2; ks++) {
        uint32_t ah[4][4], al[4][4];
        #pragma unroll
        for (int mi = 0; mi < 4; mi++) {
            const uint32_t off = (uint32_t)((m_base + mi*16 + a_rr) * ATSTR + ks*16 + a_kk) * 2;
            LDMX4(ah[mi][0], ah[mi][1], ah[mi][2], ah[mi][3], smb + R3_AH + off);
            LDMX4(al[mi][0], al[mi][1], al[mi][2], al[mi][3], smb + R3_AL + off);
        }
        uint32_t bh[4][2], bl[4][2];
        #pragma unroll
        for (int ni = 0; ni < 2; ni++) {
            const uint32_t off = (uint32_t)((ks*16 + t_koff + tb_rr) * VSTR + n_base + ni*16 + t_noff) * 2;
            LDMX4T(bh[2*ni][0], bh[2*ni][1], bh[2*ni+1][0], bh[2*ni+1][1], smb + R3_MH + off);
            LDMX4T(bl[2*ni][0], bl[2*ni][1], bl[2*ni+1][0], bl[2*ni+1][1], smb + R3_ML + off);
        }
        #pragma unroll
        for (int mi = 0; mi < 4; mi++)
            #pragma unroll
            for (int nj = 0; nj < 4; nj++) {
                MMA16816(acc[mi][nj], ah[mi], bh[nj]);
                MMA16816(acc[mi][nj], ah[mi], bl[nj]);
                MMA16816(acc[mi][nj], al[mi], bh[nj]);
            }
    }

    #pragma unroll
    for (int mi = 0; mi < 4; mi++) {
        const int row0 = b*TT + c*CN + m_base + mi*16 + (lane >> 2);
        #pragma unroll
        for (int nj = 0; nj < 4; nj++) {
            const int col = dt*128 + n_base + nj*8 + (lane & 3) * 2;
            *(float2*)(&outC[(size_t)row0 * DD + col]) = make_float2(acc[mi][nj][0], acc[mi][nj][1]);
            *(float2*)(&outC[(size_t)(row0 + 8) * DD + col]) = make_float2(acc[mi][nj][2], acc[mi][nj][3]);
        }
    }
}

extern "C" void kernel_launch(void* const* d_in, const int* in_sizes, int n_in,
                              void* d_out, int out_size) {
    (void)in_sizes; (void)n_in; (void)out_size;
    const float* h      = (const float*)d_in[0];
    const float* state0 = (const float*)d_in[1];
    const float* gamma  = (const float*)d_in[2];
    const float* beta   = (const float*)d_in[3];
    const float* Wq     = (const float*)d_in[4];
    const float* bq     = (const float*)d_in[5];
    const float* Wv     = (const float*)d_in[6];
    const float* bv     = (const float*)d_in[7];
    float* out = (float*)d_out;
    float* outCtx   = out;
    float* outFinal = out + (size_t)BB*TT*DD;

    cudaFuncSetAttribute(gemm_tc_kernel, cudaFuncAttributeMaxDynamicSharedMemorySize, GEMM_SMEM);
    cudaFuncSetAttribute(route_tc_kernel, cudaFuncAttributeMaxDynamicSharedMemorySize, RT_SMEM);
    cudaFuncSetAttribute(u_tc_kernel, cudaFuncAttributeMaxDynamicSharedMemorySize, U_SMEM);
    cudaFuncSetAttribute(r1_tc_kernel, cudaFuncAttributeMaxDynamicSharedMemorySize, R1_SMEM);
    cudaFuncSetAttribute(r2_kernel, cudaFuncAttributeMaxDynamicSharedMemorySize, R2_SMEM);
    cudaFuncSetAttribute(r3_tc_kernel, cudaFuncAttributeMaxDynamicSharedMemorySize, R3_SMEM);

    ln_kernel<<<BB*TT, 256>>>(h, gamma, beta);
    convw_kernel<<<2*DD*DD/1024, 256>>>(Wq, Wv);
    convs_kernel<<<BB*SS*DD/1024, 256>>>(state0);
    gemm_tc_kernel<<<dim3(DD/128, BB*TT/128, 2), 256, GEMM_SMEM>>>(bq, bv);
    route_tc_kernel<<<dim3(4, NCH, BB), 256, RT_SMEM>>>();
    route_red_kernel<<<dim3(NCH, BB), 128>>>();
    u_tc_kernel<<<dim3(DD/128, NCH, BB), 256, U_SMEM>>>();
    scan_kernel<<<BB*SS*DD/256, 256>>>(state0, outFinal);
    r1_tc_kernel<<<dim3(4, NCH, BB), 256, R1_SMEM>>>();
    reduce_p_kernel<<<dim3(CN, NCH, BB), 128>>>();
    r2_kernel<<<dim3(NCH, BB), 256, R2_SMEM>>>();
    r3_tc_kernel<<<dim3(DD/128, NCH, BB), 256, R3_SMEM>>>(outCtx);
}